// round 8
// baseline (speedup 1.0000x reference)
#include <cuda_runtime.h>
#include <cstdint>
#include <cstddef>

#define B 32
#define T 512
#define D 500
#define H 10
#define HD 50
#define D3 1500
#define BT (B*T)
#define BTD (BT*D)
#define KW 7
#define QKVP 1920   // padded qkv row pitch: 3 * H * 64

// ---------------- scratch (static device arrays; no runtime allocation) ----
__device__ float g_b0[BTD];
__device__ float g_b1[BTD];
__device__ float g_b2[BTD];
__device__ float g_bt[BTD];
__device__ float g_b1t[BTD];
__device__ float g_b2t[BTD];
__device__ float g_qkv[(size_t)BT * QKVP];
__device__ float g_wt[6 * D * D + D3 * D];

// ---------------- helpers ---------------------------------------------------
__device__ __forceinline__ uint32_t f2tf32(float x) {
    uint32_t r;
    asm("cvt.rna.tf32.f32 %0, %1;" : "=r"(r) : "f"(x));
    return r;
}
__device__ __forceinline__ uint32_t smem_u32(const void* p) {
    uint32_t a;
    asm("{ .reg .u64 t; cvta.to.shared.u64 t, %1; cvt.u32.u64 %0, t; }" : "=r"(a) : "l"(p));
    return a;
}

#define MMA_TF32(c, a, b) \
    asm volatile("mma.sync.aligned.m16n8k8.row.col.f32.tf32.tf32.f32 " \
        "{%0,%1,%2,%3}, {%4,%5,%6,%7}, {%8,%9}, {%0,%1,%2,%3};" \
        : "+f"((c)[0]), "+f"((c)[1]), "+f"((c)[2]), "+f"((c)[3]) \
        : "r"((a)[0]), "r"((a)[1]), "r"((a)[2]), "r"((a)[3]), \
          "r"((b)[0]), "r"((b)[1]))

#define CP16(dst, src) \
    asm volatile("cp.async.ca.shared.global [%0], [%1], 16;" :: "r"(dst), "l"(src) : "memory")
#define CP8(dst, src) \
    asm volatile("cp.async.ca.shared.global [%0], [%1], 8;"  :: "r"(dst), "l"(src) : "memory")
#define CP16P(dst, src, p) \
    asm volatile("cp.async.ca.shared.global [%0], [%1], 16, %2;" :: "r"(dst), "l"(src), "r"(p) : "memory")
#define CPCOMMIT() asm volatile("cp.async.commit_group;" ::: "memory")
#define CPWAIT0()  asm volatile("cp.async.wait_group 0;" ::: "memory")
#define CPWAIT1()  asm volatile("cp.async.wait_group 1;" ::: "memory")

// ---------------- merged weight tf32 pre-round -----------------------------
__global__ void cvt_all(const float* __restrict__ p0, const float* __restrict__ p1,
                        const float* __restrict__ p2, const float* __restrict__ p3,
                        const float* __restrict__ p4, const float* __restrict__ p5,
                        const float* __restrict__ p6, uint32_t* __restrict__ o) {
    const int DD = D * D;
    int i = blockIdx.x * blockDim.x + threadIdx.x;
    if (i >= 6 * DD + D3 * D) return;
    float v;
    if      (i < DD)              v = p0[i];
    else if (i < 2 * DD)          v = p1[i - DD];
    else if (i < 3 * DD)          v = p2[i - 2 * DD];
    else if (i < 4 * DD)          v = p3[i - 3 * DD];
    else if (i < 4 * DD + D3 * D) v = p4[i - 4 * DD];
    else if (i < 5 * DD + D3 * D) v = p5[i - 4 * DD - D3 * D];
    else                          v = p6[i - 5 * DD - D3 * D];
    o[i] = f2tf32(v);
}

// ---------------- positional embedding + add ------------------------------
__global__ void posemb_kernel(const int* __restrict__ ori,
                              const float* __restrict__ x,
                              float* __restrict__ out) {
    int idx = blockIdx.x * blockDim.x + threadIdx.x;
    if (idx >= BTD) return;
    int d  = idx % D;
    int bt = idx / D;
    int t  = bt % T;
    float pe = 0.f;
    if (ori[bt] != 0) {
        float pos = (float)(t + 1);
        int   i   = (d < 250) ? d : (d - 250);
        float ang = pos * expf((float)i * -0.036989318763f);
        pe = (d < 250) ? sinf(ang) : cosf(ang);
    }
    out[idx] = pe + x[idx];
}

// ---------------- depthwise conv1d (k=7, pad=3), float4, tf32-rounded out --
__global__ void dwconv4_kernel(const float* __restrict__ x,
                               const float* __restrict__ w,
                               const float* __restrict__ bias,
                               uint32_t* __restrict__ y) {
    int idx = blockIdx.x * blockDim.x + threadIdx.x;
    if (idx >= BTD / 4) return;
    int d4 = idx % (D / 4);
    int bt = idx / (D / 4);
    int t  = bt % T;
    int b  = bt / T;
    int d  = d4 * 4;
    float4 bv = *(const float4*)(bias + d);
    float a0 = bv.x, a1 = bv.y, a2 = bv.z, a3 = bv.w;
    const float* xb = x + (size_t)(b * T) * D + d;
#pragma unroll
    for (int j = 0; j < KW; j++) {
        int tt = t + j - 3;
        if (tt >= 0 && tt < T) {
            float4 v = *(const float4*)(xb + (size_t)tt * D);
            a0 = fmaf(w[(d + 0) * KW + j], v.x, a0);
            a1 = fmaf(w[(d + 1) * KW + j], v.y, a1);
            a2 = fmaf(w[(d + 2) * KW + j], v.z, a2);
            a3 = fmaf(w[(d + 3) * KW + j], v.w, a3);
        }
    }
    *(uint4*)(y + (size_t)idx * 4) =
        make_uint4(f2tf32(a0), f2tf32(a1), f2tf32(a2), f2tf32(a3));
}

// =================== 3-stage pipelined tf32 warp-mma GEMM ===================
// Scalar LDS fragment loads (round-6 proven), 3-stage cp.async, 1 sync/chunk.
// modes: 0 = C fp32 (+res); 1 = + Ct tf32-rounded copy; 2 = head-padded qkv
#define GBM 128
#define GBN 128
#define GBK 32
#define SPITCH 36
#define GBUF ((GBM + GBN) * SPITCH)
#define GSM_BYTES (3 * GBUF * 4)

__global__ __launch_bounds__(256, 2)
void gemm_pipe(const float* __restrict__ A, const float* __restrict__ W,
               const float* __restrict__ bias, const float* __restrict__ res,
               float* __restrict__ C, uint32_t* __restrict__ Ct,
               int N, int Kd, int mode) {
    extern __shared__ uint32_t sm[];

    int tid  = threadIdx.x;
    int lane = tid & 31, wid = tid >> 5;
    int g = lane >> 2, t = lane & 3;
    int m0 = blockIdx.y * GBM;
    int n0 = blockIdx.x * GBN;
    int wm = (wid & 1) * 64;
    int wn = (wid >> 1) * 32;

    int r0 = tid >> 3, kg = tid & 7;
    uint32_t smbase = smem_u32(sm);

    uint32_t adstoff[4], bdstoff[4];
    const float* asrc[4];
    const float* bsrc[4];
    uint32_t bok[4];
#pragma unroll
    for (int i = 0; i < 4; i++) {
        int r = r0 + i * 32;
        adstoff[i] = (uint32_t)(r * SPITCH + kg * 4) * 4;
        bdstoff[i] = adstoff[i] + GBM * SPITCH * 4;
        asrc[i] = A + (size_t)(m0 + r) * Kd + kg * 4;
        int n = n0 + r;
        bok[i] = (n < N) ? 16u : 0u;
        bsrc[i] = W + (size_t)((n < N) ? n : 0) * Kd + kg * 4;
    }

    float acc[4][4][4];
#pragma unroll
    for (int mt = 0; mt < 4; mt++)
#pragma unroll
        for (int nt = 0; nt < 4; nt++)
#pragma unroll
            for (int i = 0; i < 4; i++) acc[mt][nt][i] = 0.f;

    const int KT = (Kd + GBK - 1) / GBK;

#define ISSUE_COPY(chunk, stage)                                              \
    {                                                                         \
        int k0c = (chunk) * GBK;                                              \
        int kk_ = k0c + kg * 4;                                               \
        uint32_t kin = (kk_ < Kd) ? 16u : 0u;                                 \
        uint32_t sb_ = smbase + (uint32_t)(stage) * (GBUF * 4);               \
        _Pragma("unroll")                                                     \
        for (int i = 0; i < 4; i++) {                                         \
            const float* sa = kin ? (asrc[i] + k0c) : A;                      \
            CP16P(sb_ + adstoff[i], sa, kin);                                 \
            uint32_t bb = kin & bok[i];                                       \
            const float* sb2 = bb ? (bsrc[i] + k0c) : W;                      \
            CP16P(sb_ + bdstoff[i], sb2, bb);                                 \
        }                                                                     \
        CPCOMMIT();                                                           \
    }

    // prologue: chunks 0,1 -> stages 0,1
    ISSUE_COPY(0, 0);
    ISSUE_COPY(1, 1);

    int stage = 0;
    for (int kt = 0; kt < KT; kt++) {
        if (kt + 1 < KT) { CPWAIT1(); } else { CPWAIT0(); }
        __syncthreads();
        // prefetch chunk kt+2 (that stage was last read in iter kt-1)
        if (kt + 2 < KT) {
            int ns = stage + 2; if (ns >= 3) ns -= 3;
            ISSUE_COPY(kt + 2, ns);
        }

        const uint32_t* Ab = sm + (size_t)stage * GBUF;
        const uint32_t* Bb = Ab + GBM * SPITCH;
#pragma unroll
        for (int ks = 0; ks < 4; ks++) {
            int kk = ks * 8;
            uint32_t af[4][4], bf[4][2];
#pragma unroll
            for (int mt = 0; mt < 4; mt++) {
                const uint32_t* Ar = Ab + (wm + mt * 16 + g) * SPITCH + kk;
                af[mt][0] = Ar[t];
                af[mt][1] = Ar[8 * SPITCH + t];
                af[mt][2] = Ar[t + 4];
                af[mt][3] = Ar[8 * SPITCH + t + 4];
            }
#pragma unroll
            for (int nt = 0; nt < 4; nt++) {
                const uint32_t* Br = Bb + (wn + nt * 8 + g) * SPITCH + kk;
                bf[nt][0] = Br[t];
                bf[nt][1] = Br[t + 4];
            }
#pragma unroll
            for (int mt = 0; mt < 4; mt++)
#pragma unroll
                for (int nt = 0; nt < 4; nt++)
                    MMA_TF32(acc[mt][nt], af[mt], bf[nt]);
        }
        stage++; if (stage == 3) stage = 0;
    }
#undef ISSUE_COPY

#pragma unroll
    for (int mt = 0; mt < 4; mt++) {
        int row0 = m0 + wm + mt * 16 + g;
#pragma unroll
        for (int nt = 0; nt < 4; nt++) {
            int col = n0 + wn + nt * 8 + 2 * t;
            if (col < N) {
                float2 bv = *(const float2*)(bias + col);
                float2 o0, o1;
                o0.x = acc[mt][nt][0] + bv.x;
                o0.y = acc[mt][nt][1] + bv.y;
                o1.x = acc[mt][nt][2] + bv.x;
                o1.y = acc[mt][nt][3] + bv.y;
                if (mode == 2) {
                    int which = col / 500;
                    int rem   = col - which * 500;
                    int hh    = rem / 50;
                    int dd    = rem - hh * 50;
                    size_t p0 = (size_t)row0 * QKVP + which * 640 + hh * 64 + dd;
                    size_t p1 = (size_t)(row0 + 8) * QKVP + which * 640 + hh * 64 + dd;
                    uint32_t* Cq = (uint32_t*)C;
                    *(uint2*)(Cq + p0) = make_uint2(f2tf32(o0.x), f2tf32(o0.y));
                    *(uint2*)(Cq + p1) = make_uint2(f2tf32(o1.x), f2tf32(o1.y));
                } else {
                    size_t i0 = (size_t)row0 * N + col;
                    size_t i1 = (size_t)(row0 + 8) * N + col;
                    if (res) {
                        float2 r0v = *(const float2*)(res + i0);
                        float2 r1v = *(const float2*)(res + i1);
                        o0.x += r0v.x; o0.y += r0v.y;
                        o1.x += r1v.x; o1.y += r1v.y;
                    }
                    *(float2*)(C + i0) = o0;
                    *(float2*)(C + i1) = o1;
                    if (mode == 1) {
                        *(uint2*)(Ct + i0) = make_uint2(f2tf32(o0.x), f2tf32(o0.y));
                        *(uint2*)(Ct + i1) = make_uint2(f2tf32(o1.x), f2tf32(o1.y));
                    }
                }
            }
        }
    }
}

// =================== tf32 warp-mma flash attention (round-6 form) ===========
#define AMQ 128
#define ANK 64
#define ADP 56
#define APQ 60
#define APV 68
#define ASM_BYTES ((AMQ*APQ + ANK*APQ + ADP*APV + AMQ*APV) * 4 + 64)

__global__ __launch_bounds__(256, 2)
void attn_mma(const float* __restrict__ qkv2,
              const unsigned char* __restrict__ mask,
              uint32_t* __restrict__ out) {
    extern __shared__ uint32_t dsm[];
    uint32_t* Qs = dsm;                    // [128][60]
    uint32_t* Ks = Qs + AMQ * APQ;         // [64][60]
    uint32_t* Vt = Ks + ANK * APQ;         // [56][68]
    uint32_t* Ps = Vt + ADP * APV;         // [128][68]
    unsigned char* msk = (unsigned char*)(Ps + AMQ * APV);

    int tid  = threadIdx.x;
    int lane = tid & 31, wid = tid >> 5;
    int g = lane >> 2, t = lane & 3;
    int bh = blockIdx.y;
    int b  = bh / H, h = bh % H;
    int q0 = blockIdx.x * AMQ;
    const float scale = 0.14142135623730951f;

    for (int i = tid; i < AMQ * 6; i += 256) Qs[(i / 6) * APQ + 50 + (i % 6)] = 0;
    for (int i = tid; i < ANK * 6; i += 256) Ks[(i / 6) * APQ + 50 + (i % 6)] = 0;
    for (int i = tid; i < 6 * APV; i += 256) Vt[(50 + i / APV) * APV + (i % APV)] = 0;

    {
        int r = tid >> 1, e = tid & 1;
        const float* src = qkv2 + (size_t)(b * T + q0 + r) * QKVP + h * 64;
        uint32_t dst = smem_u32(Qs + r * APQ);
#pragma unroll
        for (int c = e; c < 12; c += 2) CP16(dst + 16 * c, src + 4 * c);
        if (e == 0) CP8(dst + 192, src + 48);
        CPCOMMIT();
    }

    int wq = wid * 16;
    const uint32_t* QA = Qs + (wq + g) * APQ;
    const uint32_t* QB = Qs + (wq + g + 8) * APQ;
    uint32_t* PsA = Ps + (wq + g) * APV;
    uint32_t* PsB = Ps + (wq + g + 8) * APV;

    float m0 = -1e30f, m1 = -1e30f, l0 = 0.f, l1 = 0.f;
    float oacc[7][4];
#pragma unroll
    for (int nt = 0; nt < 7; nt++)
#pragma unroll
        for (int i = 0; i < 4; i++) oacc[nt][i] = 0.f;

    for (int kt = 0; kt < T / ANK; kt++) {
        int k0 = kt * ANK;
        __syncthreads();

        {
            int j = tid >> 2, q = tid & 3;
            const float* src = qkv2 + (size_t)(b * T + k0 + j) * QKVP + 640 + h * 64;
            uint32_t dst = smem_u32(Ks + j * APQ);
            CP16(dst + 16 * q,       src + 4 * q);
            CP16(dst + 16 * (q + 4), src + 4 * (q + 4));
            CP16(dst + 16 * (q + 8), src + 4 * (q + 8));
            if (q == 3) CP8(dst + 192, src + 48);
            CPCOMMIT();
        }
        {
            int j = tid >> 2, q = tid & 3;
            const float* src = qkv2 + (size_t)(b * T + k0 + j) * QKVP + 1280 + h * 64;
#pragma unroll
            for (int p = q; p < 25; p += 4) {
                float2 v = *(const float2*)(src + 2 * p);
                Vt[(2 * p) * APV + j]     = __float_as_uint(v.x);
                Vt[(2 * p + 1) * APV + j] = __float_as_uint(v.y);
            }
        }
        if (tid < ANK) msk[tid] = mask[b * T + k0 + tid];
        CPWAIT0();
        __syncthreads();

        float sacc[8][4];
#pragma unroll
        for (int nt = 0; nt < 8; nt++)
#pragma unroll
            for (int i = 0; i < 4; i++) sacc[nt][i] = 0.f;
#pragma unroll
        for (int ks = 0; ks < 7; ks++) {
            int kk = ks * 8;
            uint32_t af[4] = {QA[kk + t], QB[kk + t], QA[kk + t + 4], QB[kk + t + 4]};
#pragma unroll
            for (int nt = 0; nt < 8; nt++) {
                const uint32_t* Kr = Ks + (nt * 8 + g) * APQ + kk;
                uint32_t bf[2] = {Kr[t], Kr[t + 4]};
                MMA_TF32(sacc[nt], af, bf);
            }
        }

        float mx0 = -1e30f, mx1 = -1e30f;
#pragma unroll
        for (int nt = 0; nt < 8; nt++) {
            sacc[nt][0] *= scale; sacc[nt][1] *= scale;
            sacc[nt][2] *= scale; sacc[nt][3] *= scale;
            int c = nt * 8 + 2 * t;
            if (msk[c])     { sacc[nt][0] = -1e30f; sacc[nt][2] = -1e30f; }
            if (msk[c + 1]) { sacc[nt][1] = -1e30f; sacc[nt][3] = -1e30f; }
            mx0 = fmaxf(mx0, fmaxf(sacc[nt][0], sacc[nt][1]));
            mx1 = fmaxf(mx1, fmaxf(sacc[nt][2], sacc[nt][3]));
        }
        mx0 = fmaxf(mx0, __shfl_xor_sync(0xffffffffu, mx0, 1));
        mx0 = fmaxf(mx0, __shfl_xor_sync(0xffffffffu, mx0, 2));
        mx1 = fmaxf(mx1, __shfl_xor_sync(0xffffffffu, mx1, 1));
        mx1 = fmaxf(mx1, __shfl_xor_sync(0xffffffffu, mx1, 2));
        float mn0 = fmaxf(m0, mx0), mn1 = fmaxf(m1, mx1);
        float c0 = __expf(m0 - mn0), c1 = __expf(m1 - mn1);
        float s0 = 0.f, s1 = 0.f;
#pragma unroll
        for (int nt = 0; nt < 8; nt++) {
            float p00 = __expf(sacc[nt][0] - mn0);
            float p01 = __expf(sacc[nt][1] - mn0);
            float p10 = __expf(sacc[nt][2] - mn1);
            float p11 = __expf(sacc[nt][3] - mn1);
            s0 += p00 + p01;
            s1 += p10 + p11;
            int c = nt * 8 + 2 * t;
            *(uint2*)(PsA + c) = make_uint2(f2tf32(p00), f2tf32(p01));
            *(uint2*)(PsB + c) = make_uint2(f2tf32(p10), f2tf32(p11));
        }
        s0 += __shfl_xor_sync(0xffffffffu, s0, 1);
        s0 += __shfl_xor_sync(0xffffffffu, s0, 2);
        s1 += __shfl_xor_sync(0xffffffffu, s1, 1);
        s1 += __shfl_xor_sync(0xffffffffu, s1, 2);
        l0 = l0 * c0 + s0; m0 = mn0;
        l1 = l1 * c1 + s1; m1 = mn1;
#pragma unroll
        for (int nt = 0; nt < 7; nt++) {
            oacc[nt][0] *= c0; oacc[nt][1] *= c0;
            oacc[nt][2] *= c1; oacc[nt][3] *= c1;
        }
        __syncwarp();

#pragma unroll
        for (int ks = 0; ks < 8; ks++) {
            int kk = ks * 8;
            uint32_t af[4] = {PsA[kk + t], PsB[kk + t], PsA[kk + t + 4], PsB[kk + t + 4]};
#pragma unroll
            for (int nt = 0; nt < 7; nt++) {
                const uint32_t* Vr = Vt + (nt * 8 + g) * APV + kk;
                uint32_t bf[2] = {Vr[t], Vr[t + 4]};
                MMA_TF32(oacc[nt], af, bf);
            }
        }
    }

    float inv0 = 1.f / l0, inv1 = 1.f / l1;
    int r0 = q0 + wq + g;
    uint32_t* o0 = out + (size_t)(b * T + r0) * D + h * HD;
    uint32_t* o1 = o0 + (size_t)8 * D;
#pragma unroll
    for (int nt = 0; nt < 7; nt++) {
        int c = nt * 8 + 2 * t;
        if (c < HD) {
            *(uint2*)(o0 + c) = make_uint2(f2tf32(oacc[nt][0] * inv0),
                                           f2tf32(oacc[nt][1] * inv0));
            *(uint2*)(o1 + c) = make_uint2(f2tf32(oacc[nt][2] * inv1),
                                           f2tf32(oacc[nt][3] * inv1));
        }
    }
}

// ---------------- launch ----------------------------------------------------
extern "C" void kernel_launch(void* const* d_in, const int* in_sizes, int n_in,
                              void* d_out, int out_size) {
    const int* ori            = (const int*)d_in[0];
    const float* x            = (const float*)d_in[1];
    const unsigned char* xm   = (const unsigned char*)d_in[2];
    const float *dwp[4], *dbp[4], *pwp[4], *pbp[4];
    for (int i = 0; i < 4; i++) {
        dwp[i] = (const float*)d_in[3 + 4 * i];
        dbp[i] = (const float*)d_in[4 + 4 * i];
        pwp[i] = (const float*)d_in[5 + 4 * i];
        pbp[i] = (const float*)d_in[6 + 4 * i];
    }
    const float* in_w  = (const float*)d_in[19];
    const float* in_b  = (const float*)d_in[20];
    const float* out_w = (const float*)d_in[21];
    const float* out_b = (const float*)d_in[22];
    const float* ffc_w = (const float*)d_in[23];
    const float* ffc_b = (const float*)d_in[24];
    float* outp = (float*)d_out;

    float *b0, *b1, *b2, *bt, *b1t, *b2t, *qkvp, *wt;
    cudaGetSymbolAddress((void**)&b0,   g_b0);
    cudaGetSymbolAddress((void**)&b1,   g_b1);
    cudaGetSymbolAddress((void**)&b2,   g_b2);
    cudaGetSymbolAddress((void**)&bt,   g_bt);
    cudaGetSymbolAddress((void**)&b1t,  g_b1t);
    cudaGetSymbolAddress((void**)&b2t,  g_b2t);
    cudaGetSymbolAddress((void**)&qkvp, g_qkv);
    cudaGetSymbolAddress((void**)&wt,   g_wt);

    cudaFuncSetAttribute(attn_mma, cudaFuncAttributeMaxDynamicSharedMemorySize, ASM_BYTES);
    cudaFuncSetAttribute(gemm_pipe, cudaFuncAttributeMaxDynamicSharedMemorySize, GSM_BYTES);

    const int DD = D * D;
    float* wtp[4];
    for (int i = 0; i < 4; i++) wtp[i] = wt + i * DD;
    float* wt_in  = wt + 4 * DD;
    float* wt_out = wt_in + D3 * D;
    float* wt_ffc = wt_out + DD;

    int ncvt = 6 * DD + D3 * D;
    cvt_all<<<(ncvt + 255) / 256, 256>>>(pwp[0], pwp[1], pwp[2], pwp[3],
                                         in_w, out_w, ffc_w, (uint32_t*)wt);

    int eblocks  = (BTD + 255) / 256;
    int e4blocks = (BTD / 4 + 255) / 256;
    dim3 gg5((D + GBN - 1) / GBN, BT / GBM);    // (4, 128)
    dim3 ggq((D3 + GBN - 1) / GBN, BT / GBM);   // (12, 128)
    dim3 gga(T / AMQ, B * H);                   // (4, 320)

    posemb_kernel<<<eblocks, 256>>>(ori, x, b0);
    dwconv4_kernel<<<e4blocks, 256>>>(b0, dwp[0], dbp[0], (uint32_t*)bt);
    gemm_pipe<<<gg5, 256, GSM_BYTES>>>(bt, wtp[0], pbp[0], b0, b1, nullptr, D, D, 0);
    dwconv4_kernel<<<e4blocks, 256>>>(b1, dwp[1], dbp[1], (uint32_t*)bt);
    gemm_pipe<<<gg5, 256, GSM_BYTES>>>(bt, wtp[1], pbp[1], b1, b2, nullptr, D, D, 0);
    dwconv4_kernel<<<e4blocks, 256>>>(b2, dwp[2], dbp[2], (uint32_t*)bt);
    gemm_pipe<<<gg5, 256, GSM_BYTES>>>(bt, wtp[2], pbp[2], b2, b0, nullptr, D, D, 0);
    dwconv4_kernel<<<e4blocks, 256>>>(b0, dwp[3], dbp[3], (uint32_t*)bt);
    gemm_pipe<<<gg5, 256, GSM_BYTES>>>(bt, wtp[3], pbp[3], b0, b1, (uint32_t*)b1t, D, D, 1);
    gemm_pipe<<<ggq, 256, GSM_BYTES>>>(b1t, wt_in, in_b, nullptr, qkvp, nullptr, D3, D, 2);
    attn_mma<<<gga, 256, ASM_BYTES>>>(qkvp, xm, (uint32_t*)bt);
    gemm_pipe<<<gg5, 256, GSM_BYTES>>>(bt, wt_out, out_b, b1, b2, (uint32_t*)b2t, D, D, 1);
    gemm_pipe<<<gg5, 256, GSM_BYTES>>>(b2t, wt_ffc, ffc_b, b2, outp, nullptr, D, D, 0);
}

// round 9
// speedup vs baseline: 1.2755x; 1.2755x over previous
#include <cuda_runtime.h>
#include <cstdint>
#include <cstddef>

#define B 32
#define T 512
#define D 500
#define H 10
#define HD 50
#define D3 1500
#define BT (B*T)
#define BTD (BT*D)
#define KW 7
#define QKVP 1920   // padded qkv row pitch: 3 * H * 64

// ---------------- scratch (static device arrays; no runtime allocation) ----
__device__ float g_b0[BTD];
__device__ float g_b1[BTD];
__device__ float g_b2[BTD];
__device__ float g_bt[BTD];
__device__ float g_b1t[BTD];
__device__ float g_b2t[BTD];
__device__ float g_qkv[(size_t)BT * QKVP];
__device__ float g_wt[6 * D * D + D3 * D];
__device__ float g_wtr[4 * KW * D];          // transposed dwconv weights [K][D]

// ---------------- helpers ---------------------------------------------------
__device__ __forceinline__ uint32_t f2tf32(float x) {
    uint32_t r;
    asm("cvt.rna.tf32.f32 %0, %1;" : "=r"(r) : "f"(x));
    return r;
}
__device__ __forceinline__ uint32_t smem_u32(const void* p) {
    uint32_t a;
    asm("{ .reg .u64 t; cvta.to.shared.u64 t, %1; cvt.u32.u64 %0, t; }" : "=r"(a) : "l"(p));
    return a;
}

#define MMA_TF32(c, a, b) \
    asm volatile("mma.sync.aligned.m16n8k8.row.col.f32.tf32.tf32.f32 " \
        "{%0,%1,%2,%3}, {%4,%5,%6,%7}, {%8,%9}, {%0,%1,%2,%3};" \
        : "+f"((c)[0]), "+f"((c)[1]), "+f"((c)[2]), "+f"((c)[3]) \
        : "r"((a)[0]), "r"((a)[1]), "r"((a)[2]), "r"((a)[3]), \
          "r"((b)[0]), "r"((b)[1]))

#define CP16(dst, src) \
    asm volatile("cp.async.ca.shared.global [%0], [%1], 16;" :: "r"(dst), "l"(src) : "memory")
#define CP8(dst, src) \
    asm volatile("cp.async.ca.shared.global [%0], [%1], 8;"  :: "r"(dst), "l"(src) : "memory")
#define CP16P(dst, src, p) \
    asm volatile("cp.async.ca.shared.global [%0], [%1], 16, %2;" :: "r"(dst), "l"(src), "r"(p) : "memory")
#define CPCOMMIT() asm volatile("cp.async.commit_group;" ::: "memory")
#define CPWAIT0()  asm volatile("cp.async.wait_group 0;" ::: "memory")
#define CPWAIT1()  asm volatile("cp.async.wait_group 1;" ::: "memory")

// ---------------- merged weight prep: tf32 round + dwconv transpose --------
__global__ void cvt_all(const float* __restrict__ p0, const float* __restrict__ p1,
                        const float* __restrict__ p2, const float* __restrict__ p3,
                        const float* __restrict__ p4, const float* __restrict__ p5,
                        const float* __restrict__ p6,
                        const float* __restrict__ dw0, const float* __restrict__ dw1,
                        const float* __restrict__ dw2, const float* __restrict__ dw3,
                        uint32_t* __restrict__ o, float* __restrict__ otr) {
    const int DD = D * D;
    const int NCVT = 6 * DD + D3 * D;
    int i = blockIdx.x * blockDim.x + threadIdx.x;
    if (i < NCVT) {
        float v;
        if      (i < DD)              v = p0[i];
        else if (i < 2 * DD)          v = p1[i - DD];
        else if (i < 3 * DD)          v = p2[i - 2 * DD];
        else if (i < 4 * DD)          v = p3[i - 3 * DD];
        else if (i < 4 * DD + D3 * D) v = p4[i - 4 * DD];
        else if (i < 5 * DD + D3 * D) v = p5[i - 4 * DD - D3 * D];
        else                          v = p6[i - 5 * DD - D3 * D];
        o[i] = f2tf32(v);
    } else {
        int i2 = i - NCVT;
        if (i2 < 4 * KW * D) {
            int arr = i2 / (KW * D);
            int rem = i2 - arr * (KW * D);
            int j = rem / D;
            int d = rem - j * D;
            const float* src = (arr == 0) ? dw0 : (arr == 1) ? dw1 : (arr == 2) ? dw2 : dw3;
            // transposed, raw fp32 (dwconv math unchanged)
            otr[arr * KW * D + j * D + d] = src[d * KW + j];
        }
    }
}

// ---------------- positional embedding + add ------------------------------
__global__ void posemb_kernel(const int* __restrict__ ori,
                              const float* __restrict__ x,
                              float* __restrict__ out) {
    int idx = blockIdx.x * blockDim.x + threadIdx.x;
    if (idx >= BTD) return;
    int d  = idx % D;
    int bt = idx / D;
    int t  = bt % T;
    float pe = 0.f;
    if (ori[bt] != 0) {
        float pos = (float)(t + 1);
        int   i   = (d < 250) ? d : (d - 250);
        float ang = pos * expf((float)i * -0.036989318763f);
        pe = (d < 250) ? sinf(ang) : cosf(ang);
    }
    out[idx] = pe + x[idx];
}

// ------- depthwise conv1d (k=7, pad=3), float4, transposed weights ---------
__global__ void dwconv4_kernel(const float* __restrict__ x,
                               const float* __restrict__ wT,   // [KW][D]
                               const float* __restrict__ bias,
                               uint32_t* __restrict__ y) {
    int idx = blockIdx.x * blockDim.x + threadIdx.x;
    if (idx >= BTD / 4) return;
    int d4 = idx % (D / 4);
    int bt = idx / (D / 4);
    int t  = bt % T;
    int b  = bt / T;
    int d  = d4 * 4;
    float4 bv = *(const float4*)(bias + d);
    float a0 = bv.x, a1 = bv.y, a2 = bv.z, a3 = bv.w;
    const float* xb = x + (size_t)(b * T) * D + d;
#pragma unroll
    for (int j = 0; j < KW; j++) {
        int tt = t + j - 3;
        if (tt >= 0 && tt < T) {
            float4 v = *(const float4*)(xb + (size_t)tt * D);
            float4 w4 = *(const float4*)(wT + j * D + d);
            a0 = fmaf(w4.x, v.x, a0);
            a1 = fmaf(w4.y, v.y, a1);
            a2 = fmaf(w4.z, v.z, a2);
            a3 = fmaf(w4.w, v.w, a3);
        }
    }
    *(uint4*)(y + (size_t)idx * 4) =
        make_uint4(f2tf32(a0), f2tf32(a1), f2tf32(a2), f2tf32(a3));
}

// =================== pipelined tf32 warp-mma GEMM (round-6 proven) ==========
// modes: 0 = C fp32 (+res); 1 = + Ct tf32-rounded copy; 2 = head-padded qkv
#define GBM 128
#define GBN 128
#define GBK 32
#define SPITCH 36
#define GBUF ((GBM + GBN) * SPITCH)
#define GSM_BYTES (2 * GBUF * 4)

__global__ __launch_bounds__(256, 2)
void gemm_pipe(const float* __restrict__ A, const float* __restrict__ W,
               const float* __restrict__ bias, const float* __restrict__ res,
               float* __restrict__ C, uint32_t* __restrict__ Ct,
               int N, int Kd, int mode) {
    extern __shared__ uint32_t sm[];

    int tid  = threadIdx.x;
    int lane = tid & 31, wid = tid >> 5;
    int g = lane >> 2, t = lane & 3;
    int m0 = blockIdx.y * GBM;
    int n0 = blockIdx.x * GBN;
    int wm = (wid & 1) * 64;
    int wn = (wid >> 1) * 32;

    int r0 = tid >> 3, kg = tid & 7;
    uint32_t smbase = smem_u32(sm);
    uint32_t adst[4], bdst[4];
    const float* asrc[4];
    const float* bsrc[4];
    uint32_t bok[4];
#pragma unroll
    for (int i = 0; i < 4; i++) {
        int r = r0 + i * 32;
        adst[i] = smbase + (uint32_t)(r * SPITCH + kg * 4) * 4;
        bdst[i] = adst[i] + GBM * SPITCH * 4;
        asrc[i] = A + (size_t)(m0 + r) * Kd + kg * 4;
        int n = n0 + r;
        bok[i] = (n < N) ? 16u : 0u;
        bsrc[i] = W + (size_t)((n < N) ? n : 0) * Kd + kg * 4;
    }

    float acc[4][4][4];
#pragma unroll
    for (int mt = 0; mt < 4; mt++)
#pragma unroll
        for (int nt = 0; nt < 4; nt++)
#pragma unroll
            for (int i = 0; i < 4; i++) acc[mt][nt][i] = 0.f;

    const int KT = (Kd + GBK - 1) / GBK;

    // prologue: stage chunk 0 into buffer 0
    {
        int k = kg * 4;
        uint32_t kin = (k < Kd) ? 16u : 0u;
#pragma unroll
        for (int i = 0; i < 4; i++) {
            const float* sa = kin ? asrc[i] : A;
            CP16P(adst[i], sa, kin);
            uint32_t bb = kin & bok[i];
            const float* sb = bb ? bsrc[i] : W;
            CP16P(bdst[i], sb, bb);
        }
        CPCOMMIT();
    }

    for (int kt = 0; kt < KT; kt++) {
        int buf = kt & 1;
        if (kt + 1 < KT) {
            int k0 = (kt + 1) * GBK;
            int k = k0 + kg * 4;
            uint32_t kin = (k < Kd) ? 16u : 0u;
            uint32_t bo = (buf ^ 1) ? (uint32_t)GBUF * 4 : 0u;
#pragma unroll
            for (int i = 0; i < 4; i++) {
                const float* sa = kin ? (asrc[i] + k0) : A;
                CP16P(adst[i] + bo, sa, kin);
                uint32_t bb = kin & bok[i];
                const float* sb = bb ? (bsrc[i] + k0) : W;
                CP16P(bdst[i] + bo, sb, bb);
            }
            CPCOMMIT();
            CPWAIT1();
        } else {
            CPWAIT0();
        }
        __syncthreads();

        const uint32_t* Ab = sm + (buf ? GBUF : 0);
        const uint32_t* Bb = Ab + GBM * SPITCH;
#pragma unroll
        for (int ks = 0; ks < 4; ks++) {
            int kk = ks * 8;
            uint32_t af[4][4], bf[4][2];
#pragma unroll
            for (int mt = 0; mt < 4; mt++) {
                const uint32_t* Ar = Ab + (wm + mt * 16 + g) * SPITCH + kk;
                af[mt][0] = Ar[t];
                af[mt][1] = Ar[8 * SPITCH + t];
                af[mt][2] = Ar[t + 4];
                af[mt][3] = Ar[8 * SPITCH + t + 4];
            }
#pragma unroll
            for (int nt = 0; nt < 4; nt++) {
                const uint32_t* Br = Bb + (wn + nt * 8 + g) * SPITCH + kk;
                bf[nt][0] = Br[t];
                bf[nt][1] = Br[t + 4];
            }
#pragma unroll
            for (int mt = 0; mt < 4; mt++)
#pragma unroll
                for (int nt = 0; nt < 4; nt++)
                    MMA_TF32(acc[mt][nt], af[mt], bf[nt]);
        }
        __syncthreads();
    }

#pragma unroll
    for (int mt = 0; mt < 4; mt++) {
        int row0 = m0 + wm + mt * 16 + g;
#pragma unroll
        for (int nt = 0; nt < 4; nt++) {
            int col = n0 + wn + nt * 8 + 2 * t;
            if (col < N) {
                float2 bv = *(const float2*)(bias + col);
                float2 o0, o1;
                o0.x = acc[mt][nt][0] + bv.x;
                o0.y = acc[mt][nt][1] + bv.y;
                o1.x = acc[mt][nt][2] + bv.x;
                o1.y = acc[mt][nt][3] + bv.y;
                if (mode == 2) {
                    int which = col / 500;
                    int rem   = col - which * 500;
                    int hh    = rem / 50;
                    int dd    = rem - hh * 50;
                    size_t p0 = (size_t)row0 * QKVP + which * 640 + hh * 64 + dd;
                    size_t p1 = (size_t)(row0 + 8) * QKVP + which * 640 + hh * 64 + dd;
                    uint32_t* Cq = (uint32_t*)C;
                    *(uint2*)(Cq + p0) = make_uint2(f2tf32(o0.x), f2tf32(o0.y));
                    *(uint2*)(Cq + p1) = make_uint2(f2tf32(o1.x), f2tf32(o1.y));
                } else {
                    size_t i0 = (size_t)row0 * N + col;
                    size_t i1 = (size_t)(row0 + 8) * N + col;
                    if (res) {
                        float2 r0v = *(const float2*)(res + i0);
                        float2 r1v = *(const float2*)(res + i1);
                        o0.x += r0v.x; o0.y += r0v.y;
                        o1.x += r1v.x; o1.y += r1v.y;
                    }
                    *(float2*)(C + i0) = o0;
                    *(float2*)(C + i1) = o1;
                    if (mode == 1) {
                        *(uint2*)(Ct + i0) = make_uint2(f2tf32(o0.x), f2tf32(o0.y));
                        *(uint2*)(Ct + i1) = make_uint2(f2tf32(o1.x), f2tf32(o1.y));
                    }
                }
            }
        }
    }
}

// =================== tf32 warp-mma flash attention (round-6 proven) =========
#define AMQ 128
#define ANK 64
#define ADP 56
#define APQ 60
#define APV 68
#define ASM_BYTES ((AMQ*APQ + ANK*APQ + ADP*APV + AMQ*APV) * 4 + 64)

__global__ __launch_bounds__(256, 2)
void attn_mma(const float* __restrict__ qkv2,
              const unsigned char* __restrict__ mask,
              uint32_t* __restrict__ out) {
    extern __shared__ uint32_t dsm[];
    uint32_t* Qs = dsm;                    // [128][60]
    uint32_t* Ks = Qs + AMQ * APQ;         // [64][60]
    uint32_t* Vt = Ks + ANK * APQ;         // [56][68]
    uint32_t* Ps = Vt + ADP * APV;         // [128][68]
    unsigned char* msk = (unsigned char*)(Ps + AMQ * APV);

    int tid  = threadIdx.x;
    int lane = tid & 31, wid = tid >> 5;
    int g = lane >> 2, t = lane & 3;
    int bh = blockIdx.y;
    int b  = bh / H, h = bh % H;
    int q0 = blockIdx.x * AMQ;
    const float scale = 0.14142135623730951f;

    for (int i = tid; i < AMQ * 6; i += 256) Qs[(i / 6) * APQ + 50 + (i % 6)] = 0;
    for (int i = tid; i < ANK * 6; i += 256) Ks[(i / 6) * APQ + 50 + (i % 6)] = 0;
    for (int i = tid; i < 6 * APV; i += 256) Vt[(50 + i / APV) * APV + (i % APV)] = 0;

    {
        int r = tid >> 1, e = tid & 1;
        const float* src = qkv2 + (size_t)(b * T + q0 + r) * QKVP + h * 64;
        uint32_t dst = smem_u32(Qs + r * APQ);
#pragma unroll
        for (int c = e; c < 12; c += 2) CP16(dst + 16 * c, src + 4 * c);
        if (e == 0) CP8(dst + 192, src + 48);
        CPCOMMIT();
    }

    int wq = wid * 16;
    const uint32_t* QA = Qs + (wq + g) * APQ;
    const uint32_t* QB = Qs + (wq + g + 8) * APQ;
    uint32_t* PsA = Ps + (wq + g) * APV;
    uint32_t* PsB = Ps + (wq + g + 8) * APV;

    float m0 = -1e30f, m1 = -1e30f, l0 = 0.f, l1 = 0.f;
    float oacc[7][4];
#pragma unroll
    for (int nt = 0; nt < 7; nt++)
#pragma unroll
        for (int i = 0; i < 4; i++) oacc[nt][i] = 0.f;

    for (int kt = 0; kt < T / ANK; kt++) {
        int k0 = kt * ANK;
        __syncthreads();

        {
            int j = tid >> 2, q = tid & 3;
            const float* src = qkv2 + (size_t)(b * T + k0 + j) * QKVP + 640 + h * 64;
            uint32_t dst = smem_u32(Ks + j * APQ);
            CP16(dst + 16 * q,       src + 4 * q);
            CP16(dst + 16 * (q + 4), src + 4 * (q + 4));
            CP16(dst + 16 * (q + 8), src + 4 * (q + 8));
            if (q == 3) CP8(dst + 192, src + 48);
            CPCOMMIT();
        }
        {
            int j = tid >> 2, q = tid & 3;
            const float* src = qkv2 + (size_t)(b * T + k0 + j) * QKVP + 1280 + h * 64;
#pragma unroll
            for (int p = q; p < 25; p += 4) {
                float2 v = *(const float2*)(src + 2 * p);
                Vt[(2 * p) * APV + j]     = __float_as_uint(v.x);
                Vt[(2 * p + 1) * APV + j] = __float_as_uint(v.y);
            }
        }
        if (tid < ANK) msk[tid] = mask[b * T + k0 + tid];
        CPWAIT0();
        __syncthreads();

        float sacc[8][4];
#pragma unroll
        for (int nt = 0; nt < 8; nt++)
#pragma unroll
            for (int i = 0; i < 4; i++) sacc[nt][i] = 0.f;
#pragma unroll
        for (int ks = 0; ks < 7; ks++) {
            int kk = ks * 8;
            uint32_t af[4] = {QA[kk + t], QB[kk + t], QA[kk + t + 4], QB[kk + t + 4]};
#pragma unroll
            for (int nt = 0; nt < 8; nt++) {
                const uint32_t* Kr = Ks + (nt * 8 + g) * APQ + kk;
                uint32_t bf[2] = {Kr[t], Kr[t + 4]};
                MMA_TF32(sacc[nt], af, bf);
            }
        }

        float mx0 = -1e30f, mx1 = -1e30f;
#pragma unroll
        for (int nt = 0; nt < 8; nt++) {
            sacc[nt][0] *= scale; sacc[nt][1] *= scale;
            sacc[nt][2] *= scale; sacc[nt][3] *= scale;
            int c = nt * 8 + 2 * t;
            if (msk[c])     { sacc[nt][0] = -1e30f; sacc[nt][2] = -1e30f; }
            if (msk[c + 1]) { sacc[nt][1] = -1e30f; sacc[nt][3] = -1e30f; }
            mx0 = fmaxf(mx0, fmaxf(sacc[nt][0], sacc[nt][1]));
            mx1 = fmaxf(mx1, fmaxf(sacc[nt][2], sacc[nt][3]));
        }
        mx0 = fmaxf(mx0, __shfl_xor_sync(0xffffffffu, mx0, 1));
        mx0 = fmaxf(mx0, __shfl_xor_sync(0xffffffffu, mx0, 2));
        mx1 = fmaxf(mx1, __shfl_xor_sync(0xffffffffu, mx1, 1));
        mx1 = fmaxf(mx1, __shfl_xor_sync(0xffffffffu, mx1, 2));
        float mn0 = fmaxf(m0, mx0), mn1 = fmaxf(m1, mx1);
        float c0 = __expf(m0 - mn0), c1 = __expf(m1 - mn1);
        float s0 = 0.f, s1 = 0.f;
#pragma unroll
        for (int nt = 0; nt < 8; nt++) {
            float p00 = __expf(sacc[nt][0] - mn0);
            float p01 = __expf(sacc[nt][1] - mn0);
            float p10 = __expf(sacc[nt][2] - mn1);
            float p11 = __expf(sacc[nt][3] - mn1);
            s0 += p00 + p01;
            s1 += p10 + p11;
            int c = nt * 8 + 2 * t;
            *(uint2*)(PsA + c) = make_uint2(f2tf32(p00), f2tf32(p01));
            *(uint2*)(PsB + c) = make_uint2(f2tf32(p10), f2tf32(p11));
        }
        s0 += __shfl_xor_sync(0xffffffffu, s0, 1);
        s0 += __shfl_xor_sync(0xffffffffu, s0, 2);
        s1 += __shfl_xor_sync(0xffffffffu, s1, 1);
        s1 += __shfl_xor_sync(0xffffffffu, s1, 2);
        l0 = l0 * c0 + s0; m0 = mn0;
        l1 = l1 * c1 + s1; m1 = mn1;
#pragma unroll
        for (int nt = 0; nt < 7; nt++) {
            oacc[nt][0] *= c0; oacc[nt][1] *= c0;
            oacc[nt][2] *= c1; oacc[nt][3] *= c1;
        }
        __syncwarp();

#pragma unroll
        for (int ks = 0; ks < 8; ks++) {
            int kk = ks * 8;
            uint32_t af[4] = {PsA[kk + t], PsB[kk + t], PsA[kk + t + 4], PsB[kk + t + 4]};
#pragma unroll
            for (int nt = 0; nt < 7; nt++) {
                const uint32_t* Vr = Vt + (nt * 8 + g) * APV + kk;
                uint32_t bf[2] = {Vr[t], Vr[t + 4]};
                MMA_TF32(oacc[nt], af, bf);
            }
        }
    }

    float inv0 = 1.f / l0, inv1 = 1.f / l1;
    int r0 = q0 + wq + g;
    uint32_t* o0 = out + (size_t)(b * T + r0) * D + h * HD;
    uint32_t* o1 = o0 + (size_t)8 * D;
#pragma unroll
    for (int nt = 0; nt < 7; nt++) {
        int c = nt * 8 + 2 * t;
        if (c < HD) {
            *(uint2*)(o0 + c) = make_uint2(f2tf32(oacc[nt][0] * inv0),
                                           f2tf32(oacc[nt][1] * inv0));
            *(uint2*)(o1 + c) = make_uint2(f2tf32(oacc[nt][2] * inv1),
                                           f2tf32(oacc[nt][3] * inv1));
        }
    }
}

// ---------------- launch ----------------------------------------------------
extern "C" void kernel_launch(void* const* d_in, const int* in_sizes, int n_in,
                              void* d_out, int out_size) {
    const int* ori            = (const int*)d_in[0];
    const float* x            = (const float*)d_in[1];
    const unsigned char* xm   = (const unsigned char*)d_in[2];
    const float *dwp[4], *dbp[4], *pwp[4], *pbp[4];
    for (int i = 0; i < 4; i++) {
        dwp[i] = (const float*)d_in[3 + 4 * i];
        dbp[i] = (const float*)d_in[4 + 4 * i];
        pwp[i] = (const float*)d_in[5 + 4 * i];
        pbp[i] = (const float*)d_in[6 + 4 * i];
    }
    const float* in_w  = (const float*)d_in[19];
    const float* in_b  = (const float*)d_in[20];
    const float* out_w = (const float*)d_in[21];
    const float* out_b = (const float*)d_in[22];
    const float* ffc_w = (const float*)d_in[23];
    const float* ffc_b = (const float*)d_in[24];
    float* outp = (float*)d_out;

    float *b0, *b1, *b2, *bt, *b1t, *b2t, *qkvp, *wt, *wtr;
    cudaGetSymbolAddress((void**)&b0,   g_b0);
    cudaGetSymbolAddress((void**)&b1,   g_b1);
    cudaGetSymbolAddress((void**)&b2,   g_b2);
    cudaGetSymbolAddress((void**)&bt,   g_bt);
    cudaGetSymbolAddress((void**)&b1t,  g_b1t);
    cudaGetSymbolAddress((void**)&b2t,  g_b2t);
    cudaGetSymbolAddress((void**)&qkvp, g_qkv);
    cudaGetSymbolAddress((void**)&wt,   g_wt);
    cudaGetSymbolAddress((void**)&wtr,  g_wtr);

    cudaFuncSetAttribute(attn_mma, cudaFuncAttributeMaxDynamicSharedMemorySize, ASM_BYTES);
    cudaFuncSetAttribute(gemm_pipe, cudaFuncAttributeMaxDynamicSharedMemorySize, GSM_BYTES);

    const int DD = D * D;
    float* wtp[4];
    for (int i = 0; i < 4; i++) wtp[i] = wt + i * DD;
    float* wt_in  = wt + 4 * DD;
    float* wt_out = wt_in + D3 * D;
    float* wt_ffc = wt_out + DD;

    int ntot = 6 * DD + D3 * D + 4 * KW * D;
    cvt_all<<<(ntot + 255) / 256, 256>>>(pwp[0], pwp[1], pwp[2], pwp[3],
                                         in_w, out_w, ffc_w,
                                         dwp[0], dwp[1], dwp[2], dwp[3],
                                         (uint32_t*)wt, wtr);

    int eblocks  = (BTD + 255) / 256;
    int e4blocks = (BTD / 4 + 255) / 256;
    dim3 gg5((D + GBN - 1) / GBN, BT / GBM);    // (4, 128)
    dim3 ggq((D3 + GBN - 1) / GBN, BT / GBM);   // (12, 128)
    dim3 gga(T / AMQ, B * H);                   // (4, 320)

    posemb_kernel<<<eblocks, 256>>>(ori, x, b0);
    dwconv4_kernel<<<e4blocks, 256>>>(b0, wtr + 0 * KW * D, dbp[0], (uint32_t*)bt);
    gemm_pipe<<<gg5, 256, GSM_BYTES>>>(bt, wtp[0], pbp[0], b0, b1, nullptr, D, D, 0);
    dwconv4_kernel<<<e4blocks, 256>>>(b1, wtr + 1 * KW * D, dbp[1], (uint32_t*)bt);
    gemm_pipe<<<gg5, 256, GSM_BYTES>>>(bt, wtp[1], pbp[1], b1, b2, nullptr, D, D, 0);
    dwconv4_kernel<<<e4blocks, 256>>>(b2, wtr + 2 * KW * D, dbp[2], (uint32_t*)bt);
    gemm_pipe<<<gg5, 256, GSM_BYTES>>>(bt, wtp[2], pbp[2], b2, b0, nullptr, D, D, 0);
    dwconv4_kernel<<<e4blocks, 256>>>(b0, wtr + 3 * KW * D, dbp[3], (uint32_t*)bt);
    gemm_pipe<<<gg5, 256, GSM_BYTES>>>(bt, wtp[3], pbp[3], b0, b1, (uint32_t*)b1t, D, D, 1);
    gemm_pipe<<<ggq, 256, GSM_BYTES>>>(b1t, wt_in, in_b, nullptr, qkvp, nullptr, D3, D, 2);
    attn_mma<<<gga, 256, ASM_BYTES>>>(qkvp, xm, (uint32_t*)bt);
    gemm_pipe<<<gg5, 256, GSM_BYTES>>>(bt, wt_out, out_b, b1, b2, (uint32_t*)b2t, D, D, 1);
    gemm_pipe<<<gg5, 256, GSM_BYTES>>>(b2t, wt_ffc, ffc_b, b2, outp, nullptr, D, D, 0);
}

// round 10
// speedup vs baseline: 1.8097x; 1.4188x over previous
#include <cuda_runtime.h>
#include <cuda_fp16.h>
#include <cstdint>
#include <cstddef>

#define B 32
#define T 512
#define D 500
#define H 10
#define HD 50
#define D3 1500
#define BT (B*T)
#define BTD (BT*D)
#define KW 7
#define KAP 512      // padded activation K pitch (halves)
#define QKVP 1920    // padded qkv row pitch (floats): 3 * H * 64

// ---------------- scratch (static device arrays; no runtime allocation) ----
__device__ float  g_b0[BTD];
__device__ float  g_b1[BTD];
__device__ float  g_b2[BTD];
__device__ __half g_bt[(size_t)BT * KAP];
__device__ __half g_b1t[(size_t)BT * KAP];
__device__ __half g_b2t[(size_t)BT * KAP];
__device__ float  g_qkv[(size_t)BT * QKVP];
__device__ __half g_wt[2304000];             // padded fp16 weights
__device__ float  g_wtr[4 * KW * D];         // transposed dwconv weights [K][D]

#define PWS 256000   // 500*512
#define INS 768000   // 1500*512

// ---------------- helpers ---------------------------------------------------
__device__ __forceinline__ uint32_t f2tf32(float x) {
    uint32_t r;
    asm("cvt.rna.tf32.f32 %0, %1;" : "=r"(r) : "f"(x));
    return r;
}
__device__ __forceinline__ uint32_t smem_u32(const void* p) {
    uint32_t a;
    asm("{ .reg .u64 t; cvta.to.shared.u64 t, %1; cvt.u32.u64 %0, t; }" : "=r"(a) : "l"(p));
    return a;
}
__device__ __forceinline__ uint32_t pack_h2(float lo, float hi) {
    __half2 h = __floats2half2_rn(lo, hi);
    return *(uint32_t*)&h;
}

#define MMA_TF32(c, a, b) \
    asm volatile("mma.sync.aligned.m16n8k8.row.col.f32.tf32.tf32.f32 " \
        "{%0,%1,%2,%3}, {%4,%5,%6,%7}, {%8,%9}, {%0,%1,%2,%3};" \
        : "+f"((c)[0]), "+f"((c)[1]), "+f"((c)[2]), "+f"((c)[3]) \
        : "r"((a)[0]), "r"((a)[1]), "r"((a)[2]), "r"((a)[3]), \
          "r"((b)[0]), "r"((b)[1]))

#define MMA_F16(c, a, b) \
    asm volatile("mma.sync.aligned.m16n8k16.row.col.f32.f16.f16.f32 " \
        "{%0,%1,%2,%3}, {%4,%5,%6,%7}, {%8,%9}, {%0,%1,%2,%3};" \
        : "+f"((c)[0]), "+f"((c)[1]), "+f"((c)[2]), "+f"((c)[3]) \
        : "r"((a)[0]), "r"((a)[1]), "r"((a)[2]), "r"((a)[3]), \
          "r"((b)[0]), "r"((b)[1]))

#define CP16(dst, src) \
    asm volatile("cp.async.ca.shared.global [%0], [%1], 16;" :: "r"(dst), "l"(src) : "memory")
#define CP8(dst, src) \
    asm volatile("cp.async.ca.shared.global [%0], [%1], 8;"  :: "r"(dst), "l"(src) : "memory")
#define CP16P(dst, src, p) \
    asm volatile("cp.async.ca.shared.global [%0], [%1], 16, %2;" :: "r"(dst), "l"(src), "r"(p) : "memory")
#define CPCOMMIT() asm volatile("cp.async.commit_group;" ::: "memory")
#define CPWAIT0()  asm volatile("cp.async.wait_group 0;" ::: "memory")
#define CPWAIT1()  asm volatile("cp.async.wait_group 1;" ::: "memory")

// -------- merged weight prep: fp16 pad-convert + dwconv transpose ----------
__global__ void cvt_all(const float* __restrict__ p0, const float* __restrict__ p1,
                        const float* __restrict__ p2, const float* __restrict__ p3,
                        const float* __restrict__ p4, const float* __restrict__ p5,
                        const float* __restrict__ p6,
                        const float* __restrict__ dw0, const float* __restrict__ dw1,
                        const float* __restrict__ dw2, const float* __restrict__ dw3,
                        __half* __restrict__ wh, float* __restrict__ otr) {
    const int NW = 4 * PWS + INS + 2 * PWS;   // 2,304,000
    int i = blockIdx.x * blockDim.x + threadIdx.x;
    if (i < NW) {
        const float* src;
        int idx;
        if      (i < PWS)          { src = p0; idx = i; }
        else if (i < 2 * PWS)      { src = p1; idx = i - PWS; }
        else if (i < 3 * PWS)      { src = p2; idx = i - 2 * PWS; }
        else if (i < 4 * PWS)      { src = p3; idx = i - 3 * PWS; }
        else if (i < 4 * PWS + INS){ src = p4; idx = i - 4 * PWS; }
        else if (i < 5 * PWS + INS){ src = p5; idx = i - 4 * PWS - INS; }
        else                       { src = p6; idx = i - 5 * PWS - INS; }
        int row = idx >> 9, col = idx & 511;
        float v = (col < 500) ? src[row * 500 + col] : 0.f;
        wh[i] = __float2half(v);
    } else {
        int i2 = i - NW;
        if (i2 < 4 * KW * D) {
            int arr = i2 / (KW * D);
            int rem = i2 - arr * (KW * D);
            int j = rem / D;
            int d = rem - j * D;
            const float* src = (arr == 0) ? dw0 : (arr == 1) ? dw1 : (arr == 2) ? dw2 : dw3;
            otr[arr * KW * D + j * D + d] = src[d * KW + j];
        }
    }
}

// ---------------- positional embedding + add ------------------------------
__global__ void posemb_kernel(const int* __restrict__ ori,
                              const float* __restrict__ x,
                              float* __restrict__ out) {
    int idx = blockIdx.x * blockDim.x + threadIdx.x;
    if (idx >= BTD) return;
    int d  = idx % D;
    int bt = idx / D;
    int t  = bt % T;
    float pe = 0.f;
    if (ori[bt] != 0) {
        float pos = (float)(t + 1);
        int   i   = (d < 250) ? d : (d - 250);
        float ang = pos * expf((float)i * -0.036989318763f);
        pe = (d < 250) ? sinf(ang) : cosf(ang);
    }
    out[idx] = pe + x[idx];
}

// ------- depthwise conv1d (k=7, pad=3), float4 in, fp16 padded out ---------
__global__ void dwconv4_kernel(const float* __restrict__ x,
                               const float* __restrict__ wT,   // [KW][D]
                               const float* __restrict__ bias,
                               __half* __restrict__ y) {
    int idx = blockIdx.x * blockDim.x + threadIdx.x;
    if (idx >= BT * (KAP / 4)) return;
    int d4 = idx & 127;
    int bt = idx >> 7;
    __half* yp = y + (size_t)bt * KAP + d4 * 4;
    if (d4 >= 125) {   // pad halves 500..511
        *(uint2*)yp = make_uint2(0u, 0u);
        return;
    }
    int t = bt % T;
    int b = bt / T;
    int d = d4 * 4;
    float4 bv = *(const float4*)(bias + d);
    float a0 = bv.x, a1 = bv.y, a2 = bv.z, a3 = bv.w;
    const float* xb = x + (size_t)(b * T) * D + d;
#pragma unroll
    for (int j = 0; j < KW; j++) {
        int tt = t + j - 3;
        if (tt >= 0 && tt < T) {
            float4 v = *(const float4*)(xb + (size_t)tt * D);
            float4 w4 = *(const float4*)(wT + j * D + d);
            a0 = fmaf(w4.x, v.x, a0);
            a1 = fmaf(w4.y, v.y, a1);
            a2 = fmaf(w4.z, v.z, a2);
            a3 = fmaf(w4.w, v.w, a3);
        }
    }
    *(uint2*)yp = make_uint2(pack_h2(a0, a1), pack_h2(a2, a3));
}

// =================== pipelined fp16 warp-mma GEMM ===========================
// A: [M][KAP] fp16 (pads zero). W: [N][512] fp16 (pads zero). K chunks of 64.
// modes: 0 = C fp32 (+res); 1 = + Ct fp16 padded copy; 2 = head-padded fp32 qkv
#define GBM 128
#define GBN 128
#define SPITCH 36
#define GBUF ((GBM + GBN) * SPITCH)
#define GSM_BYTES (2 * GBUF * 4)
#define KTC 8   // 512 / 64

__global__ __launch_bounds__(256, 2)
void gemm_pipe(const __half* __restrict__ A, const __half* __restrict__ W,
               const float* __restrict__ bias, const float* __restrict__ res,
               float* __restrict__ C, __half* __restrict__ Ct,
               int N, int mode) {
    extern __shared__ uint32_t sm[];

    int tid  = threadIdx.x;
    int lane = tid & 31, wid = tid >> 5;
    int g = lane >> 2, t = lane & 3;
    int m0 = blockIdx.y * GBM;
    int n0 = blockIdx.x * GBN;
    int wm = (wid & 1) * 64;
    int wn = (wid >> 1) * 32;

    int r0 = tid >> 3, kg = tid & 7;
    uint32_t smbase = smem_u32(sm);
    uint32_t adst[4], bdst[4];
    const __half* asrc[4];
    const __half* bsrc[4];
    uint32_t bok[4];
#pragma unroll
    for (int i = 0; i < 4; i++) {
        int r = r0 + i * 32;
        adst[i] = smbase + (uint32_t)(r * SPITCH + kg * 4) * 4;
        bdst[i] = adst[i] + GBM * SPITCH * 4;
        asrc[i] = A + (size_t)(m0 + r) * KAP + kg * 8;
        int n = n0 + r;
        bok[i] = (n < N) ? 16u : 0u;
        bsrc[i] = W + (size_t)((n < N) ? n : 0) * 512 + kg * 8;
    }

    float acc[4][4][4];
#pragma unroll
    for (int mt = 0; mt < 4; mt++)
#pragma unroll
        for (int nt = 0; nt < 4; nt++)
#pragma unroll
            for (int i = 0; i < 4; i++) acc[mt][nt][i] = 0.f;

    // prologue: stage chunk 0 into buffer 0
    {
#pragma unroll
        for (int i = 0; i < 4; i++) {
            CP16(adst[i], asrc[i]);
            CP16P(bdst[i], bsrc[i], bok[i]);
        }
        CPCOMMIT();
    }

    for (int kt = 0; kt < KTC; kt++) {
        int buf = kt & 1;
        if (kt + 1 < KTC) {
            int koff = (kt + 1) * 64;   // halves
            uint32_t bo = (buf ^ 1) ? (uint32_t)GBUF * 4 : 0u;
#pragma unroll
            for (int i = 0; i < 4; i++) {
                CP16(adst[i] + bo, asrc[i] + koff);
                CP16P(bdst[i] + bo, bsrc[i] + koff, bok[i]);
            }
            CPCOMMIT();
            CPWAIT1();
        } else {
            CPWAIT0();
        }
        __syncthreads();

        const uint32_t* Ab = sm + (buf ? GBUF : 0);
        const uint32_t* Bb = Ab + GBM * SPITCH;
#pragma unroll
        for (int ks = 0; ks < 4; ks++) {
            int kk = ks * 8;   // words
            uint32_t af[4][4], bf[4][2];
#pragma unroll
            for (int mt = 0; mt < 4; mt++) {
                const uint32_t* Ar = Ab + (wm + mt * 16 + g) * SPITCH + kk;
                af[mt][0] = Ar[t];
                af[mt][1] = Ar[8 * SPITCH + t];
                af[mt][2] = Ar[t + 4];
                af[mt][3] = Ar[8 * SPITCH + t + 4];
            }
#pragma unroll
            for (int nt = 0; nt < 4; nt++) {
                const uint32_t* Br = Bb + (wn + nt * 8 + g) * SPITCH + kk;
                bf[nt][0] = Br[t];
                bf[nt][1] = Br[t + 4];
            }
#pragma unroll
            for (int mt = 0; mt < 4; mt++)
#pragma unroll
                for (int nt = 0; nt < 4; nt++)
                    MMA_F16(acc[mt][nt], af[mt], bf[nt]);
        }
        __syncthreads();
    }

#pragma unroll
    for (int mt = 0; mt < 4; mt++) {
        int row0 = m0 + wm + mt * 16 + g;
#pragma unroll
        for (int nt = 0; nt < 4; nt++) {
            int col = n0 + wn + nt * 8 + 2 * t;
            if (col < N) {
                float2 bv = *(const float2*)(bias + col);
                float2 o0, o1;
                o0.x = acc[mt][nt][0] + bv.x;
                o0.y = acc[mt][nt][1] + bv.y;
                o1.x = acc[mt][nt][2] + bv.x;
                o1.y = acc[mt][nt][3] + bv.y;
                if (mode == 2) {
                    int which = col / 500;
                    int rem   = col - which * 500;
                    int hh    = rem / 50;
                    int dd    = rem - hh * 50;
                    size_t p0 = (size_t)row0 * QKVP + which * 640 + hh * 64 + dd;
                    size_t p1 = (size_t)(row0 + 8) * QKVP + which * 640 + hh * 64 + dd;
                    uint32_t* Cq = (uint32_t*)C;
                    *(uint2*)(Cq + p0) = make_uint2(f2tf32(o0.x), f2tf32(o0.y));
                    *(uint2*)(Cq + p1) = make_uint2(f2tf32(o1.x), f2tf32(o1.y));
                } else {
                    size_t i0 = (size_t)row0 * N + col;
                    size_t i1 = (size_t)(row0 + 8) * N + col;
                    if (res) {
                        float2 r0v = *(const float2*)(res + i0);
                        float2 r1v = *(const float2*)(res + i1);
                        o0.x += r0v.x; o0.y += r0v.y;
                        o1.x += r1v.x; o1.y += r1v.y;
                    }
                    *(float2*)(C + i0) = o0;
                    *(float2*)(C + i1) = o1;
                    if (mode == 1) {
                        size_t q0i = (size_t)row0 * KAP + col;
                        size_t q1i = (size_t)(row0 + 8) * KAP + col;
                        *(uint32_t*)(Ct + q0i) = pack_h2(o0.x, o0.y);
                        *(uint32_t*)(Ct + q1i) = pack_h2(o1.x, o1.y);
                    }
                }
            }
        }
    }
    // zero pad cols 500..511 of the fp16 copy (one warp-slice; rows this CTA owns)
    if (mode == 1 && n0 == 0 && lane < 16) {
        int row = m0 + wm + (lane & 15);
#pragma unroll
        for (int rr = 0; rr < 4; rr++) {
            uint32_t* pz = (uint32_t*)(Ct + (size_t)(row + rr * 16) * KAP + 500);
#pragma unroll
            for (int w = 0; w < 6; w++) pz[w] = 0u;
        }
    }
}

// =================== tf32 warp-mma flash attention (fp16 output) ============
#define AMQ 128
#define ANK 64
#define ADP 56
#define APQ 60
#define APV 68
#define ASM_BYTES ((AMQ*APQ + ANK*APQ + ADP*APV + AMQ*APV) * 4 + 64)

__global__ __launch_bounds__(256, 2)
void attn_mma(const float* __restrict__ qkv2,
              const unsigned char* __restrict__ mask,
              __half* __restrict__ outh) {
    extern __shared__ uint32_t dsm[];
    uint32_t* Qs = dsm;                    // [128][60]
    uint32_t* Ks = Qs + AMQ * APQ;         // [64][60]
    uint32_t* Vt = Ks + ANK * APQ;         // [56][68]
    uint32_t* Ps = Vt + ADP * APV;         // [128][68]
    unsigned char* msk = (unsigned char*)(Ps + AMQ * APV);

    int tid  = threadIdx.x;
    int lane = tid & 31, wid = tid >> 5;
    int g = lane >> 2, t = lane & 3;
    int bh = blockIdx.y;
    int b  = bh / H, h = bh % H;
    int q0 = blockIdx.x * AMQ;
    const float scale = 0.14142135623730951f;

    for (int i = tid; i < AMQ * 6; i += 256) Qs[(i / 6) * APQ + 50 + (i % 6)] = 0;
    for (int i = tid; i < ANK * 6; i += 256) Ks[(i / 6) * APQ + 50 + (i % 6)] = 0;
    for (int i = tid; i < 6 * APV; i += 256) Vt[(50 + i / APV) * APV + (i % APV)] = 0;

    {
        int r = tid >> 1, e = tid & 1;
        const float* src = qkv2 + (size_t)(b * T + q0 + r) * QKVP + h * 64;
        uint32_t dst = smem_u32(Qs + r * APQ);
#pragma unroll
        for (int c = e; c < 12; c += 2) CP16(dst + 16 * c, src + 4 * c);
        if (e == 0) CP8(dst + 192, src + 48);
        CPCOMMIT();
    }

    int wq = wid * 16;
    const uint32_t* QA = Qs + (wq + g) * APQ;
    const uint32_t* QB = Qs + (wq + g + 8) * APQ;
    uint32_t* PsA = Ps + (wq + g) * APV;
    uint32_t* PsB = Ps + (wq + g + 8) * APV;

    float m0 = -1e30f, m1 = -1e30f, l0 = 0.f, l1 = 0.f;
    float oacc[7][4];
#pragma unroll
    for (int nt = 0; nt < 7; nt++)
#pragma unroll
        for (int i = 0; i < 4; i++) oacc[nt][i] = 0.f;

    for (int kt = 0; kt < T / ANK; kt++) {
        int k0 = kt * ANK;
        __syncthreads();

        {
            int j = tid >> 2, q = tid & 3;
            const float* src = qkv2 + (size_t)(b * T + k0 + j) * QKVP + 640 + h * 64;
            uint32_t dst = smem_u32(Ks + j * APQ);
            CP16(dst + 16 * q,       src + 4 * q);
            CP16(dst + 16 * (q + 4), src + 4 * (q + 4));
            CP16(dst + 16 * (q + 8), src + 4 * (q + 8));
            if (q == 3) CP8(dst + 192, src + 48);
            CPCOMMIT();
        }
        {
            int j = tid >> 2, q = tid & 3;
            const float* src = qkv2 + (size_t)(b * T + k0 + j) * QKVP + 1280 + h * 64;
#pragma unroll
            for (int p = q; p < 25; p += 4) {
                float2 v = *(const float2*)(src + 2 * p);
                Vt[(2 * p) * APV + j]     = __float_as_uint(v.x);
                Vt[(2 * p + 1) * APV + j] = __float_as_uint(v.y);
            }
        }
        if (tid < ANK) msk[tid] = mask[b * T + k0 + tid];
        CPWAIT0();
        __syncthreads();

        float sacc[8][4];
#pragma unroll
        for (int nt = 0; nt < 8; nt++)
#pragma unroll
            for (int i = 0; i < 4; i++) sacc[nt][i] = 0.f;
#pragma unroll
        for (int ks = 0; ks < 7; ks++) {
            int kk = ks * 8;
            uint32_t af[4] = {QA[kk + t], QB[kk + t], QA[kk + t + 4], QB[kk + t + 4]};
#pragma unroll
            for (int nt = 0; nt < 8; nt++) {
                const uint32_t* Kr = Ks + (nt * 8 + g) * APQ + kk;
                uint32_t bf[2] = {Kr[t], Kr[t + 4]};
                MMA_TF32(sacc[nt], af, bf);
            }
        }

        float mx0 = -1e30f, mx1 = -1e30f;
#pragma unroll
        for (int nt = 0; nt < 8; nt++) {
            sacc[nt][0] *= scale; sacc[nt][1] *= scale;
            sacc[nt][2] *= scale; sacc[nt][3] *= scale;
            int c = nt * 8 + 2 * t;
            if (msk[c])     { sacc[nt][0] = -1e30f; sacc[nt][2] = -1e30f; }
            if (msk[c + 1]) { sacc[nt][1] = -1e30f; sacc[nt][3] = -1e30f; }
            mx0 = fmaxf(mx0, fmaxf(sacc[nt][0], sacc[nt][1]));
            mx1 = fmaxf(mx1, fmaxf(sacc[nt][2], sacc[nt][3]));
        }
        mx0 = fmaxf(mx0, __shfl_xor_sync(0xffffffffu, mx0, 1));
        mx0 = fmaxf(mx0, __shfl_xor_sync(0xffffffffu, mx0, 2));
        mx1 = fmaxf(mx1, __shfl_xor_sync(0xffffffffu, mx1, 1));
        mx1 = fmaxf(mx1, __shfl_xor_sync(0xffffffffu, mx1, 2));
        float mn0 = fmaxf(m0, mx0), mn1 = fmaxf(m1, mx1);
        float c0 = __expf(m0 - mn0), c1 = __expf(m1 - mn1);
        float s0 = 0.f, s1 = 0.f;
#pragma unroll
        for (int nt = 0; nt < 8; nt++) {
            float p00 = __expf(sacc[nt][0] - mn0);
            float p01 = __expf(sacc[nt][1] - mn0);
            float p10 = __expf(sacc[nt][2] - mn1);
            float p11 = __expf(sacc[nt][3] - mn1);
            s0 += p00 + p01;
            s1 += p10 + p11;
            int c = nt * 8 + 2 * t;
            *(uint2*)(PsA + c) = make_uint2(f2tf32(p00), f2tf32(p01));
            *(uint2*)(PsB + c) = make_uint2(f2tf32(p10), f2tf32(p11));
        }
        s0 += __shfl_xor_sync(0xffffffffu, s0, 1);
        s0 += __shfl_xor_sync(0xffffffffu, s0, 2);
        s1 += __shfl_xor_sync(0xffffffffu, s1, 1);
        s1 += __shfl_xor_sync(0xffffffffu, s1, 2);
        l0 = l0 * c0 + s0; m0 = mn0;
        l1 = l1 * c1 + s1; m1 = mn1;
#pragma unroll
        for (int nt = 0; nt < 7; nt++) {
            oacc[nt][0] *= c0; oacc[nt][1] *= c0;
            oacc[nt][2] *= c1; oacc[nt][3] *= c1;
        }
        __syncwarp();

#pragma unroll
        for (int ks = 0; ks < 8; ks++) {
            int kk = ks * 8;
            uint32_t af[4] = {PsA[kk + t], PsB[kk + t], PsA[kk + t + 4], PsB[kk + t + 4]};
#pragma unroll
            for (int nt = 0; nt < 7; nt++) {
                const uint32_t* Vr = Vt + (nt * 8 + g) * APV + kk;
                uint32_t bf[2] = {Vr[t], Vr[t + 4]};
                MMA_TF32(oacc[nt], af, bf);
            }
        }
    }

    // epilogue: O / l as fp16 into padded [BT][KAP]
    float inv0 = 1.f / l0, inv1 = 1.f / l1;
    int r0 = q0 + wq + g;
    __half* o0 = outh + (size_t)(b * T + r0) * KAP + h * HD;
    __half* o1 = o0 + (size_t)8 * KAP;
#pragma unroll
    for (int nt = 0; nt < 7; nt++) {
        int c = nt * 8 + 2 * t;
        if (c < HD) {
            *(uint32_t*)(o0 + c) = pack_h2(oacc[nt][0] * inv0, oacc[nt][1] * inv0);
            *(uint32_t*)(o1 + c) = pack_h2(oacc[nt][2] * inv1, oacc[nt][3] * inv1);
        }
    }
    // zero pad halves 500..511 (one head-block per (b,q0) does it)
    if (h == 0 && lane < 16) {
        int row = q0 + wq + (lane & 15);
        uint32_t* pz = (uint32_t*)(outh + (size_t)(b * T + row) * KAP + 500);
#pragma unroll
        for (int w = 0; w < 6; w++) pz[w] = 0u;
    }
}

// ---------------- launch ----------------------------------------------------
extern "C" void kernel_launch(void* const* d_in, const int* in_sizes, int n_in,
                              void* d_out, int out_size) {
    const int* ori            = (const int*)d_in[0];
    const float* x            = (const float*)d_in[1];
    const unsigned char* xm   = (const unsigned char*)d_in[2];
    const float *dwp[4], *dbp[4], *pwp[4], *pbp[4];
    for (int i = 0; i < 4; i++) {
        dwp[i] = (const float*)d_in[3 + 4 * i];
        dbp[i] = (const float*)d_in[4 + 4 * i];
        pwp[i] = (const float*)d_in[5 + 4 * i];
        pbp[i] = (const float*)d_in[6 + 4 * i];
    }
    const float* in_w  = (const float*)d_in[19];
    const float* in_b  = (const float*)d_in[20];
    const float* out_w = (const float*)d_in[21];
    const float* out_b = (const float*)d_in[22];
    const float* ffc_w = (const float*)d_in[23];
    const float* ffc_b = (const float*)d_in[24];
    float* outp = (float*)d_out;

    float *b0, *b1, *b2, *qkvp, *wtr;
    __half *bt, *b1t, *b2t, *wth;
    cudaGetSymbolAddress((void**)&b0,   g_b0);
    cudaGetSymbolAddress((void**)&b1,   g_b1);
    cudaGetSymbolAddress((void**)&b2,   g_b2);
    cudaGetSymbolAddress((void**)&bt,   g_bt);
    cudaGetSymbolAddress((void**)&b1t,  g_b1t);
    cudaGetSymbolAddress((void**)&b2t,  g_b2t);
    cudaGetSymbolAddress((void**)&qkvp, g_qkv);
    cudaGetSymbolAddress((void**)&wth,  g_wt);
    cudaGetSymbolAddress((void**)&wtr,  g_wtr);

    cudaFuncSetAttribute(attn_mma, cudaFuncAttributeMaxDynamicSharedMemorySize, ASM_BYTES);
    cudaFuncSetAttribute(gemm_pipe, cudaFuncAttributeMaxDynamicSharedMemorySize, GSM_BYTES);

    __half* wtp[4];
    for (int i = 0; i < 4; i++) wtp[i] = wth + i * PWS;
    __half* wt_in  = wth + 4 * PWS;
    __half* wt_out = wt_in + INS;
    __half* wt_ffc = wt_out + PWS;

    int ntot = 4 * PWS + INS + 2 * PWS + 4 * KW * D;
    cvt_all<<<(ntot + 255) / 256, 256>>>(pwp[0], pwp[1], pwp[2], pwp[3],
                                         in_w, out_w, ffc_w,
                                         dwp[0], dwp[1], dwp[2], dwp[3],
                                         wth, wtr);

    int eblocks  = (BTD + 255) / 256;
    int e4blocks = (BT * (KAP / 4) + 255) / 256;
    dim3 gg5((D + GBN - 1) / GBN, BT / GBM);    // (4, 128)
    dim3 ggq((D3 + GBN - 1) / GBN, BT / GBM);   // (12, 128)
    dim3 gga(T / AMQ, B * H);                   // (4, 320)

    posemb_kernel<<<eblocks, 256>>>(ori, x, b0);
    dwconv4_kernel<<<e4blocks, 256>>>(b0, wtr + 0 * KW * D, dbp[0], bt);
    gemm_pipe<<<gg5, 256, GSM_BYTES>>>(bt, wtp[0], pbp[0], b0, b1, nullptr, D, 0);
    dwconv4_kernel<<<e4blocks, 256>>>(b1, wtr + 1 * KW * D, dbp[1], bt);
    gemm_pipe<<<gg5, 256, GSM_BYTES>>>(bt, wtp[1], pbp[1], b1, b2, nullptr, D, 0);
    dwconv4_kernel<<<e4blocks, 256>>>(b2, wtr + 2 * KW * D, dbp[2], bt);
    gemm_pipe<<<gg5, 256, GSM_BYTES>>>(bt, wtp[2], pbp[2], b2, b0, nullptr, D, 0);
    dwconv4_kernel<<<e4blocks, 256>>>(b0, wtr + 3 * KW * D, dbp[3], bt);
    gemm_pipe<<<gg5, 256, GSM_BYTES>>>(bt, wtp[3], pbp[3], b0, b1, b1t, D, 1);
    gemm_pipe<<<ggq, 256, GSM_BYTES>>>(b1t, wt_in, in_b, nullptr, qkvp, nullptr, D3, 2);
    attn_mma<<<gga, 256, ASM_BYTES>>>(qkvp, xm, bt);
    gemm_pipe<<<gg5, 256, GSM_BYTES>>>(bt, wt_out, out_b, b1, b2, b2t, D, 1);
    gemm_pipe<<<gg5, 256, GSM_BYTES>>>(b2t, wt_ffc, ffc_b, b2, outp, nullptr, D, 0);
}

// round 11
// speedup vs baseline: 1.9504x; 1.0778x over previous
#include <cuda_runtime.h>
#include <cuda_fp16.h>
#include <cstdint>
#include <cstddef>

#define B 32
#define T 512
#define D 500
#define H 10
#define HD 50
#define D3 1500
#define BT (B*T)
#define BTD (BT*D)
#define KW 7
#define KAP 512      // padded activation K pitch (halves)
#define QKVP 1920    // padded qkv row pitch (halves): 3 * H * 64

// ---------------- scratch (static device arrays; no runtime allocation) ----
__device__ float  g_b0[BTD];
__device__ float  g_b1[BTD];
__device__ float  g_b2[BTD];
__device__ __half g_bt[(size_t)BT * KAP];
__device__ __half g_b1t[(size_t)BT * KAP];
__device__ __half g_b2t[(size_t)BT * KAP];
__device__ __half g_qkv[(size_t)BT * QKVP];
__device__ __half g_wt[2304000];             // padded fp16 weights
__device__ float  g_wtr[4 * KW * D];         // transposed dwconv weights [K][D]

#define PWS 256000   // 500*512
#define INS 768000   // 1500*512

// ---------------- helpers ---------------------------------------------------
__device__ __forceinline__ uint32_t smem_u32(const void* p) {
    uint32_t a;
    asm("{ .reg .u64 t; cvta.to.shared.u64 t, %1; cvt.u32.u64 %0, t; }" : "=r"(a) : "l"(p));
    return a;
}
__device__ __forceinline__ uint32_t pack_h2(float lo, float hi) {
    __half2 h = __floats2half2_rn(lo, hi);
    return *(uint32_t*)&h;
}

#define MMA_F16(c, a, b) \
    asm volatile("mma.sync.aligned.m16n8k16.row.col.f32.f16.f16.f32 " \
        "{%0,%1,%2,%3}, {%4,%5,%6,%7}, {%8,%9}, {%0,%1,%2,%3};" \
        : "+f"((c)[0]), "+f"((c)[1]), "+f"((c)[2]), "+f"((c)[3]) \
        : "r"((a)[0]), "r"((a)[1]), "r"((a)[2]), "r"((a)[3]), \
          "r"((b)[0]), "r"((b)[1]))

#define CP16(dst, src) \
    asm volatile("cp.async.ca.shared.global [%0], [%1], 16;" :: "r"(dst), "l"(src) : "memory")
#define CP16P(dst, src, p) \
    asm volatile("cp.async.ca.shared.global [%0], [%1], 16, %2;" :: "r"(dst), "l"(src), "r"(p) : "memory")
#define CPCOMMIT() asm volatile("cp.async.commit_group;" ::: "memory")
#define CPWAIT0()  asm volatile("cp.async.wait_group 0;" ::: "memory")
#define CPWAIT1()  asm volatile("cp.async.wait_group 1;" ::: "memory")

// -------- merged weight prep: fp16 pad-convert + dwconv transpose ----------
__global__ void cvt_all(const float* __restrict__ p0, const float* __restrict__ p1,
                        const float* __restrict__ p2, const float* __restrict__ p3,
                        const float* __restrict__ p4, const float* __restrict__ p5,
                        const float* __restrict__ p6,
                        const float* __restrict__ dw0, const float* __restrict__ dw1,
                        const float* __restrict__ dw2, const float* __restrict__ dw3,
                        __half* __restrict__ wh, float* __restrict__ otr) {
    const int NW = 4 * PWS + INS + 2 * PWS;   // 2,304,000
    int i = blockIdx.x * blockDim.x + threadIdx.x;
    if (i < NW) {
        const float* src;
        int idx;
        if      (i < PWS)          { src = p0; idx = i; }
        else if (i < 2 * PWS)      { src = p1; idx = i - PWS; }
        else if (i < 3 * PWS)      { src = p2; idx = i - 2 * PWS; }
        else if (i < 4 * PWS)      { src = p3; idx = i - 3 * PWS; }
        else if (i < 4 * PWS + INS){ src = p4; idx = i - 4 * PWS; }
        else if (i < 5 * PWS + INS){ src = p5; idx = i - 4 * PWS - INS; }
        else                       { src = p6; idx = i - 5 * PWS - INS; }
        int row = idx >> 9, col = idx & 511;
        float v = (col < 500) ? src[row * 500 + col] : 0.f;
        wh[i] = __float2half(v);
    } else {
        int i2 = i - NW;
        if (i2 < 4 * KW * D) {
            int arr = i2 / (KW * D);
            int rem = i2 - arr * (KW * D);
            int j = rem / D;
            int d = rem - j * D;
            const float* src = (arr == 0) ? dw0 : (arr == 1) ? dw1 : (arr == 2) ? dw2 : dw3;
            otr[arr * KW * D + j * D + d] = src[d * KW + j];
        }
    }
}

// ---------------- zero qkv head-slot pad lanes (50..63 of each 64) ---------
__global__ void zero_qkv_pads(__half* __restrict__ q) {
    int i = blockIdx.x * blockDim.x + threadIdx.x;
    if (i >= BT * 30) return;
    int row = i / 30, slot = i - row * 30;
    uint32_t* p = (uint32_t*)(q + (size_t)row * QKVP + slot * 64 + 50);
#pragma unroll
    for (int w = 0; w < 7; w++) p[w] = 0u;
}

// ---------------- positional embedding + add ------------------------------
__global__ void posemb_kernel(const int* __restrict__ ori,
                              const float* __restrict__ x,
                              float* __restrict__ out) {
    int idx = blockIdx.x * blockDim.x + threadIdx.x;
    if (idx >= BTD) return;
    int d  = idx % D;
    int bt = idx / D;
    int t  = bt % T;
    float pe = 0.f;
    if (ori[bt] != 0) {
        float pos = (float)(t + 1);
        int   i   = (d < 250) ? d : (d - 250);
        float ang = pos * expf((float)i * -0.036989318763f);
        pe = (d < 250) ? sinf(ang) : cosf(ang);
    }
    out[idx] = pe + x[idx];
}

// ------- depthwise conv1d (k=7, pad=3), float4 in, fp16 padded out ---------
__global__ void dwconv4_kernel(const float* __restrict__ x,
                               const float* __restrict__ wT,   // [KW][D]
                               const float* __restrict__ bias,
                               __half* __restrict__ y) {
    int idx = blockIdx.x * blockDim.x + threadIdx.x;
    if (idx >= BT * (KAP / 4)) return;
    int d4 = idx & 127;
    int bt = idx >> 7;
    __half* yp = y + (size_t)bt * KAP + d4 * 4;
    if (d4 >= 125) {
        *(uint2*)yp = make_uint2(0u, 0u);
        return;
    }
    int t = bt % T;
    int b = bt / T;
    int d = d4 * 4;
    float4 bv = *(const float4*)(bias + d);
    float a0 = bv.x, a1 = bv.y, a2 = bv.z, a3 = bv.w;
    const float* xb = x + (size_t)(b * T) * D + d;
#pragma unroll
    for (int j = 0; j < KW; j++) {
        int tt = t + j - 3;
        if (tt >= 0 && tt < T) {
            float4 v = *(const float4*)(xb + (size_t)tt * D);
            float4 w4 = *(const float4*)(wT + j * D + d);
            a0 = fmaf(w4.x, v.x, a0);
            a1 = fmaf(w4.y, v.y, a1);
            a2 = fmaf(w4.z, v.z, a2);
            a3 = fmaf(w4.w, v.w, a3);
        }
    }
    *(uint2*)yp = make_uint2(pack_h2(a0, a1), pack_h2(a2, a3));
}

// =================== pipelined fp16 warp-mma GEMM ===========================
// modes: 0 = C fp32 (+res); 1 = + Ct fp16 padded copy; 2 = head-padded fp16 qkv
#define GBM 128
#define GBN 128
#define SPITCH 36
#define GBUF ((GBM + GBN) * SPITCH)
#define GSM_BYTES (2 * GBUF * 4)
#define KTC 8   // 512 / 64

__global__ __launch_bounds__(256, 2)
void gemm_pipe(const __half* __restrict__ A, const __half* __restrict__ W,
               const float* __restrict__ bias, const float* __restrict__ res,
               float* __restrict__ C, __half* __restrict__ Ct,
               int N, int mode) {
    extern __shared__ uint32_t sm[];

    int tid  = threadIdx.x;
    int lane = tid & 31, wid = tid >> 5;
    int g = lane >> 2, t = lane & 3;
    int m0 = blockIdx.y * GBM;
    int n0 = blockIdx.x * GBN;
    int wm = (wid & 1) * 64;
    int wn = (wid >> 1) * 32;

    int r0 = tid >> 3, kg = tid & 7;
    uint32_t smbase = smem_u32(sm);
    uint32_t adst[4], bdst[4];
    const __half* asrc[4];
    const __half* bsrc[4];
    uint32_t bok[4];
#pragma unroll
    for (int i = 0; i < 4; i++) {
        int r = r0 + i * 32;
        adst[i] = smbase + (uint32_t)(r * SPITCH + kg * 4) * 4;
        bdst[i] = adst[i] + GBM * SPITCH * 4;
        asrc[i] = A + (size_t)(m0 + r) * KAP + kg * 8;
        int n = n0 + r;
        bok[i] = (n < N) ? 16u : 0u;
        bsrc[i] = W + (size_t)((n < N) ? n : 0) * 512 + kg * 8;
    }

    float acc[4][4][4];
#pragma unroll
    for (int mt = 0; mt < 4; mt++)
#pragma unroll
        for (int nt = 0; nt < 4; nt++)
#pragma unroll
            for (int i = 0; i < 4; i++) acc[mt][nt][i] = 0.f;

    {
#pragma unroll
        for (int i = 0; i < 4; i++) {
            CP16(adst[i], asrc[i]);
            CP16P(bdst[i], bsrc[i], bok[i]);
        }
        CPCOMMIT();
    }

    for (int kt = 0; kt < KTC; kt++) {
        int buf = kt & 1;
        if (kt + 1 < KTC) {
            int koff = (kt + 1) * 64;
            uint32_t bo = (buf ^ 1) ? (uint32_t)GBUF * 4 : 0u;
#pragma unroll
            for (int i = 0; i < 4; i++) {
                CP16(adst[i] + bo, asrc[i] + koff);
                CP16P(bdst[i] + bo, bsrc[i] + koff, bok[i]);
            }
            CPCOMMIT();
            CPWAIT1();
        } else {
            CPWAIT0();
        }
        __syncthreads();

        const uint32_t* Ab = sm + (buf ? GBUF : 0);
        const uint32_t* Bb = Ab + GBM * SPITCH;
#pragma unroll
        for (int ks = 0; ks < 4; ks++) {
            int kk = ks * 8;
            uint32_t af[4][4], bf[4][2];
#pragma unroll
            for (int mt = 0; mt < 4; mt++) {
                const uint32_t* Ar = Ab + (wm + mt * 16 + g) * SPITCH + kk;
                af[mt][0] = Ar[t];
                af[mt][1] = Ar[8 * SPITCH + t];
                af[mt][2] = Ar[t + 4];
                af[mt][3] = Ar[8 * SPITCH + t + 4];
            }
#pragma unroll
            for (int nt = 0; nt < 4; nt++) {
                const uint32_t* Br = Bb + (wn + nt * 8 + g) * SPITCH + kk;
                bf[nt][0] = Br[t];
                bf[nt][1] = Br[t + 4];
            }
#pragma unroll
            for (int mt = 0; mt < 4; mt++)
#pragma unroll
                for (int nt = 0; nt < 4; nt++)
                    MMA_F16(acc[mt][nt], af[mt], bf[nt]);
        }
        __syncthreads();
    }

#pragma unroll
    for (int mt = 0; mt < 4; mt++) {
        int row0 = m0 + wm + mt * 16 + g;
#pragma unroll
        for (int nt = 0; nt < 4; nt++) {
            int col = n0 + wn + nt * 8 + 2 * t;
            if (col < N) {
                float2 bv = *(const float2*)(bias + col);
                float2 o0, o1;
                o0.x = acc[mt][nt][0] + bv.x;
                o0.y = acc[mt][nt][1] + bv.y;
                o1.x = acc[mt][nt][2] + bv.x;
                o1.y = acc[mt][nt][3] + bv.y;
                if (mode == 2) {
                    // head-padded fp16 qkv: col -> (which, head, d); dd is even
                    int which = col / 500;
                    int rem   = col - which * 500;
                    int hh    = rem / 50;
                    int dd    = rem - hh * 50;
                    size_t p0 = (size_t)row0 * QKVP + which * 640 + hh * 64 + dd;
                    size_t p1 = (size_t)(row0 + 8) * QKVP + which * 640 + hh * 64 + dd;
                    __half* Ch = (__half*)Ct;
                    *(uint32_t*)(Ch + p0) = pack_h2(o0.x, o0.y);
                    *(uint32_t*)(Ch + p1) = pack_h2(o1.x, o1.y);
                } else {
                    size_t i0 = (size_t)row0 * N + col;
                    size_t i1 = (size_t)(row0 + 8) * N + col;
                    if (res) {
                        float2 r0v = *(const float2*)(res + i0);
                        float2 r1v = *(const float2*)(res + i1);
                        o0.x += r0v.x; o0.y += r0v.y;
                        o1.x += r1v.x; o1.y += r1v.y;
                    }
                    *(float2*)(C + i0) = o0;
                    *(float2*)(C + i1) = o1;
                    if (mode == 1) {
                        size_t q0i = (size_t)row0 * KAP + col;
                        size_t q1i = (size_t)(row0 + 8) * KAP + col;
                        *(uint32_t*)(Ct + q0i) = pack_h2(o0.x, o0.y);
                        *(uint32_t*)(Ct + q1i) = pack_h2(o1.x, o1.y);
                    }
                }
            }
        }
    }
    if (mode == 1 && n0 == 0 && lane < 16) {
        int row = m0 + wm + (lane & 15);
#pragma unroll
        for (int rr = 0; rr < 4; rr++) {
            uint32_t* pz = (uint32_t*)(Ct + (size_t)(row + rr * 16) * KAP + 500);
#pragma unroll
            for (int w = 0; w < 6; w++) pz[w] = 0u;
        }
    }
}

// =================== fp16 warp-mma flash attention ==========================
// qkv fp16 head-padded [BT][1920]; pads pre-zeroed. Pitch 36 words everywhere.
#define AMQ 128
#define ANK 64
#define APW 36
#define ASM_BYTES (((AMQ + ANK + 56 + AMQ) * APW) * 4 + 64)

__global__ __launch_bounds__(256, 2)
void attn_mma(const __half* __restrict__ qkvh,
              const unsigned char* __restrict__ mask,
              __half* __restrict__ outh) {
    extern __shared__ uint32_t dsm[];
    uint32_t* Qs = dsm;                    // [128][36] words (64 halves + pad)
    uint32_t* Ks = Qs + AMQ * APW;         // [64][36]
    uint32_t* Vt = Ks + ANK * APW;         // [56][36]  (d, j) halves
    uint32_t* Ps = Vt + 56 * APW;          // [128][36]
    unsigned char* msk = (unsigned char*)(Ps + AMQ * APW);

    int tid  = threadIdx.x;
    int lane = tid & 31, wid = tid >> 5;
    int g = lane >> 2, t = lane & 3;
    int bh = blockIdx.y;
    int b  = bh / H, h = bh % H;
    int q0 = blockIdx.x * AMQ;
    const float scale = 0.14142135623730951f;

    // zero Vt pad rows 50..55 once
    for (int i = tid; i < 6 * 32; i += 256)
        Vt[(50 + i / 32) * APW + (i % 32)] = 0;

    // stage Q (fp16 rows, 128B each, pads already zero in gmem)
    {
        int r = tid >> 1, e = tid & 1;
        const __half* src = qkvh + (size_t)(b * T + q0 + r) * QKVP + h * 64;
        uint32_t dst = smem_u32(Qs + r * APW);
#pragma unroll
        for (int c = e; c < 8; c += 2) CP16(dst + 16 * c, src + 8 * c);
        CPCOMMIT();
    }

    int wq = wid * 16;
    const uint32_t* QA = Qs + (wq + g) * APW;
    const uint32_t* QB = Qs + (wq + g + 8) * APW;
    uint32_t* PsA = Ps + (wq + g) * APW;
    uint32_t* PsB = Ps + (wq + g + 8) * APW;

    float m0 = -1e30f, m1 = -1e30f, l0 = 0.f, l1 = 0.f;
    float oacc[7][4];
#pragma unroll
    for (int nt = 0; nt < 7; nt++)
#pragma unroll
        for (int i = 0; i < 4; i++) oacc[nt][i] = 0.f;

    for (int kt = 0; kt < T / ANK; kt++) {
        int k0 = kt * ANK;
        __syncthreads();

        // K via cp.async (full 128B rows)
        {
            int j = tid >> 2, q = tid & 3;
            const __half* src = qkvh + (size_t)(b * T + k0 + j) * QKVP + 640 + h * 64;
            uint32_t dst = smem_u32(Ks + j * APW);
            CP16(dst + 16 * q,       src + 8 * q);
            CP16(dst + 16 * (q + 4), src + 8 * (q + 4));
            CPCOMMIT();
        }
        // V fp16 transpose (d<50)
        {
            int j = tid >> 2, q = tid & 3;
            const __half* src = qkvh + (size_t)(b * T + k0 + j) * QKVP + 1280 + h * 64;
#pragma unroll
            for (int p = q; p < 25; p += 4) {
                uint32_t v = *(const uint32_t*)(src + 2 * p);
                __half2 hv = *(__half2*)&v;
                ((__half*)(Vt + (2 * p) * APW))[j]     = hv.x;
                ((__half*)(Vt + (2 * p + 1) * APW))[j] = hv.y;
            }
        }
        if (tid < ANK) msk[tid] = mask[b * T + k0 + tid];
        CPWAIT0();
        __syncthreads();

        // ---- S = Q K^T : fp16 m16n8k16, 4 k-steps
        float sacc[8][4];
#pragma unroll
        for (int nt = 0; nt < 8; nt++)
#pragma unroll
            for (int i = 0; i < 4; i++) sacc[nt][i] = 0.f;
#pragma unroll
        for (int ks = 0; ks < 4; ks++) {
            int kk = ks * 8;
            uint32_t af[4] = {QA[kk + t], QB[kk + t], QA[kk + t + 4], QB[kk + t + 4]};
#pragma unroll
            for (int nt = 0; nt < 8; nt++) {
                const uint32_t* Kr = Ks + (nt * 8 + g) * APW + kk;
                uint32_t bf[2] = {Kr[t], Kr[t + 4]};
                MMA_F16(sacc[nt], af, bf);
            }
        }

        // ---- scale + mask + online softmax (fragment layout unchanged)
        float mx0 = -1e30f, mx1 = -1e30f;
#pragma unroll
        for (int nt = 0; nt < 8; nt++) {
            sacc[nt][0] *= scale; sacc[nt][1] *= scale;
            sacc[nt][2] *= scale; sacc[nt][3] *= scale;
            int c = nt * 8 + 2 * t;
            if (msk[c])     { sacc[nt][0] = -1e30f; sacc[nt][2] = -1e30f; }
            if (msk[c + 1]) { sacc[nt][1] = -1e30f; sacc[nt][3] = -1e30f; }
            mx0 = fmaxf(mx0, fmaxf(sacc[nt][0], sacc[nt][1]));
            mx1 = fmaxf(mx1, fmaxf(sacc[nt][2], sacc[nt][3]));
        }
        mx0 = fmaxf(mx0, __shfl_xor_sync(0xffffffffu, mx0, 1));
        mx0 = fmaxf(mx0, __shfl_xor_sync(0xffffffffu, mx0, 2));
        mx1 = fmaxf(mx1, __shfl_xor_sync(0xffffffffu, mx1, 1));
        mx1 = fmaxf(mx1, __shfl_xor_sync(0xffffffffu, mx1, 2));
        float mn0 = fmaxf(m0, mx0), mn1 = fmaxf(m1, mx1);
        float c0 = __expf(m0 - mn0), c1 = __expf(m1 - mn1);
        float s0 = 0.f, s1 = 0.f;
#pragma unroll
        for (int nt = 0; nt < 8; nt++) {
            float p00 = __expf(sacc[nt][0] - mn0);
            float p01 = __expf(sacc[nt][1] - mn0);
            float p10 = __expf(sacc[nt][2] - mn1);
            float p11 = __expf(sacc[nt][3] - mn1);
            s0 += p00 + p01;
            s1 += p10 + p11;
            PsA[nt * 4 + t] = pack_h2(p00, p01);
            PsB[nt * 4 + t] = pack_h2(p10, p11);
        }
        s0 += __shfl_xor_sync(0xffffffffu, s0, 1);
        s0 += __shfl_xor_sync(0xffffffffu, s0, 2);
        s1 += __shfl_xor_sync(0xffffffffu, s1, 1);
        s1 += __shfl_xor_sync(0xffffffffu, s1, 2);
        l0 = l0 * c0 + s0; m0 = mn0;
        l1 = l1 * c1 + s1; m1 = mn1;
#pragma unroll
        for (int nt = 0; nt < 7; nt++) {
            oacc[nt][0] *= c0; oacc[nt][1] *= c0;
            oacc[nt][2] *= c1; oacc[nt][3] *= c1;
        }
        __syncwarp();   // P rows are warp-local

        // ---- O += P V : fp16 m16n8k16, 4 k-steps over 64 kv
#pragma unroll
        for (int ks = 0; ks < 4; ks++) {
            int kk = ks * 8;
            uint32_t af[4] = {PsA[kk + t], PsB[kk + t], PsA[kk + t + 4], PsB[kk + t + 4]};
#pragma unroll
            for (int nt = 0; nt < 7; nt++) {
                const uint32_t* Vr = Vt + (nt * 8 + g) * APW + kk;
                uint32_t bf[2] = {Vr[t], Vr[t + 4]};
                MMA_F16(oacc[nt], af, bf);
            }
        }
    }

    // epilogue: O / l as fp16 into padded [BT][KAP]
    float inv0 = 1.f / l0, inv1 = 1.f / l1;
    int r0 = q0 + wq + g;
    __half* o0 = outh + (size_t)(b * T + r0) * KAP + h * HD;
    __half* o1 = o0 + (size_t)8 * KAP;
#pragma unroll
    for (int nt = 0; nt < 7; nt++) {
        int c = nt * 8 + 2 * t;
        if (c < HD) {
            *(uint32_t*)(o0 + c) = pack_h2(oacc[nt][0] * inv0, oacc[nt][1] * inv0);
            *(uint32_t*)(o1 + c) = pack_h2(oacc[nt][2] * inv1, oacc[nt][3] * inv1);
        }
    }
    if (h == 0 && lane < 16) {
        int row = q0 + wq + (lane & 15);
        uint32_t* pz = (uint32_t*)(outh + (size_t)(b * T + row) * KAP + 500);
#pragma unroll
        for (int w = 0; w < 6; w++) pz[w] = 0u;
    }
}

// ---------------- launch ----------------------------------------------------
extern "C" void kernel_launch(void* const* d_in, const int* in_sizes, int n_in,
                              void* d_out, int out_size) {
    const int* ori            = (const int*)d_in[0];
    const float* x            = (const float*)d_in[1];
    const unsigned char* xm   = (const unsigned char*)d_in[2];
    const float *dwp[4], *dbp[4], *pwp[4], *pbp[4];
    for (int i = 0; i < 4; i++) {
        dwp[i] = (const float*)d_in[3 + 4 * i];
        dbp[i] = (const float*)d_in[4 + 4 * i];
        pwp[i] = (const float*)d_in[5 + 4 * i];
        pbp[i] = (const float*)d_in[6 + 4 * i];
    }
    const float* in_w  = (const float*)d_in[19];
    const float* in_b  = (const float*)d_in[20];
    const float* out_w = (const float*)d_in[21];
    const float* out_b = (const float*)d_in[22];
    const float* ffc_w = (const float*)d_in[23];
    const float* ffc_b = (const float*)d_in[24];
    float* outp = (float*)d_out;

    float *b0, *b1, *b2, *wtr;
    __half *bt, *b1t, *b2t, *wth, *qkvh;
    cudaGetSymbolAddress((void**)&b0,   g_b0);
    cudaGetSymbolAddress((void**)&b1,   g_b1);
    cudaGetSymbolAddress((void**)&b2,   g_b2);
    cudaGetSymbolAddress((void**)&bt,   g_bt);
    cudaGetSymbolAddress((void**)&b1t,  g_b1t);
    cudaGetSymbolAddress((void**)&b2t,  g_b2t);
    cudaGetSymbolAddress((void**)&qkvh, g_qkv);
    cudaGetSymbolAddress((void**)&wth,  g_wt);
    cudaGetSymbolAddress((void**)&wtr,  g_wtr);

    cudaFuncSetAttribute(attn_mma, cudaFuncAttributeMaxDynamicSharedMemorySize, ASM_BYTES);
    cudaFuncSetAttribute(gemm_pipe, cudaFuncAttributeMaxDynamicSharedMemorySize, GSM_BYTES);

    __half* wtp[4];
    for (int i = 0; i < 4; i++) wtp[i] = wth + i * PWS;
    __half* wt_in  = wth + 4 * PWS;
    __half* wt_out = wt_in + INS;
    __half* wt_ffc = wt_out + PWS;

    int ntot = 4 * PWS + INS + 2 * PWS + 4 * KW * D;
    cvt_all<<<(ntot + 255) / 256, 256>>>(pwp[0], pwp[1], pwp[2], pwp[3],
                                         in_w, out_w, ffc_w,
                                         dwp[0], dwp[1], dwp[2], dwp[3],
                                         wth, wtr);
    zero_qkv_pads<<<(BT * 30 + 255) / 256, 256>>>(qkvh);

    int eblocks  = (BTD + 255) / 256;
    int e4blocks = (BT * (KAP / 4) + 255) / 256;
    dim3 gg5((D + GBN - 1) / GBN, BT / GBM);    // (4, 128)
    dim3 ggq((D3 + GBN - 1) / GBN, BT / GBM);   // (12, 128)
    dim3 gga(T / AMQ, B * H);                   // (4, 320)

    posemb_kernel<<<eblocks, 256>>>(ori, x, b0);
    dwconv4_kernel<<<e4blocks, 256>>>(b0, wtr + 0 * KW * D, dbp[0], bt);
    gemm_pipe<<<gg5, 256, GSM_BYTES>>>(bt, wtp[0], pbp[0], b0, b1, nullptr, D, 0);
    dwconv4_kernel<<<e4blocks, 256>>>(b1, wtr + 1 * KW * D, dbp[1], bt);
    gemm_pipe<<<gg5, 256, GSM_BYTES>>>(bt, wtp[1], pbp[1], b1, b2, nullptr, D, 0);
    dwconv4_kernel<<<e4blocks, 256>>>(b2, wtr + 2 * KW * D, dbp[2], bt);
    gemm_pipe<<<gg5, 256, GSM_BYTES>>>(bt, wtp[2], pbp[2], b2, b0, nullptr, D, 0);
    dwconv4_kernel<<<e4blocks, 256>>>(b0, wtr + 3 * KW * D, dbp[3], bt);
    gemm_pipe<<<gg5, 256, GSM_BYTES>>>(bt, wtp[3], pbp[3], b0, b1, b1t, D, 1);
    gemm_pipe<<<ggq, 256, GSM_BYTES>>>(b1t, wt_in, in_b, nullptr, nullptr, qkvh, D3, 2);
    attn_mma<<<gga, 256, ASM_BYTES>>>(qkvh, xm, bt);
    gemm_pipe<<<gg5, 256, GSM_BYTES>>>(bt, wt_out, out_b, b1, b2, b2t, D, 1);
    gemm_pipe<<<gg5, 256, GSM_BYTES>>>(b2t, wt_ffc, ffc_b, b2, outp, nullptr, D, 0);
}

// round 12
// speedup vs baseline: 2.0555x; 1.0539x over previous
#include <cuda_runtime.h>
#include <cuda_fp16.h>
#include <cstdint>
#include <cstddef>

#define B 32
#define T 512
#define D 500
#define H 10
#define HD 50
#define D3 1500
#define BT (B*T)
#define BTD (BT*D)
#define KW 7
#define KAP 512      // padded activation K pitch (halves)
#define QKVP 1920    // padded qkv row pitch (halves): 3 * H * 64

// ---------------- scratch (static device arrays; no runtime allocation) ----
__device__ float  g_b0[BTD];
__device__ float  g_b1[BTD];
__device__ float  g_b2[BTD];
__device__ __half g_bt[(size_t)BT * KAP];
__device__ __half g_b1t[(size_t)BT * KAP];
__device__ __half g_b2t[(size_t)BT * KAP];
__device__ __half g_qkv[(size_t)BT * QKVP];
__device__ __half g_wt[2304000];             // padded fp16 weights
__device__ float  g_wtr[4 * KW * D];         // transposed dwconv weights [K][D]

#define PWS 256000   // 500*512
#define INS 768000   // 1500*512

// ---------------- helpers ---------------------------------------------------
__device__ __forceinline__ uint32_t smem_u32(const void* p) {
    uint32_t a;
    asm("{ .reg .u64 t; cvta.to.shared.u64 t, %1; cvt.u32.u64 %0, t; }" : "=r"(a) : "l"(p));
    return a;
}
__device__ __forceinline__ uint32_t pack_h2(float lo, float hi) {
    __half2 h = __floats2half2_rn(lo, hi);
    return *(uint32_t*)&h;
}

#define MMA_F16(c, a, b) \
    asm volatile("mma.sync.aligned.m16n8k16.row.col.f32.f16.f16.f32 " \
        "{%0,%1,%2,%3}, {%4,%5,%6,%7}, {%8,%9}, {%0,%1,%2,%3};" \
        : "+f"((c)[0]), "+f"((c)[1]), "+f"((c)[2]), "+f"((c)[3]) \
        : "r"((a)[0]), "r"((a)[1]), "r"((a)[2]), "r"((a)[3]), \
          "r"((b)[0]), "r"((b)[1]))

#define CP16(dst, src) \
    asm volatile("cp.async.ca.shared.global [%0], [%1], 16;" :: "r"(dst), "l"(src) : "memory")
#define CP16P(dst, src, p) \
    asm volatile("cp.async.ca.shared.global [%0], [%1], 16, %2;" :: "r"(dst), "l"(src), "r"(p) : "memory")
#define CPCOMMIT() asm volatile("cp.async.commit_group;" ::: "memory")
#define CPWAIT0()  asm volatile("cp.async.wait_group 0;" ::: "memory")
#define CPWAIT1()  asm volatile("cp.async.wait_group 1;" ::: "memory")

// -------- merged weight prep: fp16 pad-convert + dwconv transpose ----------
__global__ void cvt_all(const float* __restrict__ p0, const float* __restrict__ p1,
                        const float* __restrict__ p2, const float* __restrict__ p3,
                        const float* __restrict__ p4, const float* __restrict__ p5,
                        const float* __restrict__ p6,
                        const float* __restrict__ dw0, const float* __restrict__ dw1,
                        const float* __restrict__ dw2, const float* __restrict__ dw3,
                        __half* __restrict__ wh, float* __restrict__ otr) {
    const int NW = 4 * PWS + INS + 2 * PWS;   // 2,304,000
    int i = blockIdx.x * blockDim.x + threadIdx.x;
    if (i < NW) {
        const float* src;
        int idx;
        if      (i < PWS)          { src = p0; idx = i; }
        else if (i < 2 * PWS)      { src = p1; idx = i - PWS; }
        else if (i < 3 * PWS)      { src = p2; idx = i - 2 * PWS; }
        else if (i < 4 * PWS)      { src = p3; idx = i - 3 * PWS; }
        else if (i < 4 * PWS + INS){ src = p4; idx = i - 4 * PWS; }
        else if (i < 5 * PWS + INS){ src = p5; idx = i - 4 * PWS - INS; }
        else                       { src = p6; idx = i - 5 * PWS - INS; }
        int row = idx >> 9, col = idx & 511;
        float v = (col < 500) ? src[row * 500 + col] : 0.f;
        wh[i] = __float2half(v);
    } else {
        int i2 = i - NW;
        if (i2 < 4 * KW * D) {
            int arr = i2 / (KW * D);
            int rem = i2 - arr * (KW * D);
            int j = rem / D;
            int d = rem - j * D;
            const float* src = (arr == 0) ? dw0 : (arr == 1) ? dw1 : (arr == 2) ? dw2 : dw3;
            otr[arr * KW * D + j * D + d] = src[d * KW + j];
        }
    }
}

// ---------------- zero qkv head-slot pad lanes (50..63 of each 64) ---------
__global__ void zero_qkv_pads(__half* __restrict__ q) {
    int i = blockIdx.x * blockDim.x + threadIdx.x;
    if (i >= BT * 30) return;
    int row = i / 30, slot = i - row * 30;
    uint32_t* p = (uint32_t*)(q + (size_t)row * QKVP + slot * 64 + 50);
#pragma unroll
    for (int w = 0; w < 7; w++) p[w] = 0u;
}

// ---------------- positional embedding + add ------------------------------
__global__ void posemb_kernel(const int* __restrict__ ori,
                              const float* __restrict__ x,
                              float* __restrict__ out) {
    int idx = blockIdx.x * blockDim.x + threadIdx.x;
    if (idx >= BTD) return;
    int d  = idx % D;
    int bt = idx / D;
    int t  = bt % T;
    float pe = 0.f;
    if (ori[bt] != 0) {
        float pos = (float)(t + 1);
        int   i   = (d < 250) ? d : (d - 250);
        float ang = pos * expf((float)i * -0.036989318763f);
        pe = (d < 250) ? sinf(ang) : cosf(ang);
    }
    out[idx] = pe + x[idx];
}

// ------- depthwise conv1d (k=7, pad=3): 4 t-outputs per thread -------------
// Each thread: fixed (b, channel-quad d4), rows t0..t0+3. 10 row loads + 7
// weight loads replace 56. Accumulation order per output identical to before
// (s ascending => j ascending), so output is bit-identical.
__global__ void dwconv4_kernel(const float* __restrict__ x,
                               const float* __restrict__ wT,   // [KW][D]
                               const float* __restrict__ bias,
                               __half* __restrict__ y) {
    int idx = blockIdx.x * blockDim.x + threadIdx.x;
    if (idx >= (BT / 4) * 128) return;
    int d4  = idx & 127;
    int btq = idx >> 7;
    int b   = btq >> 7;          // T/4 = 128
    int t0  = (btq & 127) * 4;
    __half* yp = y + (size_t)(b * T + t0) * KAP + d4 * 4;
    if (d4 >= 125) {             // pad halves 500..511
#pragma unroll
        for (int r = 0; r < 4; r++)
            *(uint2*)(yp + (size_t)r * KAP) = make_uint2(0u, 0u);
        return;
    }
    int d = d4 * 4;
    float4 bv = *(const float4*)(bias + d);
    float acc[4][4];
#pragma unroll
    for (int r = 0; r < 4; r++) {
        acc[r][0] = bv.x; acc[r][1] = bv.y; acc[r][2] = bv.z; acc[r][3] = bv.w;
    }
    float4 w4[KW];
#pragma unroll
    for (int j = 0; j < KW; j++) w4[j] = *(const float4*)(wT + j * D + d);

    const float* xb = x + (size_t)(b * T) * D + d;
#pragma unroll
    for (int s = 0; s < 10; s++) {
        int tt = t0 + s - 3;
        if (tt >= 0 && tt < T) {
            float4 v = *(const float4*)(xb + (size_t)tt * D);
#pragma unroll
            for (int r = 0; r < 4; r++) {
                int j = s - r;
                if (j >= 0 && j < KW) {
                    acc[r][0] = fmaf(w4[j].x, v.x, acc[r][0]);
                    acc[r][1] = fmaf(w4[j].y, v.y, acc[r][1]);
                    acc[r][2] = fmaf(w4[j].z, v.z, acc[r][2]);
                    acc[r][3] = fmaf(w4[j].w, v.w, acc[r][3]);
                }
            }
        }
    }
#pragma unroll
    for (int r = 0; r < 4; r++)
        *(uint2*)(yp + (size_t)r * KAP) =
            make_uint2(pack_h2(acc[r][0], acc[r][1]), pack_h2(acc[r][2], acc[r][3]));
}

// =================== pipelined fp16 warp-mma GEMM ===========================
// modes: 0 = C fp32 (+res); 1 = + Ct fp16 padded copy; 2 = head-padded fp16 qkv
#define GBM 128
#define GBN 128
#define SPITCH 36
#define GBUF ((GBM + GBN) * SPITCH)
#define GSM_BYTES (2 * GBUF * 4)
#define KTC 8   // 512 / 64

__global__ __launch_bounds__(256, 2)
void gemm_pipe(const __half* __restrict__ A, const __half* __restrict__ W,
               const float* __restrict__ bias, const float* __restrict__ res,
               float* __restrict__ C, __half* __restrict__ Ct,
               int N, int mode) {
    extern __shared__ uint32_t sm[];

    int tid  = threadIdx.x;
    int lane = tid & 31, wid = tid >> 5;
    int g = lane >> 2, t = lane & 3;
    int m0 = blockIdx.y * GBM;
    int n0 = blockIdx.x * GBN;
    int wm = (wid & 1) * 64;
    int wn = (wid >> 1) * 32;

    int r0 = tid >> 3, kg = tid & 7;
    uint32_t smbase = smem_u32(sm);
    uint32_t adst[4], bdst[4];
    const __half* asrc[4];
    const __half* bsrc[4];
    uint32_t bok[4];
#pragma unroll
    for (int i = 0; i < 4; i++) {
        int r = r0 + i * 32;
        adst[i] = smbase + (uint32_t)(r * SPITCH + kg * 4) * 4;
        bdst[i] = adst[i] + GBM * SPITCH * 4;
        asrc[i] = A + (size_t)(m0 + r) * KAP + kg * 8;
        int n = n0 + r;
        bok[i] = (n < N) ? 16u : 0u;
        bsrc[i] = W + (size_t)((n < N) ? n : 0) * 512 + kg * 8;
    }

    float acc[4][4][4];
#pragma unroll
    for (int mt = 0; mt < 4; mt++)
#pragma unroll
        for (int nt = 0; nt < 4; nt++)
#pragma unroll
            for (int i = 0; i < 4; i++) acc[mt][nt][i] = 0.f;

    {
#pragma unroll
        for (int i = 0; i < 4; i++) {
            CP16(adst[i], asrc[i]);
            CP16P(bdst[i], bsrc[i], bok[i]);
        }
        CPCOMMIT();
    }

    for (int kt = 0; kt < KTC; kt++) {
        int buf = kt & 1;
        if (kt + 1 < KTC) {
            int koff = (kt + 1) * 64;
            uint32_t bo = (buf ^ 1) ? (uint32_t)GBUF * 4 : 0u;
#pragma unroll
            for (int i = 0; i < 4; i++) {
                CP16(adst[i] + bo, asrc[i] + koff);
                CP16P(bdst[i] + bo, bsrc[i] + koff, bok[i]);
            }
            CPCOMMIT();
            CPWAIT1();
        } else {
            CPWAIT0();
        }
        __syncthreads();

        const uint32_t* Ab = sm + (buf ? GBUF : 0);
        const uint32_t* Bb = Ab + GBM * SPITCH;
#pragma unroll
        for (int ks = 0; ks < 4; ks++) {
            int kk = ks * 8;
            uint32_t af[4][4], bf[4][2];
#pragma unroll
            for (int mt = 0; mt < 4; mt++) {
                const uint32_t* Ar = Ab + (wm + mt * 16 + g) * SPITCH + kk;
                af[mt][0] = Ar[t];
                af[mt][1] = Ar[8 * SPITCH + t];
                af[mt][2] = Ar[t + 4];
                af[mt][3] = Ar[8 * SPITCH + t + 4];
            }
#pragma unroll
            for (int nt = 0; nt < 4; nt++) {
                const uint32_t* Br = Bb + (wn + nt * 8 + g) * SPITCH + kk;
                bf[nt][0] = Br[t];
                bf[nt][1] = Br[t + 4];
            }
#pragma unroll
            for (int mt = 0; mt < 4; mt++)
#pragma unroll
                for (int nt = 0; nt < 4; nt++)
                    MMA_F16(acc[mt][nt], af[mt], bf[nt]);
        }
        __syncthreads();
    }

#pragma unroll
    for (int mt = 0; mt < 4; mt++) {
        int row0 = m0 + wm + mt * 16 + g;
#pragma unroll
        for (int nt = 0; nt < 4; nt++) {
            int col = n0 + wn + nt * 8 + 2 * t;
            if (col < N) {
                float2 bv = *(const float2*)(bias + col);
                float2 o0, o1;
                o0.x = acc[mt][nt][0] + bv.x;
                o0.y = acc[mt][nt][1] + bv.y;
                o1.x = acc[mt][nt][2] + bv.x;
                o1.y = acc[mt][nt][3] + bv.y;
                if (mode == 2) {
                    int which = col / 500;
                    int rem   = col - which * 500;
                    int hh    = rem / 50;
                    int dd    = rem - hh * 50;
                    size_t p0 = (size_t)row0 * QKVP + which * 640 + hh * 64 + dd;
                    size_t p1 = (size_t)(row0 + 8) * QKVP + which * 640 + hh * 64 + dd;
                    __half* Ch = (__half*)Ct;
                    *(uint32_t*)(Ch + p0) = pack_h2(o0.x, o0.y);
                    *(uint32_t*)(Ch + p1) = pack_h2(o1.x, o1.y);
                } else {
                    size_t i0 = (size_t)row0 * N + col;
                    size_t i1 = (size_t)(row0 + 8) * N + col;
                    if (res) {
                        float2 r0v = *(const float2*)(res + i0);
                        float2 r1v = *(const float2*)(res + i1);
                        o0.x += r0v.x; o0.y += r0v.y;
                        o1.x += r1v.x; o1.y += r1v.y;
                    }
                    *(float2*)(C + i0) = o0;
                    *(float2*)(C + i1) = o1;
                    if (mode == 1) {
                        size_t q0i = (size_t)row0 * KAP + col;
                        size_t q1i = (size_t)(row0 + 8) * KAP + col;
                        *(uint32_t*)(Ct + q0i) = pack_h2(o0.x, o0.y);
                        *(uint32_t*)(Ct + q1i) = pack_h2(o1.x, o1.y);
                    }
                }
            }
        }
    }
    if (mode == 1 && n0 == 0 && lane < 16) {
        int row = m0 + wm + (lane & 15);
#pragma unroll
        for (int rr = 0; rr < 4; rr++) {
            uint32_t* pz = (uint32_t*)(Ct + (size_t)(row + rr * 16) * KAP + 500);
#pragma unroll
            for (int w = 0; w < 6; w++) pz[w] = 0u;
        }
    }
}

// =================== fp16 warp-mma flash attention ==========================
#define AMQ 128
#define ANK 64
#define APW 36
#define ASM_BYTES (((AMQ + ANK + 56 + AMQ) * APW) * 4 + 64)

__global__ __launch_bounds__(256, 3)
void attn_mma(const __half* __restrict__ qkvh,
              const unsigned char* __restrict__ mask,
              __half* __restrict__ outh) {
    extern __shared__ uint32_t dsm[];
    uint32_t* Qs = dsm;                    // [128][36] words (64 halves + pad)
    uint32_t* Ks = Qs + AMQ * APW;         // [64][36]
    uint32_t* Vt = Ks + ANK * APW;         // [56][36]  (d, j) halves
    uint32_t* Ps = Vt + 56 * APW;          // [128][36]
    unsigned char* msk = (unsigned char*)(Ps + AMQ * APW);

    int tid  = threadIdx.x;
    int lane = tid & 31, wid = tid >> 5;
    int g = lane >> 2, t = lane & 3;
    int bh = blockIdx.y;
    int b  = bh / H, h = bh % H;
    int q0 = blockIdx.x * AMQ;
    const float scale = 0.14142135623730951f;

    for (int i = tid; i < 6 * 32; i += 256)
        Vt[(50 + i / 32) * APW + (i % 32)] = 0;

    {
        int r = tid >> 1, e = tid & 1;
        const __half* src = qkvh + (size_t)(b * T + q0 + r) * QKVP + h * 64;
        uint32_t dst = smem_u32(Qs + r * APW);
#pragma unroll
        for (int c = e; c < 8; c += 2) CP16(dst + 16 * c, src + 8 * c);
        CPCOMMIT();
    }

    int wq = wid * 16;
    const uint32_t* QA = Qs + (wq + g) * APW;
    const uint32_t* QB = Qs + (wq + g + 8) * APW;
    uint32_t* PsA = Ps + (wq + g) * APW;
    uint32_t* PsB = Ps + (wq + g + 8) * APW;

    float m0 = -1e30f, m1 = -1e30f, l0 = 0.f, l1 = 0.f;
    float oacc[7][4];
#pragma unroll
    for (int nt = 0; nt < 7; nt++)
#pragma unroll
        for (int i = 0; i < 4; i++) oacc[nt][i] = 0.f;

    for (int kt = 0; kt < T / ANK; kt++) {
        int k0 = kt * ANK;
        __syncthreads();

        {
            int j = tid >> 2, q = tid & 3;
            const __half* src = qkvh + (size_t)(b * T + k0 + j) * QKVP + 640 + h * 64;
            uint32_t dst = smem_u32(Ks + j * APW);
            CP16(dst + 16 * q,       src + 8 * q);
            CP16(dst + 16 * (q + 4), src + 8 * (q + 4));
            CPCOMMIT();
        }
        {
            int j = tid >> 2, q = tid & 3;
            const __half* src = qkvh + (size_t)(b * T + k0 + j) * QKVP + 1280 + h * 64;
#pragma unroll
            for (int p = q; p < 25; p += 4) {
                uint32_t v = *(const uint32_t*)(src + 2 * p);
                __half2 hv = *(__half2*)&v;
                ((__half*)(Vt + (2 * p) * APW))[j]     = hv.x;
                ((__half*)(Vt + (2 * p + 1) * APW))[j] = hv.y;
            }
        }
        if (tid < ANK) msk[tid] = mask[b * T + k0 + tid];
        CPWAIT0();
        __syncthreads();

        float sacc[8][4];
#pragma unroll
        for (int nt = 0; nt < 8; nt++)
#pragma unroll
            for (int i = 0; i < 4; i++) sacc[nt][i] = 0.f;
#pragma unroll
        for (int ks = 0; ks < 4; ks++) {
            int kk = ks * 8;
            uint32_t af[4] = {QA[kk + t], QB[kk + t], QA[kk + t + 4], QB[kk + t + 4]};
#pragma unroll
            for (int nt = 0; nt < 8; nt++) {
                const uint32_t* Kr = Ks + (nt * 8 + g) * APW + kk;
                uint32_t bf[2] = {Kr[t], Kr[t + 4]};
                MMA_F16(sacc[nt], af, bf);
            }
        }

        float mx0 = -1e30f, mx1 = -1e30f;
#pragma unroll
        for (int nt = 0; nt < 8; nt++) {
            sacc[nt][0] *= scale; sacc[nt][1] *= scale;
            sacc[nt][2] *= scale; sacc[nt][3] *= scale;
            int c = nt * 8 + 2 * t;
            if (msk[c])     { sacc[nt][0] = -1e30f; sacc[nt][2] = -1e30f; }
            if (msk[c + 1]) { sacc[nt][1] = -1e30f; sacc[nt][3] = -1e30f; }
            mx0 = fmaxf(mx0, fmaxf(sacc[nt][0], sacc[nt][1]));
            mx1 = fmaxf(mx1, fmaxf(sacc[nt][2], sacc[nt][3]));
        }
        mx0 = fmaxf(mx0, __shfl_xor_sync(0xffffffffu, mx0, 1));
        mx0 = fmaxf(mx0, __shfl_xor_sync(0xffffffffu, mx0, 2));
        mx1 = fmaxf(mx1, __shfl_xor_sync(0xffffffffu, mx1, 1));
        mx1 = fmaxf(mx1, __shfl_xor_sync(0xffffffffu, mx1, 2));
        float mn0 = fmaxf(m0, mx0), mn1 = fmaxf(m1, mx1);
        float c0 = __expf(m0 - mn0), c1 = __expf(m1 - mn1);
        float s0 = 0.f, s1 = 0.f;
#pragma unroll
        for (int nt = 0; nt < 8; nt++) {
            float p00 = __expf(sacc[nt][0] - mn0);
            float p01 = __expf(sacc[nt][1] - mn0);
            float p10 = __expf(sacc[nt][2] - mn1);
            float p11 = __expf(sacc[nt][3] - mn1);
            s0 += p00 + p01;
            s1 += p10 + p11;
            PsA[nt * 4 + t] = pack_h2(p00, p01);
            PsB[nt * 4 + t] = pack_h2(p10, p11);
        }
        s0 += __shfl_xor_sync(0xffffffffu, s0, 1);
        s0 += __shfl_xor_sync(0xffffffffu, s0, 2);
        s1 += __shfl_xor_sync(0xffffffffu, s1, 1);
        s1 += __shfl_xor_sync(0xffffffffu, s1, 2);
        l0 = l0 * c0 + s0; m0 = mn0;
        l1 = l1 * c1 + s1; m1 = mn1;
#pragma unroll
        for (int nt = 0; nt < 7; nt++) {
            oacc[nt][0] *= c0; oacc[nt][1] *= c0;
            oacc[nt][2] *= c1; oacc[nt][3] *= c1;
        }
        __syncwarp();

#pragma unroll
        for (int ks = 0; ks < 4; ks++) {
            int kk = ks * 8;
            uint32_t af[4] = {PsA[kk + t], PsB[kk + t], PsA[kk + t + 4], PsB[kk + t + 4]};
#pragma unroll
            for (int nt = 0; nt < 7; nt++) {
                const uint32_t* Vr = Vt + (nt * 8 + g) * APW + kk;
                uint32_t bf[2] = {Vr[t], Vr[t + 4]};
                MMA_F16(oacc[nt], af, bf);
            }
        }
    }

    float inv0 = 1.f / l0, inv1 = 1.f / l1;
    int r0 = q0 + wq + g;
    __half* o0 = outh + (size_t)(b * T + r0) * KAP + h * HD;
    __half* o1 = o0 + (size_t)8 * KAP;
#pragma unroll
    for (int nt = 0; nt < 7; nt++) {
        int c = nt * 8 + 2 * t;
        if (c < HD) {
            *(uint32_t*)(o0 + c) = pack_h2(oacc[nt][0] * inv0, oacc[nt][1] * inv0);
            *(uint32_t*)(o1 + c) = pack_h2(oacc[nt][2] * inv1, oacc[nt][3] * inv1);
        }
    }
    if (h == 0 && lane < 16) {
        int row = q0 + wq + (lane & 15);
        uint32_t* pz = (uint32_t*)(outh + (size_t)(b * T + row) * KAP + 500);
#pragma unroll
        for (int w = 0; w < 6; w++) pz[w] = 0u;
    }
}

// ---------------- launch ----------------------------------------------------
extern "C" void kernel_launch(void* const* d_in, const int* in_sizes, int n_in,
                              void* d_out, int out_size) {
    const int* ori            = (const int*)d_in[0];
    const float* x            = (const float*)d_in[1];
    const unsigned char* xm   = (const unsigned char*)d_in[2];
    const float *dwp[4], *dbp[4], *pwp[4], *pbp[4];
    for (int i = 0; i < 4; i++) {
        dwp[i] = (const float*)d_in[3 + 4 * i];
        dbp[i] = (const float*)d_in[4 + 4 * i];
        pwp[i] = (const float*)d_in[5 + 4 * i];
        pbp[i] = (const float*)d_in[6 + 4 * i];
    }
    const float* in_w  = (const float*)d_in[19];
    const float* in_b  = (const float*)d_in[20];
    const float* out_w = (const float*)d_in[21];
    const float* out_b = (const float*)d_in[22];
    const float* ffc_w = (const float*)d_in[23];
    const float* ffc_b = (const float*)d_in[24];
    float* outp = (float*)d_out;

    float *b0, *b1, *b2, *wtr;
    __half *bt, *b1t, *b2t, *wth, *qkvh;
    cudaGetSymbolAddress((void**)&b0,   g_b0);
    cudaGetSymbolAddress((void**)&b1,   g_b1);
    cudaGetSymbolAddress((void**)&b2,   g_b2);
    cudaGetSymbolAddress((void**)&bt,   g_bt);
    cudaGetSymbolAddress((void**)&b1t,  g_b1t);
    cudaGetSymbolAddress((void**)&b2t,  g_b2t);
    cudaGetSymbolAddress((void**)&qkvh, g_qkv);
    cudaGetSymbolAddress((void**)&wth,  g_wt);
    cudaGetSymbolAddress((void**)&wtr,  g_wtr);

    cudaFuncSetAttribute(attn_mma, cudaFuncAttributeMaxDynamicSharedMemorySize, ASM_BYTES);
    cudaFuncSetAttribute(gemm_pipe, cudaFuncAttributeMaxDynamicSharedMemorySize, GSM_BYTES);

    __half* wtp[4];
    for (int i = 0; i < 4; i++) wtp[i] = wth + i * PWS;
    __half* wt_in  = wth + 4 * PWS;
    __half* wt_out = wt_in + INS;
    __half* wt_ffc = wt_out + PWS;

    int ntot = 4 * PWS + INS + 2 * PWS + 4 * KW * D;
    cvt_all<<<(ntot + 255) / 256, 256>>>(pwp[0], pwp[1], pwp[2], pwp[3],
                                         in_w, out_w, ffc_w,
                                         dwp[0], dwp[1], dwp[2], dwp[3],
                                         wth, wtr);
    zero_qkv_pads<<<(BT * 30 + 255) / 256, 256>>>(qkvh);

    int eblocks  = (BTD + 255) / 256;
    int cblocks  = ((BT / 4) * 128 + 255) / 256;   // 2048
    dim3 gg5((D + GBN - 1) / GBN, BT / GBM);    // (4, 128)
    dim3 ggq((D3 + GBN - 1) / GBN, BT / GBM);   // (12, 128)
    dim3 gga(T / AMQ, B * H);                   // (4, 320)

    posemb_kernel<<<eblocks, 256>>>(ori, x, b0);
    dwconv4_kernel<<<cblocks, 256>>>(b0, wtr + 0 * KW * D, dbp[0], bt);
    gemm_pipe<<<gg5, 256, GSM_BYTES>>>(bt, wtp[0], pbp[0], b0, b1, nullptr, D, 0);
    dwconv4_kernel<<<cblocks, 256>>>(b1, wtr + 1 * KW * D, dbp[1], bt);
    gemm_pipe<<<gg5, 256, GSM_BYTES>>>(bt, wtp[1], pbp[1], b1, b2, nullptr, D, 0);
    dwconv4_kernel<<<cblocks, 256>>>(b2, wtr + 2 * KW * D, dbp[2], bt);
    gemm_pipe<<<gg5, 256, GSM_BYTES>>>(bt, wtp[2], pbp[2], b2, b0, nullptr, D, 0);
    dwconv4_kernel<<<cblocks, 256>>>(b0, wtr + 3 * KW * D, dbp[3], bt);
    gemm_pipe<<<gg5, 256, GSM_BYTES>>>(bt, wtp[3], pbp[3], b0, b1, b1t, D, 1);
    gemm_pipe<<<ggq, 256, GSM_BYTES>>>(b1t, wt_in, in_b, nullptr, nullptr, qkvh, D3, 2);
    attn_mma<<<gga, 256, ASM_BYTES>>>(qkvh, xm, bt);
    gemm_pipe<<<gg5, 256, GSM_BYTES>>>(bt, wt_out, out_b, b1, b2, b2t, D, 1);
    gemm_pipe<<<gg5, 256, GSM_BYTES>>>(b2t, wt_ffc, ffc_b, b2, outp, nullptr, D, 0);
}

// round 13
// speedup vs baseline: 2.1180x; 1.0304x over previous
#include <cuda_runtime.h>
#include <cuda_fp16.h>
#include <cstdint>
#include <cstddef>

#define B 32
#define T 512
#define D 500
#define H 10
#define HD 50
#define D3 1500
#define BT (B*T)
#define BTD (BT*D)
#define KW 7
#define KAP 512      // padded activation K pitch (halves)
#define QKVP 1920    // padded qkv row pitch (halves): 3 * H * 64

// ---------------- scratch (static device arrays; no runtime allocation) ----
__device__ float  g_b0[BTD];
__device__ float  g_b1[BTD];
__device__ float  g_b2[BTD];
__device__ __half g_bt[(size_t)BT * KAP];
__device__ __half g_b1t[(size_t)BT * KAP];
__device__ __half g_b2t[(size_t)BT * KAP];
__device__ __half g_qkv[(size_t)BT * QKVP];
__device__ __half g_wt[2304000];             // padded fp16 weights
__device__ float  g_wtr[4 * KW * D];         // transposed dwconv weights [K][D]
__device__ float  g_pe[T * D];               // positional embedding table

#define PWS 256000   // 500*512
#define INS 768000   // 1500*512

// ---------------- helpers ---------------------------------------------------
__device__ __forceinline__ uint32_t smem_u32(const void* p) {
    uint32_t a;
    asm("{ .reg .u64 t; cvta.to.shared.u64 t, %1; cvt.u32.u64 %0, t; }" : "=r"(a) : "l"(p));
    return a;
}
__device__ __forceinline__ uint32_t pack_h2(float lo, float hi) {
    __half2 h = __floats2half2_rn(lo, hi);
    return *(uint32_t*)&h;
}

#define MMA_F16(c, a, b) \
    asm volatile("mma.sync.aligned.m16n8k16.row.col.f32.f16.f16.f32 " \
        "{%0,%1,%2,%3}, {%4,%5,%6,%7}, {%8,%9}, {%0,%1,%2,%3};" \
        : "+f"((c)[0]), "+f"((c)[1]), "+f"((c)[2]), "+f"((c)[3]) \
        : "r"((a)[0]), "r"((a)[1]), "r"((a)[2]), "r"((a)[3]), \
          "r"((b)[0]), "r"((b)[1]))

#define CP16(dst, src) \
    asm volatile("cp.async.ca.shared.global [%0], [%1], 16;" :: "r"(dst), "l"(src) : "memory")
#define CP16P(dst, src, p) \
    asm volatile("cp.async.ca.shared.global [%0], [%1], 16, %2;" :: "r"(dst), "l"(src), "r"(p) : "memory")
#define CPCOMMIT() asm volatile("cp.async.commit_group;" ::: "memory")
#define CPWAIT0()  asm volatile("cp.async.wait_group 0;" ::: "memory")
#define CPWAIT1()  asm volatile("cp.async.wait_group 1;" ::: "memory")

// -------- merged weight prep: fp16 pad-convert + dwconv transpose ----------
__global__ void cvt_all(const float* __restrict__ p0, const float* __restrict__ p1,
                        const float* __restrict__ p2, const float* __restrict__ p3,
                        const float* __restrict__ p4, const float* __restrict__ p5,
                        const float* __restrict__ p6,
                        const float* __restrict__ dw0, const float* __restrict__ dw1,
                        const float* __restrict__ dw2, const float* __restrict__ dw3,
                        __half* __restrict__ wh, float* __restrict__ otr) {
    const int NW = 4 * PWS + INS + 2 * PWS;   // 2,304,000
    int i = blockIdx.x * blockDim.x + threadIdx.x;
    if (i < NW) {
        const float* src;
        int idx;
        if      (i < PWS)          { src = p0; idx = i; }
        else if (i < 2 * PWS)      { src = p1; idx = i - PWS; }
        else if (i < 3 * PWS)      { src = p2; idx = i - 2 * PWS; }
        else if (i < 4 * PWS)      { src = p3; idx = i - 3 * PWS; }
        else if (i < 4 * PWS + INS){ src = p4; idx = i - 4 * PWS; }
        else if (i < 5 * PWS + INS){ src = p5; idx = i - 4 * PWS - INS; }
        else                       { src = p6; idx = i - 5 * PWS - INS; }
        int row = idx >> 9, col = idx & 511;
        float v = (col < 500) ? src[row * 500 + col] : 0.f;
        wh[i] = __float2half(v);
    } else {
        int i2 = i - NW;
        if (i2 < 4 * KW * D) {
            int arr = i2 / (KW * D);
            int rem = i2 - arr * (KW * D);
            int j = rem / D;
            int d = rem - j * D;
            const float* src = (arr == 0) ? dw0 : (arr == 1) ? dw1 : (arr == 2) ? dw2 : dw3;
            otr[arr * KW * D + j * D + d] = src[d * KW + j];
        }
    }
}

// ---------------- zero qkv head-slot pad lanes (50..63 of each 64) ---------
__global__ void zero_qkv_pads(__half* __restrict__ q) {
    int i = blockIdx.x * blockDim.x + threadIdx.x;
    if (i >= BT * 30) return;
    int row = i / 30, slot = i - row * 30;
    uint32_t* p = (uint32_t*)(q + (size_t)row * QKVP + slot * 64 + 50);
#pragma unroll
    for (int w = 0; w < 7; w++) p[w] = 0u;
}

// ---------------- PE table + posemb ----------------------------------------
__global__ void pe_table_kernel(float* __restrict__ tab) {
    int idx = blockIdx.x * blockDim.x + threadIdx.x;
    if (idx >= T * D) return;
    int t = idx / D, d = idx - t * D;
    float pos = (float)(t + 1);
    int   i   = (d < 250) ? d : (d - 250);
    float ang = pos * expf((float)i * -0.036989318763f);
    tab[idx] = (d < 250) ? sinf(ang) : cosf(ang);
}

__global__ void posemb_kernel(const int* __restrict__ ori,
                              const float* __restrict__ x,
                              const float* __restrict__ tab,
                              float* __restrict__ out) {
    int idx = blockIdx.x * blockDim.x + threadIdx.x;
    if (idx >= BTD) return;
    int d  = idx % D;
    int bt = idx / D;
    int t  = bt % T;
    float pe = (ori[bt] != 0) ? tab[t * D + d] : 0.f;
    out[idx] = pe + x[idx];
}

// ------- depthwise conv1d (k=7, pad=3): 4 t-outputs per thread -------------
__global__ void dwconv4_kernel(const float* __restrict__ x,
                               const float* __restrict__ wT,   // [KW][D]
                               const float* __restrict__ bias,
                               __half* __restrict__ y) {
    int idx = blockIdx.x * blockDim.x + threadIdx.x;
    if (idx >= (BT / 4) * 128) return;
    int d4  = idx & 127;
    int btq = idx >> 7;
    int b   = btq >> 7;          // T/4 = 128
    int t0  = (btq & 127) * 4;
    __half* yp = y + (size_t)(b * T + t0) * KAP + d4 * 4;
    if (d4 >= 125) {
#pragma unroll
        for (int r = 0; r < 4; r++)
            *(uint2*)(yp + (size_t)r * KAP) = make_uint2(0u, 0u);
        return;
    }
    int d = d4 * 4;
    float4 bv = *(const float4*)(bias + d);
    float acc[4][4];
#pragma unroll
    for (int r = 0; r < 4; r++) {
        acc[r][0] = bv.x; acc[r][1] = bv.y; acc[r][2] = bv.z; acc[r][3] = bv.w;
    }
    float4 w4[KW];
#pragma unroll
    for (int j = 0; j < KW; j++) w4[j] = *(const float4*)(wT + j * D + d);

    const float* xb = x + (size_t)(b * T) * D + d;
#pragma unroll
    for (int s = 0; s < 10; s++) {
        int tt = t0 + s - 3;
        if (tt >= 0 && tt < T) {
            float4 v = *(const float4*)(xb + (size_t)tt * D);
#pragma unroll
            for (int r = 0; r < 4; r++) {
                int j = s - r;
                if (j >= 0 && j < KW) {
                    acc[r][0] = fmaf(w4[j].x, v.x, acc[r][0]);
                    acc[r][1] = fmaf(w4[j].y, v.y, acc[r][1]);
                    acc[r][2] = fmaf(w4[j].z, v.z, acc[r][2]);
                    acc[r][3] = fmaf(w4[j].w, v.w, acc[r][3]);
                }
            }
        }
    }
#pragma unroll
    for (int r = 0; r < 4; r++)
        *(uint2*)(yp + (size_t)r * KAP) =
            make_uint2(pack_h2(acc[r][0], acc[r][1]), pack_h2(acc[r][2], acc[r][3]));
}

// =================== pipelined fp16 warp-mma GEMM (unchanged) ===============
#define GBM 128
#define GBN 128
#define SPITCH 36
#define GBUF ((GBM + GBN) * SPITCH)
#define GSM_BYTES (2 * GBUF * 4)
#define KTC 8   // 512 / 64

__global__ __launch_bounds__(256, 2)
void gemm_pipe(const __half* __restrict__ A, const __half* __restrict__ W,
               const float* __restrict__ bias, const float* __restrict__ res,
               float* __restrict__ C, __half* __restrict__ Ct,
               int N, int mode) {
    extern __shared__ uint32_t sm[];

    int tid  = threadIdx.x;
    int lane = tid & 31, wid = tid >> 5;
    int g = lane >> 2, t = lane & 3;
    int m0 = blockIdx.y * GBM;
    int n0 = blockIdx.x * GBN;
    int wm = (wid & 1) * 64;
    int wn = (wid >> 1) * 32;

    int r0 = tid >> 3, kg = tid & 7;
    uint32_t smbase = smem_u32(sm);
    uint32_t adst[4], bdst[4];
    const __half* asrc[4];
    const __half* bsrc[4];
    uint32_t bok[4];
#pragma unroll
    for (int i = 0; i < 4; i++) {
        int r = r0 + i * 32;
        adst[i] = smbase + (uint32_t)(r * SPITCH + kg * 4) * 4;
        bdst[i] = adst[i] + GBM * SPITCH * 4;
        asrc[i] = A + (size_t)(m0 + r) * KAP + kg * 8;
        int n = n0 + r;
        bok[i] = (n < N) ? 16u : 0u;
        bsrc[i] = W + (size_t)((n < N) ? n : 0) * 512 + kg * 8;
    }

    float acc[4][4][4];
#pragma unroll
    for (int mt = 0; mt < 4; mt++)
#pragma unroll
        for (int nt = 0; nt < 4; nt++)
#pragma unroll
            for (int i = 0; i < 4; i++) acc[mt][nt][i] = 0.f;

    {
#pragma unroll
        for (int i = 0; i < 4; i++) {
            CP16(adst[i], asrc[i]);
            CP16P(bdst[i], bsrc[i], bok[i]);
        }
        CPCOMMIT();
    }

    for (int kt = 0; kt < KTC; kt++) {
        int buf = kt & 1;
        if (kt + 1 < KTC) {
            int koff = (kt + 1) * 64;
            uint32_t bo = (buf ^ 1) ? (uint32_t)GBUF * 4 : 0u;
#pragma unroll
            for (int i = 0; i < 4; i++) {
                CP16(adst[i] + bo, asrc[i] + koff);
                CP16P(bdst[i] + bo, bsrc[i] + koff, bok[i]);
            }
            CPCOMMIT();
            CPWAIT1();
        } else {
            CPWAIT0();
        }
        __syncthreads();

        const uint32_t* Ab = sm + (buf ? GBUF : 0);
        const uint32_t* Bb = Ab + GBM * SPITCH;
#pragma unroll
        for (int ks = 0; ks < 4; ks++) {
            int kk = ks * 8;
            uint32_t af[4][4], bf[4][2];
#pragma unroll
            for (int mt = 0; mt < 4; mt++) {
                const uint32_t* Ar = Ab + (wm + mt * 16 + g) * SPITCH + kk;
                af[mt][0] = Ar[t];
                af[mt][1] = Ar[8 * SPITCH + t];
                af[mt][2] = Ar[t + 4];
                af[mt][3] = Ar[8 * SPITCH + t + 4];
            }
#pragma unroll
            for (int nt = 0; nt < 4; nt++) {
                const uint32_t* Br = Bb + (wn + nt * 8 + g) * SPITCH + kk;
                bf[nt][0] = Br[t];
                bf[nt][1] = Br[t + 4];
            }
#pragma unroll
            for (int mt = 0; mt < 4; mt++)
#pragma unroll
                for (int nt = 0; nt < 4; nt++)
                    MMA_F16(acc[mt][nt], af[mt], bf[nt]);
        }
        __syncthreads();
    }

#pragma unroll
    for (int mt = 0; mt < 4; mt++) {
        int row0 = m0 + wm + mt * 16 + g;
#pragma unroll
        for (int nt = 0; nt < 4; nt++) {
            int col = n0 + wn + nt * 8 + 2 * t;
            if (col < N) {
                float2 bv = *(const float2*)(bias + col);
                float2 o0, o1;
                o0.x = acc[mt][nt][0] + bv.x;
                o0.y = acc[mt][nt][1] + bv.y;
                o1.x = acc[mt][nt][2] + bv.x;
                o1.y = acc[mt][nt][3] + bv.y;
                if (mode == 2) {
                    int which = col / 500;
                    int rem   = col - which * 500;
                    int hh    = rem / 50;
                    int dd    = rem - hh * 50;
                    size_t p0 = (size_t)row0 * QKVP + which * 640 + hh * 64 + dd;
                    size_t p1 = (size_t)(row0 + 8) * QKVP + which * 640 + hh * 64 + dd;
                    __half* Ch = (__half*)Ct;
                    *(uint32_t*)(Ch + p0) = pack_h2(o0.x, o0.y);
                    *(uint32_t*)(Ch + p1) = pack_h2(o1.x, o1.y);
                } else {
                    size_t i0 = (size_t)row0 * N + col;
                    size_t i1 = (size_t)(row0 + 8) * N + col;
                    if (res) {
                        float2 r0v = *(const float2*)(res + i0);
                        float2 r1v = *(const float2*)(res + i1);
                        o0.x += r0v.x; o0.y += r0v.y;
                        o1.x += r1v.x; o1.y += r1v.y;
                    }
                    *(float2*)(C + i0) = o0;
                    *(float2*)(C + i1) = o1;
                    if (mode == 1) {
                        size_t q0i = (size_t)row0 * KAP + col;
                        size_t q1i = (size_t)(row0 + 8) * KAP + col;
                        *(uint32_t*)(Ct + q0i) = pack_h2(o0.x, o0.y);
                        *(uint32_t*)(Ct + q1i) = pack_h2(o1.x, o1.y);
                    }
                }
            }
        }
    }
    if (mode == 1 && n0 == 0 && lane < 16) {
        int row = m0 + wm + (lane & 15);
#pragma unroll
        for (int rr = 0; rr < 4; rr++) {
            uint32_t* pz = (uint32_t*)(Ct + (size_t)(row + rr * 16) * KAP + 500);
#pragma unroll
            for (int w = 0; w < 6; w++) pz[w] = 0u;
        }
    }
}

// =================== fp16 warp-mma flash attention (K/V double-buffered) ====
#define AMQ 128
#define ANK 64
#define APW 36
#define ASM_BYTES (((AMQ + 2*ANK + 2*56 + AMQ) * APW) * 4 + 192)

__global__ __launch_bounds__(256, 3)
void attn_mma(const __half* __restrict__ qkvh,
              const unsigned char* __restrict__ mask,
              __half* __restrict__ outh) {
    extern __shared__ uint32_t dsm[];
    uint32_t* Qs  = dsm;                      // [128][36]
    uint32_t* Ks0 = Qs + AMQ * APW;           // [2][64][36]
    uint32_t* Vt0 = Ks0 + 2 * ANK * APW;      // [2][56][36]
    uint32_t* Ps  = Vt0 + 2 * 56 * APW;       // [128][36]
    unsigned char* msk = (unsigned char*)(Ps + AMQ * APW);  // [2][64]

    int tid  = threadIdx.x;
    int lane = tid & 31, wid = tid >> 5;
    int g = lane >> 2, t = lane & 3;
    int bh = blockIdx.y;
    int b  = bh / H, h = bh % H;
    int q0 = blockIdx.x * AMQ;
    const float scale = 0.14142135623730951f;

    // zero Vt pad rows 50..55 of BOTH buffers once
    for (int i = tid; i < 2 * 6 * 32; i += 256) {
        int bb = i / 192, rr = (i % 192) / 32, cc = i % 32;
        Vt0[bb * 56 * APW + (50 + rr) * APW + cc] = 0;
    }

    // stage Q
    {
        int r = tid >> 1, e = tid & 1;
        const __half* src = qkvh + (size_t)(b * T + q0 + r) * QKVP + h * 64;
        uint32_t dst = smem_u32(Qs + r * APW);
#pragma unroll
        for (int c = e; c < 8; c += 2) CP16(dst + 16 * c, src + 8 * c);
        CPCOMMIT();
    }

    int jst = tid >> 2, qst = tid & 3;   // staging coords (row, quarter)

    // stage K/V/msk for tile 0 into buffer 0
    {
        const __half* ksrc = qkvh + (size_t)(b * T + jst) * QKVP + 640 + h * 64;
        uint32_t dst = smem_u32(Ks0 + jst * APW);
        CP16(dst + 16 * qst,       ksrc + 8 * qst);
        CP16(dst + 16 * (qst + 4), ksrc + 8 * (qst + 4));
        CPCOMMIT();
        const __half* vsrc = qkvh + (size_t)(b * T + jst) * QKVP + 1280 + h * 64;
#pragma unroll
        for (int p = qst; p < 25; p += 4) {
            uint32_t v = *(const uint32_t*)(vsrc + 2 * p);
            __half2 hv = *(__half2*)&v;
            ((__half*)(Vt0 + (2 * p) * APW))[jst]     = hv.x;
            ((__half*)(Vt0 + (2 * p + 1) * APW))[jst] = hv.y;
        }
        if (tid < ANK) msk[tid] = mask[b * T + tid];
    }

    int wq = wid * 16;
    const uint32_t* QA = Qs + (wq + g) * APW;
    const uint32_t* QB = Qs + (wq + g + 8) * APW;
    uint32_t* PsA = Ps + (wq + g) * APW;
    uint32_t* PsB = Ps + (wq + g + 8) * APW;

    float m0 = -1e30f, m1 = -1e30f, l0 = 0.f, l1 = 0.f;
    float oacc[7][4];
#pragma unroll
    for (int nt = 0; nt < 7; nt++)
#pragma unroll
        for (int i = 0; i < 4; i++) oacc[nt][i] = 0.f;

    for (int kt = 0; kt < T / ANK; kt++) {
        int buf = kt & 1;
        CPWAIT0();        // K(kt) (and Q at kt=0) complete
        __syncthreads();  // V/msk STS visible; old buffer fully consumed

        // stage tile kt+1 into buf^1 (overlaps with compute below)
        if (kt + 1 < T / ANK) {
            int k1 = (kt + 1) * ANK;
            uint32_t* Ksn = Ks0 + (buf ^ 1) * ANK * APW;
            uint32_t* Vtn = Vt0 + (buf ^ 1) * 56 * APW;
            const __half* ksrc = qkvh + (size_t)(b * T + k1 + jst) * QKVP + 640 + h * 64;
            uint32_t dst = smem_u32(Ksn + jst * APW);
            CP16(dst + 16 * qst,       ksrc + 8 * qst);
            CP16(dst + 16 * (qst + 4), ksrc + 8 * (qst + 4));
            CPCOMMIT();
            const __half* vsrc = qkvh + (size_t)(b * T + k1 + jst) * QKVP + 1280 + h * 64;
#pragma unroll
            for (int p = qst; p < 25; p += 4) {
                uint32_t v = *(const uint32_t*)(vsrc + 2 * p);
                __half2 hv = *(__half2*)&v;
                ((__half*)(Vtn + (2 * p) * APW))[jst]     = hv.x;
                ((__half*)(Vtn + (2 * p + 1) * APW))[jst] = hv.y;
            }
            if (tid < ANK) msk[(buf ^ 1) * 64 + tid] = mask[b * T + k1 + tid];
        } else {
            CPCOMMIT();   // keep group accounting uniform
        }

        const uint32_t* Ksb = Ks0 + buf * ANK * APW;
        const uint32_t* Vtb = Vt0 + buf * 56 * APW;
        const unsigned char* mskb = msk + buf * 64;

        // ---- S = Q K^T
        float sacc[8][4];
#pragma unroll
        for (int nt = 0; nt < 8; nt++)
#pragma unroll
            for (int i = 0; i < 4; i++) sacc[nt][i] = 0.f;
#pragma unroll
        for (int ks = 0; ks < 4; ks++) {
            int kk = ks * 8;
            uint32_t af[4] = {QA[kk + t], QB[kk + t], QA[kk + t + 4], QB[kk + t + 4]};
#pragma unroll
            for (int nt = 0; nt < 8; nt++) {
                const uint32_t* Kr = Ksb + (nt * 8 + g) * APW + kk;
                uint32_t bf[2] = {Kr[t], Kr[t + 4]};
                MMA_F16(sacc[nt], af, bf);
            }
        }

        // ---- scale + mask + online softmax
        float mx0 = -1e30f, mx1 = -1e30f;
#pragma unroll
        for (int nt = 0; nt < 8; nt++) {
            sacc[nt][0] *= scale; sacc[nt][1] *= scale;
            sacc[nt][2] *= scale; sacc[nt][3] *= scale;
            int c = nt * 8 + 2 * t;
            if (mskb[c])     { sacc[nt][0] = -1e30f; sacc[nt][2] = -1e30f; }
            if (mskb[c + 1]) { sacc[nt][1] = -1e30f; sacc[nt][3] = -1e30f; }
            mx0 = fmaxf(mx0, fmaxf(sacc[nt][0], sacc[nt][1]));
            mx1 = fmaxf(mx1, fmaxf(sacc[nt][2], sacc[nt][3]));
        }
        mx0 = fmaxf(mx0, __shfl_xor_sync(0xffffffffu, mx0, 1));
        mx0 = fmaxf(mx0, __shfl_xor_sync(0xffffffffu, mx0, 2));
        mx1 = fmaxf(mx1, __shfl_xor_sync(0xffffffffu, mx1, 1));
        mx1 = fmaxf(mx1, __shfl_xor_sync(0xffffffffu, mx1, 2));
        float mn0 = fmaxf(m0, mx0), mn1 = fmaxf(m1, mx1);
        float c0 = __expf(m0 - mn0), c1 = __expf(m1 - mn1);
        float s0 = 0.f, s1 = 0.f;
#pragma unroll
        for (int nt = 0; nt < 8; nt++) {
            float p00 = __expf(sacc[nt][0] - mn0);
            float p01 = __expf(sacc[nt][1] - mn0);
            float p10 = __expf(sacc[nt][2] - mn1);
            float p11 = __expf(sacc[nt][3] - mn1);
            s0 += p00 + p01;
            s1 += p10 + p11;
            PsA[nt * 4 + t] = pack_h2(p00, p01);
            PsB[nt * 4 + t] = pack_h2(p10, p11);
        }
        s0 += __shfl_xor_sync(0xffffffffu, s0, 1);
        s0 += __shfl_xor_sync(0xffffffffu, s0, 2);
        s1 += __shfl_xor_sync(0xffffffffu, s1, 1);
        s1 += __shfl_xor_sync(0xffffffffu, s1, 2);
        l0 = l0 * c0 + s0; m0 = mn0;
        l1 = l1 * c1 + s1; m1 = mn1;
#pragma unroll
        for (int nt = 0; nt < 7; nt++) {
            oacc[nt][0] *= c0; oacc[nt][1] *= c0;
            oacc[nt][2] *= c1; oacc[nt][3] *= c1;
        }
        __syncwarp();

        // ---- O += P V
#pragma unroll
        for (int ks = 0; ks < 4; ks++) {
            int kk = ks * 8;
            uint32_t af[4] = {PsA[kk + t], PsB[kk + t], PsA[kk + t + 4], PsB[kk + t + 4]};
#pragma unroll
            for (int nt = 0; nt < 7; nt++) {
                const uint32_t* Vr = Vtb + (nt * 8 + g) * APW + kk;
                uint32_t bf[2] = {Vr[t], Vr[t + 4]};
                MMA_F16(oacc[nt], af, bf);
            }
        }
    }

    float inv0 = 1.f / l0, inv1 = 1.f / l1;
    int r0 = q0 + wq + g;
    __half* o0 = outh + (size_t)(b * T + r0) * KAP + h * HD;
    __half* o1 = o0 + (size_t)8 * KAP;
#pragma unroll
    for (int nt = 0; nt < 7; nt++) {
        int c = nt * 8 + 2 * t;
        if (c < HD) {
            *(uint32_t*)(o0 + c) = pack_h2(oacc[nt][0] * inv0, oacc[nt][1] * inv0);
            *(uint32_t*)(o1 + c) = pack_h2(oacc[nt][2] * inv1, oacc[nt][3] * inv1);
        }
    }
    if (h == 0 && lane < 16) {
        int row = q0 + wq + (lane & 15);
        uint32_t* pz = (uint32_t*)(outh + (size_t)(b * T + row) * KAP + 500);
#pragma unroll
        for (int w = 0; w < 6; w++) pz[w] = 0u;
    }
}

// ---------------- launch ----------------------------------------------------
extern "C" void kernel_launch(void* const* d_in, const int* in_sizes, int n_in,
                              void* d_out, int out_size) {
    const int* ori            = (const int*)d_in[0];
    const float* x            = (const float*)d_in[1];
    const unsigned char* xm   = (const unsigned char*)d_in[2];
    const float *dwp[4], *dbp[4], *pwp[4], *pbp[4];
    for (int i = 0; i < 4; i++) {
        dwp[i] = (const float*)d_in[3 + 4 * i];
        dbp[i] = (const float*)d_in[4 + 4 * i];
        pwp[i] = (const float*)d_in[5 + 4 * i];
        pbp[i] = (const float*)d_in[6 + 4 * i];
    }
    const float* in_w  = (const float*)d_in[19];
    const float* in_b  = (const float*)d_in[20];
    const float* out_w = (const float*)d_in[21];
    const float* out_b = (const float*)d_in[22];
    const float* ffc_w = (const float*)d_in[23];
    const float* ffc_b = (const float*)d_in[24];
    float* outp = (float*)d_out;

    float *b0, *b1, *b2, *wtr, *pet;
    __half *bt, *b1t, *b2t, *wth, *qkvh;
    cudaGetSymbolAddress((void**)&b0,   g_b0);
    cudaGetSymbolAddress((void**)&b1,   g_b1);
    cudaGetSymbolAddress((void**)&b2,   g_b2);
    cudaGetSymbolAddress((void**)&bt,   g_bt);
    cudaGetSymbolAddress((void**)&b1t,  g_b1t);
    cudaGetSymbolAddress((void**)&b2t,  g_b2t);
    cudaGetSymbolAddress((void**)&qkvh, g_qkv);
    cudaGetSymbolAddress((void**)&wth,  g_wt);
    cudaGetSymbolAddress((void**)&wtr,  g_wtr);
    cudaGetSymbolAddress((void**)&pet,  g_pe);

    cudaFuncSetAttribute(attn_mma, cudaFuncAttributeMaxDynamicSharedMemorySize, ASM_BYTES);
    cudaFuncSetAttribute(gemm_pipe, cudaFuncAttributeMaxDynamicSharedMemorySize, GSM_BYTES);

    __half* wtp[4];
    for (int i = 0; i < 4; i++) wtp[i] = wth + i * PWS;
    __half* wt_in  = wth + 4 * PWS;
    __half* wt_out = wt_in + INS;
    __half* wt_ffc = wt_out + PWS;

    int ntot = 4 * PWS + INS + 2 * PWS + 4 * KW * D;
    cvt_all<<<(ntot + 255) / 256, 256>>>(pwp[0], pwp[1], pwp[2], pwp[3],
                                         in_w, out_w, ffc_w,
                                         dwp[0], dwp[1], dwp[2], dwp[3],
                                         wth, wtr);
    zero_qkv_pads<<<(BT * 30 + 255) / 256, 256>>>(qkvh);
    pe_table_kernel<<<(T * D + 255) / 256, 256>>>(pet);

    int eblocks  = (BTD + 255) / 256;
    int cblocks  = ((BT / 4) * 128 + 255) / 256;   // 2048
    dim3 gg5((D + GBN - 1) / GBN, BT / GBM);    // (4, 128)
    dim3 ggq((D3 + GBN - 1) / GBN, BT / GBM);   // (12, 128)
    dim3 gga(T / AMQ, B * H);                   // (4, 320)

    posemb_kernel<<<eblocks, 256>>>(ori, x, pet, b0);
    dwconv4_kernel<<<cblocks, 256>>>(b0, wtr + 0 * KW * D, dbp[0], bt);
    gemm_pipe<<<gg5, 256, GSM_BYTES>>>(bt, wtp[0], pbp[0], b0, b1, nullptr, D, 0);
    dwconv4_kernel<<<cblocks, 256>>>(b1, wtr + 1 * KW * D, dbp[1], bt);
    gemm_pipe<<<gg5, 256, GSM_BYTES>>>(bt, wtp[1], pbp[1], b1, b2, nullptr, D, 0);
    dwconv4_kernel<<<cblocks, 256>>>(b2, wtr + 2 * KW * D, dbp[2], bt);
    gemm_pipe<<<gg5, 256, GSM_BYTES>>>(bt, wtp[2], pbp[2], b2, b0, nullptr, D, 0);
    dwconv4_kernel<<<cblocks, 256>>>(b0, wtr + 3 * KW * D, dbp[3], bt);
    gemm_pipe<<<gg5, 256, GSM_BYTES>>>(bt, wtp[3], pbp[3], b0, b1, b1t, D, 1);
    gemm_pipe<<<ggq, 256, GSM_BYTES>>>(b1t, wt_in, in_b, nullptr, nullptr, qkvh, D3, 2);
    attn_mma<<<gga, 256, ASM_BYTES>>>(qkvh, xm, bt);
    gemm_pipe<<<gg5, 256, GSM_BYTES>>>(bt, wt_out, out_b, b1, b2, b2t, D, 1);
    gemm_pipe<<<gg5, 256, GSM_BYTES>>>(b2t, wt_ffc, ffc_b, b2, outp, nullptr, D, 0);
}

// round 14
// speedup vs baseline: 2.1645x; 1.0219x over previous
#include <cuda_runtime.h>
#include <cuda_fp16.h>
#include <cstdint>
#include <cstddef>

#define B 32
#define T 512
#define D 500
#define H 10
#define HD 50
#define D3 1500
#define BT (B*T)
#define BTD (BT*D)
#define KW 7
#define KAP 512      // padded activation K pitch (halves)
#define QKVP 1920    // padded qkv row pitch (halves): 3 * H * 64

// ---------------- scratch (static device arrays; no runtime allocation) ----
__device__ float  g_b0[BTD];
__device__ float  g_b1[BTD];
__device__ float  g_b2[BTD];
__device__ __half g_bt[(size_t)BT * KAP];
__device__ __half g_b1t[(size_t)BT * KAP];
__device__ __half g_b2t[(size_t)BT * KAP];
__device__ __half g_qkv[(size_t)BT * QKVP];
__device__ __half g_wt[2304000];             // padded fp16 weights
__device__ float  g_wtr[4 * KW * D];         // transposed dwconv weights [K][D]
__device__ float  g_pe[T * D];               // positional embedding table

#define PWS 256000   // 500*512
#define INS 768000   // 1500*512
#define NW  (4 * PWS + INS + 2 * PWS)        // 2,304,000 weight halves
#define NTR (4 * KW * D)                     // 14,000 transposed dw weights
#define NPE (T * D)                          // 256,000 PE entries
#define NQZ (BT * 30)                        // 491,520 qkv pad zero jobs

// ---------------- helpers ---------------------------------------------------
__device__ __forceinline__ uint32_t smem_u32(const void* p) {
    uint32_t a;
    asm("{ .reg .u64 t; cvta.to.shared.u64 t, %1; cvt.u32.u64 %0, t; }" : "=r"(a) : "l"(p));
    return a;
}
__device__ __forceinline__ uint32_t pack_h2(float lo, float hi) {
    __half2 h = __floats2half2_rn(lo, hi);
    return *(uint32_t*)&h;
}

#define MMA_F16(c, a, b) \
    asm volatile("mma.sync.aligned.m16n8k16.row.col.f32.f16.f16.f32 " \
        "{%0,%1,%2,%3}, {%4,%5,%6,%7}, {%8,%9}, {%0,%1,%2,%3};" \
        : "+f"((c)[0]), "+f"((c)[1]), "+f"((c)[2]), "+f"((c)[3]) \
        : "r"((a)[0]), "r"((a)[1]), "r"((a)[2]), "r"((a)[3]), \
          "r"((b)[0]), "r"((b)[1]))

#define CP16(dst, src) \
    asm volatile("cp.async.ca.shared.global [%0], [%1], 16;" :: "r"(dst), "l"(src) : "memory")
#define CP16P(dst, src, p) \
    asm volatile("cp.async.ca.shared.global [%0], [%1], 16, %2;" :: "r"(dst), "l"(src), "r"(p) : "memory")
#define CPCOMMIT() asm volatile("cp.async.commit_group;" ::: "memory")
#define CPWAIT0()  asm volatile("cp.async.wait_group 0;" ::: "memory")
#define CPWAIT1()  asm volatile("cp.async.wait_group 1;" ::: "memory")

// -------- merged prep: weights fp16 pad-convert + dwconv transpose +
//          PE table + qkv pad zero -------------------------------------------
__global__ void prep_all(const float* __restrict__ p0, const float* __restrict__ p1,
                         const float* __restrict__ p2, const float* __restrict__ p3,
                         const float* __restrict__ p4, const float* __restrict__ p5,
                         const float* __restrict__ p6,
                         const float* __restrict__ dw0, const float* __restrict__ dw1,
                         const float* __restrict__ dw2, const float* __restrict__ dw3,
                         __half* __restrict__ wh, float* __restrict__ otr,
                         float* __restrict__ pe, __half* __restrict__ qkv) {
    int i = blockIdx.x * blockDim.x + threadIdx.x;
    if (i < NW) {
        const float* src;
        int idx;
        if      (i < PWS)          { src = p0; idx = i; }
        else if (i < 2 * PWS)      { src = p1; idx = i - PWS; }
        else if (i < 3 * PWS)      { src = p2; idx = i - 2 * PWS; }
        else if (i < 4 * PWS)      { src = p3; idx = i - 3 * PWS; }
        else if (i < 4 * PWS + INS){ src = p4; idx = i - 4 * PWS; }
        else if (i < 5 * PWS + INS){ src = p5; idx = i - 4 * PWS - INS; }
        else                       { src = p6; idx = i - 5 * PWS - INS; }
        int row = idx >> 9, col = idx & 511;
        float v = (col < 500) ? src[row * 500 + col] : 0.f;
        wh[i] = __float2half(v);
        return;
    }
    int i2 = i - NW;
    if (i2 < NTR) {
        int arr = i2 / (KW * D);
        int rem = i2 - arr * (KW * D);
        int j = rem / D;
        int d = rem - j * D;
        const float* src = (arr == 0) ? dw0 : (arr == 1) ? dw1 : (arr == 2) ? dw2 : dw3;
        otr[arr * KW * D + j * D + d] = src[d * KW + j];
        return;
    }
    int i3 = i2 - NTR;
    if (i3 < NPE) {
        int t = i3 / D, d = i3 - t * D;
        float pos = (float)(t + 1);
        int   k   = (d < 250) ? d : (d - 250);
        float ang = pos * expf((float)k * -0.036989318763f);
        pe[i3] = (d < 250) ? sinf(ang) : cosf(ang);
        return;
    }
    int i4 = i3 - NPE;
    if (i4 < NQZ) {
        int row = i4 / 30, slot = i4 - row * 30;
        uint32_t* p = (uint32_t*)(qkv + (size_t)row * QKVP + slot * 64 + 50);
#pragma unroll
        for (int w = 0; w < 7; w++) p[w] = 0u;
    }
}

// ---------------- posemb (float4) -------------------------------------------
__global__ void posemb_kernel(const int* __restrict__ ori,
                              const float* __restrict__ x,
                              const float* __restrict__ tab,
                              float* __restrict__ out) {
    int idx = blockIdx.x * blockDim.x + threadIdx.x;
    if (idx >= BT * 125) return;
    int d4 = idx % 125;
    int bt = idx / 125;
    int t  = bt % T;
    int d  = d4 * 4;
    size_t off = (size_t)bt * D + d;
    float4 xv = *(const float4*)(x + off);
    if (ori[bt] != 0) {
        float4 pv = *(const float4*)(tab + t * D + d);
        xv.x += pv.x; xv.y += pv.y; xv.z += pv.z; xv.w += pv.w;
    }
    *(float4*)(&g_b0[0] + off) = xv;
}

// ------- depthwise conv1d (k=7, pad=3): 4 t-outputs per thread -------------
__global__ void dwconv4_kernel(const float* __restrict__ x,
                               const float* __restrict__ wT,   // [KW][D]
                               const float* __restrict__ bias,
                               __half* __restrict__ y) {
    int idx = blockIdx.x * blockDim.x + threadIdx.x;
    if (idx >= (BT / 4) * 128) return;
    int d4  = idx & 127;
    int btq = idx >> 7;
    int b   = btq >> 7;          // T/4 = 128
    int t0  = (btq & 127) * 4;
    __half* yp = y + (size_t)(b * T + t0) * KAP + d4 * 4;
    if (d4 >= 125) {
#pragma unroll
        for (int r = 0; r < 4; r++)
            *(uint2*)(yp + (size_t)r * KAP) = make_uint2(0u, 0u);
        return;
    }
    int d = d4 * 4;
    float4 bv = *(const float4*)(bias + d);
    float acc[4][4];
#pragma unroll
    for (int r = 0; r < 4; r++) {
        acc[r][0] = bv.x; acc[r][1] = bv.y; acc[r][2] = bv.z; acc[r][3] = bv.w;
    }
    float4 w4[KW];
#pragma unroll
    for (int j = 0; j < KW; j++) w4[j] = *(const float4*)(wT + j * D + d);

    const float* xb = x + (size_t)(b * T) * D + d;
#pragma unroll
    for (int s = 0; s < 10; s++) {
        int tt = t0 + s - 3;
        if (tt >= 0 && tt < T) {
            float4 v = *(const float4*)(xb + (size_t)tt * D);
#pragma unroll
            for (int r = 0; r < 4; r++) {
                int j = s - r;
                if (j >= 0 && j < KW) {
                    acc[r][0] = fmaf(w4[j].x, v.x, acc[r][0]);
                    acc[r][1] = fmaf(w4[j].y, v.y, acc[r][1]);
                    acc[r][2] = fmaf(w4[j].z, v.z, acc[r][2]);
                    acc[r][3] = fmaf(w4[j].w, v.w, acc[r][3]);
                }
            }
        }
    }
#pragma unroll
    for (int r = 0; r < 4; r++)
        *(uint2*)(yp + (size_t)r * KAP) =
            make_uint2(pack_h2(acc[r][0], acc[r][1]), pack_h2(acc[r][2], acc[r][3]));
}

// =================== pipelined fp16 warp-mma GEMM (unchanged) ===============
#define GBM 128
#define GBN 128
#define SPITCH 36
#define GBUF ((GBM + GBN) * SPITCH)
#define GSM_BYTES (2 * GBUF * 4)
#define KTC 8   // 512 / 64

__global__ __launch_bounds__(256, 2)
void gemm_pipe(const __half* __restrict__ A, const __half* __restrict__ W,
               const float* __restrict__ bias, const float* __restrict__ res,
               float* __restrict__ C, __half* __restrict__ Ct,
               int N, int mode) {
    extern __shared__ uint32_t sm[];

    int tid  = threadIdx.x;
    int lane = tid & 31, wid = tid >> 5;
    int g = lane >> 2, t = lane & 3;
    int m0 = blockIdx.y * GBM;
    int n0 = blockIdx.x * GBN;
    int wm = (wid & 1) * 64;
    int wn = (wid >> 1) * 32;

    int r0 = tid >> 3, kg = tid & 7;
    uint32_t smbase = smem_u32(sm);
    uint32_t adst[4], bdst[4];
    const __half* asrc[4];
    const __half* bsrc[4];
    uint32_t bok[4];
#pragma unroll
    for (int i = 0; i < 4; i++) {
        int r = r0 + i * 32;
        adst[i] = smbase + (uint32_t)(r * SPITCH + kg * 4) * 4;
        bdst[i] = adst[i] + GBM * SPITCH * 4;
        asrc[i] = A + (size_t)(m0 + r) * KAP + kg * 8;
        int n = n0 + r;
        bok[i] = (n < N) ? 16u : 0u;
        bsrc[i] = W + (size_t)((n < N) ? n : 0) * 512 + kg * 8;
    }

    float acc[4][4][4];
#pragma unroll
    for (int mt = 0; mt < 4; mt++)
#pragma unroll
        for (int nt = 0; nt < 4; nt++)
#pragma unroll
            for (int i = 0; i < 4; i++) acc[mt][nt][i] = 0.f;

    {
#pragma unroll
        for (int i = 0; i < 4; i++) {
            CP16(adst[i], asrc[i]);
            CP16P(bdst[i], bsrc[i], bok[i]);
        }
        CPCOMMIT();
    }

    for (int kt = 0; kt < KTC; kt++) {
        int buf = kt & 1;
        if (kt + 1 < KTC) {
            int koff = (kt + 1) * 64;
            uint32_t bo = (buf ^ 1) ? (uint32_t)GBUF * 4 : 0u;
#pragma unroll
            for (int i = 0; i < 4; i++) {
                CP16(adst[i] + bo, asrc[i] + koff);
                CP16P(bdst[i] + bo, bsrc[i] + koff, bok[i]);
            }
            CPCOMMIT();
            CPWAIT1();
        } else {
            CPWAIT0();
        }
        __syncthreads();

        const uint32_t* Ab = sm + (buf ? GBUF : 0);
        const uint32_t* Bb = Ab + GBM * SPITCH;
#pragma unroll
        for (int ks = 0; ks < 4; ks++) {
            int kk = ks * 8;
            uint32_t af[4][4], bf[4][2];
#pragma unroll
            for (int mt = 0; mt < 4; mt++) {
                const uint32_t* Ar = Ab + (wm + mt * 16 + g) * SPITCH + kk;
                af[mt][0] = Ar[t];
                af[mt][1] = Ar[8 * SPITCH + t];
                af[mt][2] = Ar[t + 4];
                af[mt][3] = Ar[8 * SPITCH + t + 4];
            }
#pragma unroll
            for (int nt = 0; nt < 4; nt++) {
                const uint32_t* Br = Bb + (wn + nt * 8 + g) * SPITCH + kk;
                bf[nt][0] = Br[t];
                bf[nt][1] = Br[t + 4];
            }
#pragma unroll
            for (int mt = 0; mt < 4; mt++)
#pragma unroll
                for (int nt = 0; nt < 4; nt++)
                    MMA_F16(acc[mt][nt], af[mt], bf[nt]);
        }
        __syncthreads();
    }

#pragma unroll
    for (int mt = 0; mt < 4; mt++) {
        int row0 = m0 + wm + mt * 16 + g;
#pragma unroll
        for (int nt = 0; nt < 4; nt++) {
            int col = n0 + wn + nt * 8 + 2 * t;
            if (col < N) {
                float2 bv = *(const float2*)(bias + col);
                float2 o0, o1;
                o0.x = acc[mt][nt][0] + bv.x;
                o0.y = acc[mt][nt][1] + bv.y;
                o1.x = acc[mt][nt][2] + bv.x;
                o1.y = acc[mt][nt][3] + bv.y;
                if (mode == 2) {
                    int which = col / 500;
                    int rem   = col - which * 500;
                    int hh    = rem / 50;
                    int dd    = rem - hh * 50;
                    size_t p0 = (size_t)row0 * QKVP + which * 640 + hh * 64 + dd;
                    size_t p1 = (size_t)(row0 + 8) * QKVP + which * 640 + hh * 64 + dd;
                    __half* Ch = (__half*)Ct;
                    *(uint32_t*)(Ch + p0) = pack_h2(o0.x, o0.y);
                    *(uint32_t*)(Ch + p1) = pack_h2(o1.x, o1.y);
                } else {
                    size_t i0 = (size_t)row0 * N + col;
                    size_t i1 = (size_t)(row0 + 8) * N + col;
                    if (res) {
                        float2 r0v = *(const float2*)(res + i0);
                        float2 r1v = *(const float2*)(res + i1);
                        o0.x += r0v.x; o0.y += r0v.y;
                        o1.x += r1v.x; o1.y += r1v.y;
                    }
                    *(float2*)(C + i0) = o0;
                    *(float2*)(C + i1) = o1;
                    if (mode == 1) {
                        size_t q0i = (size_t)row0 * KAP + col;
                        size_t q1i = (size_t)(row0 + 8) * KAP + col;
                        *(uint32_t*)(Ct + q0i) = pack_h2(o0.x, o0.y);
                        *(uint32_t*)(Ct + q1i) = pack_h2(o1.x, o1.y);
                    }
                }
            }
        }
    }
    if (mode == 1 && n0 == 0 && lane < 16) {
        int row = m0 + wm + (lane & 15);
#pragma unroll
        for (int rr = 0; rr < 4; rr++) {
            uint32_t* pz = (uint32_t*)(Ct + (size_t)(row + rr * 16) * KAP + 500);
#pragma unroll
            for (int w = 0; w < 6; w++) pz[w] = 0u;
        }
    }
}

// =================== fp16 warp-mma flash attention (K/V double-buffered) ====
#define AMQ 128
#define ANK 64
#define APW 36
#define ASM_BYTES (((AMQ + 2*ANK + 2*56 + AMQ) * APW) * 4 + 192)

__global__ __launch_bounds__(256, 3)
void attn_mma(const __half* __restrict__ qkvh,
              const unsigned char* __restrict__ mask,
              __half* __restrict__ outh) {
    extern __shared__ uint32_t dsm[];
    uint32_t* Qs  = dsm;                      // [128][36]
    uint32_t* Ks0 = Qs + AMQ * APW;           // [2][64][36]
    uint32_t* Vt0 = Ks0 + 2 * ANK * APW;      // [2][56][36]
    uint32_t* Ps  = Vt0 + 2 * 56 * APW;       // [128][36]
    unsigned char* msk = (unsigned char*)(Ps + AMQ * APW);  // [2][64]

    int tid  = threadIdx.x;
    int lane = tid & 31, wid = tid >> 5;
    int g = lane >> 2, t = lane & 3;
    int bh = blockIdx.y;
    int b  = bh / H, h = bh % H;
    int q0 = blockIdx.x * AMQ;
    const float scale = 0.14142135623730951f;

    for (int i = tid; i < 2 * 6 * 32; i += 256) {
        int bb = i / 192, rr = (i % 192) / 32, cc = i % 32;
        Vt0[bb * 56 * APW + (50 + rr) * APW + cc] = 0;
    }

    {
        int r = tid >> 1, e = tid & 1;
        const __half* src = qkvh + (size_t)(b * T + q0 + r) * QKVP + h * 64;
        uint32_t dst = smem_u32(Qs + r * APW);
#pragma unroll
        for (int c = e; c < 8; c += 2) CP16(dst + 16 * c, src + 8 * c);
        CPCOMMIT();
    }

    int jst = tid >> 2, qst = tid & 3;

    {
        const __half* ksrc = qkvh + (size_t)(b * T + jst) * QKVP + 640 + h * 64;
        uint32_t dst = smem_u32(Ks0 + jst * APW);
        CP16(dst + 16 * qst,       ksrc + 8 * qst);
        CP16(dst + 16 * (qst + 4), ksrc + 8 * (qst + 4));
        CPCOMMIT();
        const __half* vsrc = qkvh + (size_t)(b * T + jst) * QKVP + 1280 + h * 64;
#pragma unroll
        for (int p = qst; p < 25; p += 4) {
            uint32_t v = *(const uint32_t*)(vsrc + 2 * p);
            __half2 hv = *(__half2*)&v;
            ((__half*)(Vt0 + (2 * p) * APW))[jst]     = hv.x;
            ((__half*)(Vt0 + (2 * p + 1) * APW))[jst] = hv.y;
        }
        if (tid < ANK) msk[tid] = mask[b * T + tid];
    }

    int wq = wid * 16;
    const uint32_t* QA = Qs + (wq + g) * APW;
    const uint32_t* QB = Qs + (wq + g + 8) * APW;
    uint32_t* PsA = Ps + (wq + g) * APW;
    uint32_t* PsB = Ps + (wq + g + 8) * APW;

    float m0 = -1e30f, m1 = -1e30f, l0 = 0.f, l1 = 0.f;
    float oacc[7][4];
#pragma unroll
    for (int nt = 0; nt < 7; nt++)
#pragma unroll
        for (int i = 0; i < 4; i++) oacc[nt][i] = 0.f;

    for (int kt = 0; kt < T / ANK; kt++) {
        int buf = kt & 1;
        CPWAIT0();
        __syncthreads();

        if (kt + 1 < T / ANK) {
            int k1 = (kt + 1) * ANK;
            uint32_t* Ksn = Ks0 + (buf ^ 1) * ANK * APW;
            uint32_t* Vtn = Vt0 + (buf ^ 1) * 56 * APW;
            const __half* ksrc = qkvh + (size_t)(b * T + k1 + jst) * QKVP + 640 + h * 64;
            uint32_t dst = smem_u32(Ksn + jst * APW);
            CP16(dst + 16 * qst,       ksrc + 8 * qst);
            CP16(dst + 16 * (qst + 4), ksrc + 8 * (qst + 4));
            CPCOMMIT();
            const __half* vsrc = qkvh + (size_t)(b * T + k1 + jst) * QKVP + 1280 + h * 64;
#pragma unroll
            for (int p = qst; p < 25; p += 4) {
                uint32_t v = *(const uint32_t*)(vsrc + 2 * p);
                __half2 hv = *(__half2*)&v;
                ((__half*)(Vtn + (2 * p) * APW))[jst]     = hv.x;
                ((__half*)(Vtn + (2 * p + 1) * APW))[jst] = hv.y;
            }
            if (tid < ANK) msk[(buf ^ 1) * 64 + tid] = mask[b * T + k1 + tid];
        } else {
            CPCOMMIT();
        }

        const uint32_t* Ksb = Ks0 + buf * ANK * APW;
        const uint32_t* Vtb = Vt0 + buf * 56 * APW;
        const unsigned char* mskb = msk + buf * 64;

        float sacc[8][4];
#pragma unroll
        for (int nt = 0; nt < 8; nt++)
#pragma unroll
            for (int i = 0; i < 4; i++) sacc[nt][i] = 0.f;
#pragma unroll
        for (int ks = 0; ks < 4; ks++) {
            int kk = ks * 8;
            uint32_t af[4] = {QA[kk + t], QB[kk + t], QA[kk + t + 4], QB[kk + t + 4]};
#pragma unroll
            for (int nt = 0; nt < 8; nt++) {
                const uint32_t* Kr = Ksb + (nt * 8 + g) * APW + kk;
                uint32_t bf[2] = {Kr[t], Kr[t + 4]};
                MMA_F16(sacc[nt], af, bf);
            }
        }

        float mx0 = -1e30f, mx1 = -1e30f;
#pragma unroll
        for (int nt = 0; nt < 8; nt++) {
            sacc[nt][0] *= scale; sacc[nt][1] *= scale;
            sacc[nt][2] *= scale; sacc[nt][3] *= scale;
            int c = nt * 8 + 2 * t;
            if (mskb[c])     { sacc[nt][0] = -1e30f; sacc[nt][2] = -1e30f; }
            if (mskb[c + 1]) { sacc[nt][1] = -1e30f; sacc[nt][3] = -1e30f; }
            mx0 = fmaxf(mx0, fmaxf(sacc[nt][0], sacc[nt][1]));
            mx1 = fmaxf(mx1, fmaxf(sacc[nt][2], sacc[nt][3]));
        }
        mx0 = fmaxf(mx0, __shfl_xor_sync(0xffffffffu, mx0, 1));
        mx0 = fmaxf(mx0, __shfl_xor_sync(0xffffffffu, mx0, 2));
        mx1 = fmaxf(mx1, __shfl_xor_sync(0xffffffffu, mx1, 1));
        mx1 = fmaxf(mx1, __shfl_xor_sync(0xffffffffu, mx1, 2));
        float mn0 = fmaxf(m0, mx0), mn1 = fmaxf(m1, mx1);
        float c0 = __expf(m0 - mn0), c1 = __expf(m1 - mn1);
        float s0 = 0.f, s1 = 0.f;
#pragma unroll
        for (int nt = 0; nt < 8; nt++) {
            float p00 = __expf(sacc[nt][0] - mn0);
            float p01 = __expf(sacc[nt][1] - mn0);
            float p10 = __expf(sacc[nt][2] - mn1);
            float p11 = __expf(sacc[nt][3] - mn1);
            s0 += p00 + p01;
            s1 += p10 + p11;
            PsA[nt * 4 + t] = pack_h2(p00, p01);
            PsB[nt * 4 + t] = pack_h2(p10, p11);
        }
        s0 += __shfl_xor_sync(0xffffffffu, s0, 1);
        s0 += __shfl_xor_sync(0xffffffffu, s0, 2);
        s1 += __shfl_xor_sync(0xffffffffu, s1, 1);
        s1 += __shfl_xor_sync(0xffffffffu, s1, 2);
        l0 = l0 * c0 + s0; m0 = mn0;
        l1 = l1 * c1 + s1; m1 = mn1;
#pragma unroll
        for (int nt = 0; nt < 7; nt++) {
            oacc[nt][0] *= c0; oacc[nt][1] *= c0;
            oacc[nt][2] *= c1; oacc[nt][3] *= c1;
        }
        __syncwarp();

#pragma unroll
        for (int ks = 0; ks < 4; ks++) {
            int kk = ks * 8;
            uint32_t af[4] = {PsA[kk + t], PsB[kk + t], PsA[kk + t + 4], PsB[kk + t + 4]};
#pragma unroll
            for (int nt = 0; nt < 7; nt++) {
                const uint32_t* Vr = Vtb + (nt * 8 + g) * APW + kk;
                uint32_t bf[2] = {Vr[t], Vr[t + 4]};
                MMA_F16(oacc[nt], af, bf);
            }
        }
    }

    float inv0 = 1.f / l0, inv1 = 1.f / l1;
    int r0 = q0 + wq + g;
    __half* o0 = outh + (size_t)(b * T + r0) * KAP + h * HD;
    __half* o1 = o0 + (size_t)8 * KAP;
#pragma unroll
    for (int nt = 0; nt < 7; nt++) {
        int c = nt * 8 + 2 * t;
        if (c < HD) {
            *(uint32_t*)(o0 + c) = pack_h2(oacc[nt][0] * inv0, oacc[nt][1] * inv0);
            *(uint32_t*)(o1 + c) = pack_h2(oacc[nt][2] * inv1, oacc[nt][3] * inv1);
        }
    }
    if (h == 0 && lane < 16) {
        int row = q0 + wq + (lane & 15);
        uint32_t* pz = (uint32_t*)(outh + (size_t)(b * T + row) * KAP + 500);
#pragma unroll
        for (int w = 0; w < 6; w++) pz[w] = 0u;
    }
}

// ---------------- launch ----------------------------------------------------
extern "C" void kernel_launch(void* const* d_in, const int* in_sizes, int n_in,
                              void* d_out, int out_size) {
    const int* ori            = (const int*)d_in[0];
    const float* x            = (const float*)d_in[1];
    const unsigned char* xm   = (const unsigned char*)d_in[2];
    const float *dwp[4], *dbp[4], *pwp[4], *pbp[4];
    for (int i = 0; i < 4; i++) {
        dwp[i] = (const float*)d_in[3 + 4 * i];
        dbp[i] = (const float*)d_in[4 + 4 * i];
        pwp[i] = (const float*)d_in[5 + 4 * i];
        pbp[i] = (const float*)d_in[6 + 4 * i];
    }
    const float* in_w  = (const float*)d_in[19];
    const float* in_b  = (const float*)d_in[20];
    const float* out_w = (const float*)d_in[21];
    const float* out_b = (const float*)d_in[22];
    const float* ffc_w = (const float*)d_in[23];
    const float* ffc_b = (const float*)d_in[24];
    float* outp = (float*)d_out;

    float *b0, *b1, *b2, *wtr, *pet;
    __half *bt, *b1t, *b2t, *wth, *qkvh;
    cudaGetSymbolAddress((void**)&b0,   g_b0);
    cudaGetSymbolAddress((void**)&b1,   g_b1);
    cudaGetSymbolAddress((void**)&b2,   g_b2);
    cudaGetSymbolAddress((void**)&bt,   g_bt);
    cudaGetSymbolAddress((void**)&b1t,  g_b1t);
    cudaGetSymbolAddress((void**)&b2t,  g_b2t);
    cudaGetSymbolAddress((void**)&qkvh, g_qkv);
    cudaGetSymbolAddress((void**)&wth,  g_wt);
    cudaGetSymbolAddress((void**)&wtr,  g_wtr);
    cudaGetSymbolAddress((void**)&pet,  g_pe);

    cudaFuncSetAttribute(attn_mma, cudaFuncAttributeMaxDynamicSharedMemorySize, ASM_BYTES);
    cudaFuncSetAttribute(gemm_pipe, cudaFuncAttributeMaxDynamicSharedMemorySize, GSM_BYTES);

    __half* wtp[4];
    for (int i = 0; i < 4; i++) wtp[i] = wth + i * PWS;
    __half* wt_in  = wth + 4 * PWS;
    __half* wt_out = wt_in + INS;
    __half* wt_ffc = wt_out + PWS;

    int ntot = NW + NTR + NPE + NQZ;
    prep_all<<<(ntot + 255) / 256, 256>>>(pwp[0], pwp[1], pwp[2], pwp[3],
                                          in_w, out_w, ffc_w,
                                          dwp[0], dwp[1], dwp[2], dwp[3],
                                          wth, wtr, pet, qkvh);

    int pblocks  = (BT * 125 + 255) / 256;
    int cblocks  = ((BT / 4) * 128 + 255) / 256;   // 2048
    dim3 gg5((D + GBN - 1) / GBN, BT / GBM);    // (4, 128)
    dim3 ggq((D3 + GBN - 1) / GBN, BT / GBM);   // (12, 128)
    dim3 gga(T / AMQ, B * H);                   // (4, 320)

    posemb_kernel<<<pblocks, 256>>>(ori, x, pet, b0);
    dwconv4_kernel<<<cblocks, 256>>>(b0, wtr + 0 * KW * D, dbp[0], bt);
    gemm_pipe<<<gg5, 256, GSM_BYTES>>>(bt, wtp[0], pbp[0], b0, b1, nullptr, D, 0);
    dwconv4_kernel<<<cblocks, 256>>>(b1, wtr + 1 * KW * D, dbp[1], bt);
    gemm_pipe<<<gg5, 256, GSM_BYTES>>>(bt, wtp[1], pbp[1], b1, b2, nullptr, D, 0);
    dwconv4_kernel<<<cblocks, 256>>>(b2, wtr + 2 * KW * D, dbp[2], bt);
    gemm_pipe<<<gg5, 256, GSM_BYTES>>>(bt, wtp[2], pbp[2], b2, b0, nullptr, D, 0);
    dwconv4_kernel<<<cblocks, 256>>>(b0, wtr + 3 * KW * D, dbp[3], bt);
    gemm_pipe<<<gg5, 256, GSM_BYTES>>>(bt, wtp[3], pbp[3], b0, b1, b1t, D, 1);
    gemm_pipe<<<ggq, 256, GSM_BYTES>>>(b1t, wt_in, in_b, nullptr, nullptr, qkvh, D3, 2);
    attn_mma<<<gga, 256, ASM_BYTES>>>(qkvh, xm, bt);
    gemm_pipe<<<gg5, 256, GSM_BYTES>>>(bt, wt_out, out_b, b1, b2, b2t, D, 1);
    gemm_pipe<<<gg5, 256, GSM_BYTES>>>(b2t, wt_ffc, ffc_b, b2, outp, nullptr, D, 0);
}

// round 15
// speedup vs baseline: 2.1747x; 1.0047x over previous
#include <cuda_runtime.h>
#include <cuda_fp16.h>
#include <cstdint>
#include <cstddef>

#define B 32
#define T 512
#define D 500
#define H 10
#define HD 50
#define D3 1500
#define BT (B*T)
#define BTD (BT*D)
#define KW 7
#define KAP 512      // padded activation K pitch (halves)
#define KAPW 256     // words per activation row
#define QKVP 1920    // padded qkv row pitch (halves): 3 * H * 64

// ---------------- scratch (static device arrays; no runtime allocation) ----
__device__ float  g_b0[BTD];
__device__ float  g_b1[BTD];
__device__ float  g_b2[BTD];
__device__ __half g_bt[(size_t)BT * KAP];
__device__ __half g_b1t[(size_t)BT * KAP];
__device__ __half g_b2t[(size_t)BT * KAP];
__device__ __half g_qkv[(size_t)BT * QKVP];
__device__ __half g_wt[2304000];             // padded fp16 weights (permuted)
__device__ float  g_wtr[4 * KW * D];         // transposed dwconv weights [K][D]
__device__ float  g_pe[T * D];               // positional embedding table

#define PWS 256000   // 500*512
#define INS 768000   // 1500*512
#define NW  (4 * PWS + INS + 2 * PWS)        // 2,304,000 weight halves
#define NTR (4 * KW * D)                     // 14,000 transposed dw weights
#define NPE (T * D)                          // 256,000 PE entries
#define NQZ (BT * 30)                        // 491,520 qkv pad zero jobs

// ---------------- helpers ---------------------------------------------------
__device__ __forceinline__ uint32_t smem_u32(const void* p) {
    uint32_t a;
    asm("{ .reg .u64 t; cvta.to.shared.u64 t, %1; cvt.u32.u64 %0, t; }" : "=r"(a) : "l"(p));
    return a;
}
__device__ __forceinline__ uint32_t pack_h2(float lo, float hi) {
    __half2 h = __floats2half2_rn(lo, hi);
    return *(uint32_t*)&h;
}
// fragment-pair permutation within each 8-word block: new[2k]=old k, new[2k+1]=old k+4
__device__ __forceinline__ int pidx(int w) {
    return (w & ~7) | ((w & 3) << 1) | ((w >> 2) & 1);
}

#define MMA_F16(c, a, b) \
    asm volatile("mma.sync.aligned.m16n8k16.row.col.f32.f16.f16.f32 " \
        "{%0,%1,%2,%3}, {%4,%5,%6,%7}, {%8,%9}, {%0,%1,%2,%3};" \
        : "+f"((c)[0]), "+f"((c)[1]), "+f"((c)[2]), "+f"((c)[3]) \
        : "r"((a)[0]), "r"((a)[1]), "r"((a)[2]), "r"((a)[3]), \
          "r"((b)[0]), "r"((b)[1]))

#define CP16(dst, src) \
    asm volatile("cp.async.ca.shared.global [%0], [%1], 16;" :: "r"(dst), "l"(src) : "memory")
#define CP16P(dst, src, p) \
    asm volatile("cp.async.ca.shared.global [%0], [%1], 16, %2;" :: "r"(dst), "l"(src), "r"(p) : "memory")
#define CPCOMMIT() asm volatile("cp.async.commit_group;" ::: "memory")
#define CPWAIT0()  asm volatile("cp.async.wait_group 0;" ::: "memory")
#define CPWAIT1()  asm volatile("cp.async.wait_group 1;" ::: "memory")

// -------- merged prep: weights fp16 pad-convert (PERMUTED) + dwconv
//          transpose + PE table + qkv pad zero -------------------------------
__global__ void prep_all(const float* __restrict__ p0, const float* __restrict__ p1,
                         const float* __restrict__ p2, const float* __restrict__ p3,
                         const float* __restrict__ p4, const float* __restrict__ p5,
                         const float* __restrict__ p6,
                         const float* __restrict__ dw0, const float* __restrict__ dw1,
                         const float* __restrict__ dw2, const float* __restrict__ dw3,
                         __half* __restrict__ wh, float* __restrict__ otr,
                         float* __restrict__ pe, __half* __restrict__ qkv) {
    int i = blockIdx.x * blockDim.x + threadIdx.x;
    if (i < NW) {
        const float* src;
        int idx;
        if      (i < PWS)          { src = p0; idx = i; }
        else if (i < 2 * PWS)      { src = p1; idx = i - PWS; }
        else if (i < 3 * PWS)      { src = p2; idx = i - 2 * PWS; }
        else if (i < 4 * PWS)      { src = p3; idx = i - 3 * PWS; }
        else if (i < 4 * PWS + INS){ src = p4; idx = i - 4 * PWS; }
        else if (i < 5 * PWS + INS){ src = p5; idx = i - 4 * PWS - INS; }
        else                       { src = p6; idx = i - 5 * PWS - INS; }
        int row = idx >> 9, col = idx & 511;
        float v = (col < 500) ? src[row * 500 + col] : 0.f;
        int newcol = (pidx(col >> 1) << 1) | (col & 1);
        wh[(i & ~511) | newcol] = __float2half(v);
        return;
    }
    int i2 = i - NW;
    if (i2 < NTR) {
        int arr = i2 / (KW * D);
        int rem = i2 - arr * (KW * D);
        int j = rem / D;
        int d = rem - j * D;
        const float* src = (arr == 0) ? dw0 : (arr == 1) ? dw1 : (arr == 2) ? dw2 : dw3;
        otr[arr * KW * D + j * D + d] = src[d * KW + j];
        return;
    }
    int i3 = i2 - NTR;
    if (i3 < NPE) {
        int t = i3 / D, d = i3 - t * D;
        float pos = (float)(t + 1);
        int   k   = (d < 250) ? d : (d - 250);
        float ang = pos * expf((float)k * -0.036989318763f);
        pe[i3] = (d < 250) ? sinf(ang) : cosf(ang);
        return;
    }
    int i4 = i3 - NPE;
    if (i4 < NQZ) {
        int row = i4 / 30, slot = i4 - row * 30;
        uint32_t* p = (uint32_t*)(qkv + (size_t)row * QKVP + slot * 64 + 50);
#pragma unroll
        for (int w = 0; w < 7; w++) p[w] = 0u;
    }
}

// ---------------- posemb (float4) -------------------------------------------
__global__ void posemb_kernel(const int* __restrict__ ori,
                              const float* __restrict__ x,
                              const float* __restrict__ tab,
                              float* __restrict__ out) {
    int idx = blockIdx.x * blockDim.x + threadIdx.x;
    if (idx >= BT * 125) return;
    int d4 = idx % 125;
    int bt = idx / 125;
    int t  = bt % T;
    int d  = d4 * 4;
    size_t off = (size_t)bt * D + d;
    float4 xv = *(const float4*)(x + off);
    if (ori[bt] != 0) {
        float4 pv = *(const float4*)(tab + t * D + d);
        xv.x += pv.x; xv.y += pv.y; xv.z += pv.z; xv.w += pv.w;
    }
    *(float4*)(out + off) = xv;
}

// ------- depthwise conv1d: 4 t-outputs per thread, PERMUTED fp16 out -------
__global__ void dwconv4_kernel(const float* __restrict__ x,
                               const float* __restrict__ wT,   // [KW][D]
                               const float* __restrict__ bias,
                               __half* __restrict__ y) {
    int idx = blockIdx.x * blockDim.x + threadIdx.x;
    if (idx >= (BT / 4) * 128) return;
    int d4  = idx & 127;
    int btq = idx >> 7;
    int b   = btq >> 7;          // T/4 = 128
    int t0  = (btq & 127) * 4;
    uint32_t* yw = (uint32_t*)(y + (size_t)(b * T + t0) * KAP);
    int p0 = pidx(d4 * 2), p1 = pidx(d4 * 2 + 1);
    if (d4 >= 125) {
#pragma unroll
        for (int r = 0; r < 4; r++) {
            uint32_t* row = yw + (size_t)r * KAPW;
            row[p0] = 0u; row[p1] = 0u;
        }
        return;
    }
    int d = d4 * 4;
    float4 bv = *(const float4*)(bias + d);
    float acc[4][4];
#pragma unroll
    for (int r = 0; r < 4; r++) {
        acc[r][0] = bv.x; acc[r][1] = bv.y; acc[r][2] = bv.z; acc[r][3] = bv.w;
    }
    float4 w4[KW];
#pragma unroll
    for (int j = 0; j < KW; j++) w4[j] = *(const float4*)(wT + j * D + d);

    const float* xb = x + (size_t)(b * T) * D + d;
#pragma unroll
    for (int s = 0; s < 10; s++) {
        int tt = t0 + s - 3;
        if (tt >= 0 && tt < T) {
            float4 v = *(const float4*)(xb + (size_t)tt * D);
#pragma unroll
            for (int r = 0; r < 4; r++) {
                int j = s - r;
                if (j >= 0 && j < KW) {
                    acc[r][0] = fmaf(w4[j].x, v.x, acc[r][0]);
                    acc[r][1] = fmaf(w4[j].y, v.y, acc[r][1]);
                    acc[r][2] = fmaf(w4[j].z, v.z, acc[r][2]);
                    acc[r][3] = fmaf(w4[j].w, v.w, acc[r][3]);
                }
            }
        }
    }
#pragma unroll
    for (int r = 0; r < 4; r++) {
        uint32_t* row = yw + (size_t)r * KAPW;
        row[p0] = pack_h2(acc[r][0], acc[r][1]);
        row[p1] = pack_h2(acc[r][2], acc[r][3]);
    }
}

// =================== pipelined fp16 warp-mma GEMM (LDS.64 fragments) ========
// A/W gmem are permuted; smem pitch 40 words -> conflict-free paired loads.
#define GBM 128
#define GBN 128
#define AP 40
#define GBUF ((GBM + GBN) * AP)
#define GSM_BYTES (2 * GBUF * 4)
#define KTC 8   // 512 / 64

__global__ __launch_bounds__(256, 2)
void gemm_pipe(const __half* __restrict__ A, const __half* __restrict__ W,
               const float* __restrict__ bias, const float* __restrict__ res,
               float* __restrict__ C, __half* __restrict__ Ct,
               int N, int mode) {
    extern __shared__ uint32_t sm[];

    int tid  = threadIdx.x;
    int lane = tid & 31, wid = tid >> 5;
    int g = lane >> 2, t = lane & 3;
    int m0 = blockIdx.y * GBM;
    int n0 = blockIdx.x * GBN;
    int wm = (wid & 1) * 64;
    int wn = (wid >> 1) * 32;

    int r0 = tid >> 3, kg = tid & 7;
    uint32_t smbase = smem_u32(sm);
    uint32_t adst[4], bdst[4];
    const __half* asrc[4];
    const __half* bsrc[4];
    uint32_t bok[4];
#pragma unroll
    for (int i = 0; i < 4; i++) {
        int r = r0 + i * 32;
        adst[i] = smbase + (uint32_t)(r * AP + kg * 4) * 4;
        bdst[i] = adst[i] + GBM * AP * 4;
        asrc[i] = A + (size_t)(m0 + r) * KAP + kg * 8;
        int n = n0 + r;
        bok[i] = (n < N) ? 16u : 0u;
        bsrc[i] = W + (size_t)((n < N) ? n : 0) * 512 + kg * 8;
    }

    float acc[4][4][4];
#pragma unroll
    for (int mt = 0; mt < 4; mt++)
#pragma unroll
        for (int nt = 0; nt < 4; nt++)
#pragma unroll
            for (int i = 0; i < 4; i++) acc[mt][nt][i] = 0.f;

    {
#pragma unroll
        for (int i = 0; i < 4; i++) {
            CP16(adst[i], asrc[i]);
            CP16P(bdst[i], bsrc[i], bok[i]);
        }
        CPCOMMIT();
    }

    for (int kt = 0; kt < KTC; kt++) {
        int buf = kt & 1;
        if (kt + 1 < KTC) {
            int koff = (kt + 1) * 64;
            uint32_t bo = (buf ^ 1) ? (uint32_t)GBUF * 4 : 0u;
#pragma unroll
            for (int i = 0; i < 4; i++) {
                CP16(adst[i] + bo, asrc[i] + koff);
                CP16P(bdst[i] + bo, bsrc[i] + koff, bok[i]);
            }
            CPCOMMIT();
            CPWAIT1();
        } else {
            CPWAIT0();
        }
        __syncthreads();

        const uint32_t* Ab = sm + (buf ? GBUF : 0);
        const uint32_t* Bb = Ab + GBM * AP;
#pragma unroll
        for (int ks = 0; ks < 4; ks++) {
            int kk = ks * 8 + 2 * t;
            uint32_t af[4][4], bf[4][2];
#pragma unroll
            for (int mt = 0; mt < 4; mt++) {
                const uint32_t* Ar = Ab + (wm + mt * 16 + g) * AP + kk;
                uint2 lo = *(const uint2*)Ar;
                uint2 hi = *(const uint2*)(Ar + 8 * AP);
                af[mt][0] = lo.x; af[mt][2] = lo.y;
                af[mt][1] = hi.x; af[mt][3] = hi.y;
            }
#pragma unroll
            for (int nt = 0; nt < 4; nt++) {
                uint2 bv = *(const uint2*)(Bb + (wn + nt * 8 + g) * AP + kk);
                bf[nt][0] = bv.x; bf[nt][1] = bv.y;
            }
#pragma unroll
            for (int mt = 0; mt < 4; mt++)
#pragma unroll
                for (int nt = 0; nt < 4; nt++)
                    MMA_F16(acc[mt][nt], af[mt], bf[nt]);
        }
        __syncthreads();
    }

#pragma unroll
    for (int mt = 0; mt < 4; mt++) {
        int row0 = m0 + wm + mt * 16 + g;
#pragma unroll
        for (int nt = 0; nt < 4; nt++) {
            int col = n0 + wn + nt * 8 + 2 * t;
            if (col < N) {
                float2 bv = *(const float2*)(bias + col);
                float2 o0, o1;
                o0.x = acc[mt][nt][0] + bv.x;
                o0.y = acc[mt][nt][1] + bv.y;
                o1.x = acc[mt][nt][2] + bv.x;
                o1.y = acc[mt][nt][3] + bv.y;
                if (mode == 2) {
                    int which = col / 500;
                    int rem   = col - which * 500;
                    int hh    = rem / 50;
                    int dd    = rem - hh * 50;
                    size_t p0 = (size_t)row0 * QKVP + which * 640 + hh * 64 + dd;
                    size_t p1 = (size_t)(row0 + 8) * QKVP + which * 640 + hh * 64 + dd;
                    __half* Ch = (__half*)Ct;
                    *(uint32_t*)(Ch + p0) = pack_h2(o0.x, o0.y);
                    *(uint32_t*)(Ch + p1) = pack_h2(o1.x, o1.y);
                } else {
                    size_t i0 = (size_t)row0 * N + col;
                    size_t i1 = (size_t)(row0 + 8) * N + col;
                    if (res) {
                        float2 r0v = *(const float2*)(res + i0);
                        float2 r1v = *(const float2*)(res + i1);
                        o0.x += r0v.x; o0.y += r0v.y;
                        o1.x += r1v.x; o1.y += r1v.y;
                    }
                    *(float2*)(C + i0) = o0;
                    *(float2*)(C + i1) = o1;
                    if (mode == 1) {
                        int pw = pidx(col >> 1);
                        uint32_t* Cw = (uint32_t*)Ct;
                        Cw[(size_t)row0 * KAPW + pw]       = pack_h2(o0.x, o0.y);
                        Cw[(size_t)(row0 + 8) * KAPW + pw] = pack_h2(o1.x, o1.y);
                    }
                }
            }
        }
    }
    if (mode == 1 && n0 == 0 && lane < 16) {
        int row = m0 + wm + (lane & 15);
        uint32_t* Cw = (uint32_t*)Ct;
#pragma unroll
        for (int rr = 0; rr < 4; rr++) {
            uint32_t* pz = Cw + (size_t)(row + rr * 16) * KAPW;
#pragma unroll
            for (int w = 0; w < 6; w++) pz[pidx(250 + w)] = 0u;
        }
    }
}

// =================== fp16 warp-mma flash attention (unchanged core) =========
#define AMQ 128
#define ANK 64
#define APW 36
#define ASM_BYTES (((AMQ + 2*ANK + 2*56 + AMQ) * APW) * 4 + 192)

__global__ __launch_bounds__(256, 3)
void attn_mma(const __half* __restrict__ qkvh,
              const unsigned char* __restrict__ mask,
              __half* __restrict__ outh) {
    extern __shared__ uint32_t dsm[];
    uint32_t* Qs  = dsm;                      // [128][36]
    uint32_t* Ks0 = Qs + AMQ * APW;           // [2][64][36]
    uint32_t* Vt0 = Ks0 + 2 * ANK * APW;      // [2][56][36]
    uint32_t* Ps  = Vt0 + 2 * 56 * APW;       // [128][36]
    unsigned char* msk = (unsigned char*)(Ps + AMQ * APW);  // [2][64]

    int tid  = threadIdx.x;
    int lane = tid & 31, wid = tid >> 5;
    int g = lane >> 2, t = lane & 3;
    int bh = blockIdx.y;
    int b  = bh / H, h = bh % H;
    int q0 = blockIdx.x * AMQ;
    const float scale = 0.14142135623730951f;

    for (int i = tid; i < 2 * 6 * 32; i += 256) {
        int bb = i / 192, rr = (i % 192) / 32, cc = i % 32;
        Vt0[bb * 56 * APW + (50 + rr) * APW + cc] = 0;
    }

    {
        int r = tid >> 1, e = tid & 1;
        const __half* src = qkvh + (size_t)(b * T + q0 + r) * QKVP + h * 64;
        uint32_t dst = smem_u32(Qs + r * APW);
#pragma unroll
        for (int c = e; c < 8; c += 2) CP16(dst + 16 * c, src + 8 * c);
        CPCOMMIT();
    }

    int jst = tid >> 2, qst = tid & 3;

    {
        const __half* ksrc = qkvh + (size_t)(b * T + jst) * QKVP + 640 + h * 64;
        uint32_t dst = smem_u32(Ks0 + jst * APW);
        CP16(dst + 16 * qst,       ksrc + 8 * qst);
        CP16(dst + 16 * (qst + 4), ksrc + 8 * (qst + 4));
        CPCOMMIT();
        const __half* vsrc = qkvh + (size_t)(b * T + jst) * QKVP + 1280 + h * 64;
#pragma unroll
        for (int p = qst; p < 25; p += 4) {
            uint32_t v = *(const uint32_t*)(vsrc + 2 * p);
            __half2 hv = *(__half2*)&v;
            ((__half*)(Vt0 + (2 * p) * APW))[jst]     = hv.x;
            ((__half*)(Vt0 + (2 * p + 1) * APW))[jst] = hv.y;
        }
        if (tid < ANK) msk[tid] = mask[b * T + tid];
    }

    int wq = wid * 16;
    const uint32_t* QA = Qs + (wq + g) * APW;
    const uint32_t* QB = Qs + (wq + g + 8) * APW;
    uint32_t* PsA = Ps + (wq + g) * APW;
    uint32_t* PsB = Ps + (wq + g + 8) * APW;

    float m0 = -1e30f, m1 = -1e30f, l0 = 0.f, l1 = 0.f;
    float oacc[7][4];
#pragma unroll
    for (int nt = 0; nt < 7; nt++)
#pragma unroll
        for (int i = 0; i < 4; i++) oacc[nt][i] = 0.f;

    for (int kt = 0; kt < T / ANK; kt++) {
        int buf = kt & 1;
        CPWAIT0();
        __syncthreads();

        if (kt + 1 < T / ANK) {
            int k1 = (kt + 1) * ANK;
            uint32_t* Ksn = Ks0 + (buf ^ 1) * ANK * APW;
            uint32_t* Vtn = Vt0 + (buf ^ 1) * 56 * APW;
            const __half* ksrc = qkvh + (size_t)(b * T + k1 + jst) * QKVP + 640 + h * 64;
            uint32_t dst = smem_u32(Ksn + jst * APW);
            CP16(dst + 16 * qst,       ksrc + 8 * qst);
            CP16(dst + 16 * (qst + 4), ksrc + 8 * (qst + 4));
            CPCOMMIT();
            const __half* vsrc = qkvh + (size_t)(b * T + k1 + jst) * QKVP + 1280 + h * 64;
#pragma unroll
            for (int p = qst; p < 25; p += 4) {
                uint32_t v = *(const uint32_t*)(vsrc + 2 * p);
                __half2 hv = *(__half2*)&v;
                ((__half*)(Vtn + (2 * p) * APW))[jst]     = hv.x;
                ((__half*)(Vtn + (2 * p + 1) * APW))[jst] = hv.y;
            }
            if (tid < ANK) msk[(buf ^ 1) * 64 + tid] = mask[b * T + k1 + tid];
        } else {
            CPCOMMIT();
        }

        const uint32_t* Ksb = Ks0 + buf * ANK * APW;
        const uint32_t* Vtb = Vt0 + buf * 56 * APW;
        const unsigned char* mskb = msk + buf * 64;

        float sacc[8][4];
#pragma unroll
        for (int nt = 0; nt < 8; nt++)
#pragma unroll
            for (int i = 0; i < 4; i++) sacc[nt][i] = 0.f;
#pragma unroll
        for (int ks = 0; ks < 4; ks++) {
            int kk = ks * 8;
            uint32_t af[4] = {QA[kk + t], QB[kk + t], QA[kk + t + 4], QB[kk + t + 4]};
#pragma unroll
            for (int nt = 0; nt < 8; nt++) {
                const uint32_t* Kr = Ksb + (nt * 8 + g) * APW + kk;
                uint32_t bf[2] = {Kr[t], Kr[t + 4]};
                MMA_F16(sacc[nt], af, bf);
            }
        }

        float mx0 = -1e30f, mx1 = -1e30f;
#pragma unroll
        for (int nt = 0; nt < 8; nt++) {
            sacc[nt][0] *= scale; sacc[nt][1] *= scale;
            sacc[nt][2] *= scale; sacc[nt][3] *= scale;
            int c = nt * 8 + 2 * t;
            if (mskb[c])     { sacc[nt][0] = -1e30f; sacc[nt][2] = -1e30f; }
            if (mskb[c + 1]) { sacc[nt][1] = -1e30f; sacc[nt][3] = -1e30f; }
            mx0 = fmaxf(mx0, fmaxf(sacc[nt][0], sacc[nt][1]));
            mx1 = fmaxf(mx1, fmaxf(sacc[nt][2], sacc[nt][3]));
        }
        mx0 = fmaxf(mx0, __shfl_xor_sync(0xffffffffu, mx0, 1));
        mx0 = fmaxf(mx0, __shfl_xor_sync(0xffffffffu, mx0, 2));
        mx1 = fmaxf(mx1, __shfl_xor_sync(0xffffffffu, mx1, 1));
        mx1 = fmaxf(mx1, __shfl_xor_sync(0xffffffffu, mx1, 2));
        float mn0 = fmaxf(m0, mx0), mn1 = fmaxf(m1, mx1);
        float c0 = __expf(m0 - mn0), c1 = __expf(m1 - mn1);
        float s0 = 0.f, s1 = 0.f;
#pragma unroll
        for (int nt = 0; nt < 8; nt++) {
            float p00 = __expf(sacc[nt][0] - mn0);
            float p01 = __expf(sacc[nt][1] - mn0);
            float p10 = __expf(sacc[nt][2] - mn1);
            float p11 = __expf(sacc[nt][3] - mn1);
            s0 += p00 + p01;
            s1 += p10 + p11;
            PsA[nt * 4 + t] = pack_h2(p00, p01);
            PsB[nt * 4 + t] = pack_h2(p10, p11);
        }
        s0 += __shfl_xor_sync(0xffffffffu, s0, 1);
        s0 += __shfl_xor_sync(0xffffffffu, s0, 2);
        s1 += __shfl_xor_sync(0xffffffffu, s1, 1);
        s1 += __shfl_xor_sync(0xffffffffu, s1, 2);
        l0 = l0 * c0 + s0; m0 = mn0;
        l1 = l1 * c1 + s1; m1 = mn1;
#pragma unroll
        for (int nt = 0; nt < 7; nt++) {
            oacc[nt][0] *= c0; oacc[nt][1] *= c0;
            oacc[nt][2] *= c1; oacc[nt][3] *= c1;
        }
        __syncwarp();

#pragma unroll
        for (int ks = 0; ks < 4; ks++) {
            int kk = ks * 8;
            uint32_t af[4] = {PsA[kk + t], PsB[kk + t], PsA[kk + t + 4], PsB[kk + t + 4]};
#pragma unroll
            for (int nt = 0; nt < 7; nt++) {
                const uint32_t* Vr = Vtb + (nt * 8 + g) * APW + kk;
                uint32_t bf[2] = {Vr[t], Vr[t + 4]};
                MMA_F16(oacc[nt], af, bf);
            }
        }
    }

    // epilogue: permuted fp16 output (consumer is out_proj GEMM A)
    float inv0 = 1.f / l0, inv1 = 1.f / l1;
    int r0 = q0 + wq + g;
    uint32_t* o0w = (uint32_t*)(outh + (size_t)(b * T + r0) * KAP);
    uint32_t* o1w = o0w + 8 * KAPW;
#pragma unroll
    for (int nt = 0; nt < 7; nt++) {
        int c = nt * 8 + 2 * t;
        if (c < HD) {
            int p = pidx(h * 25 + nt * 4 + t);
            o0w[p] = pack_h2(oacc[nt][0] * inv0, oacc[nt][1] * inv0);
            o1w[p] = pack_h2(oacc[nt][2] * inv1, oacc[nt][3] * inv1);
        }
    }
    if (h == 0 && lane < 16) {
        int row = q0 + wq + (lane & 15);
        uint32_t* pz = (uint32_t*)(outh + (size_t)(b * T + row) * KAP);
#pragma unroll
        for (int w = 0; w < 6; w++) pz[pidx(250 + w)] = 0u;
    }
}

// ---------------- launch ----------------------------------------------------
extern "C" void kernel_launch(void* const* d_in, const int* in_sizes, int n_in,
                              void* d_out, int out_size) {
    const int* ori            = (const int*)d_in[0];
    const float* x            = (const float*)d_in[1];
    const unsigned char* xm   = (const unsigned char*)d_in[2];
    const float *dwp[4], *dbp[4], *pwp[4], *pbp[4];
    for (int i = 0; i < 4; i++) {
        dwp[i] = (const float*)d_in[3 + 4 * i];
        dbp[i] = (const float*)d_in[4 + 4 * i];
        pwp[i] = (const float*)d_in[5 + 4 * i];
        pbp[i] = (const float*)d_in[6 + 4 * i];
    }
    const float* in_w  = (const float*)d_in[19];
    const float* in_b  = (const float*)d_in[20];
    const float* out_w = (const float*)d_in[21];
    const float* out_b = (const float*)d_in[22];
    const float* ffc_w = (const float*)d_in[23];
    const float* ffc_b = (const float*)d_in[24];
    float* outp = (float*)d_out;

    float *b0, *b1, *b2, *wtr, *pet;
    __half *bt, *b1t, *b2t, *wth, *qkvh;
    cudaGetSymbolAddress((void**)&b0,   g_b0);
    cudaGetSymbolAddress((void**)&b1,   g_b1);
    cudaGetSymbolAddress((void**)&b2,   g_b2);
    cudaGetSymbolAddress((void**)&bt,   g_bt);
    cudaGetSymbolAddress((void**)&b1t,  g_b1t);
    cudaGetSymbolAddress((void**)&b2t,  g_b2t);
    cudaGetSymbolAddress((void**)&qkvh, g_qkv);
    cudaGetSymbolAddress((void**)&wth,  g_wt);
    cudaGetSymbolAddress((void**)&wtr,  g_wtr);
    cudaGetSymbolAddress((void**)&pet,  g_pe);

    cudaFuncSetAttribute(attn_mma, cudaFuncAttributeMaxDynamicSharedMemorySize, ASM_BYTES);
    cudaFuncSetAttribute(gemm_pipe, cudaFuncAttributeMaxDynamicSharedMemorySize, GSM_BYTES);

    __half* wtp[4];
    for (int i = 0; i < 4; i++) wtp[i] = wth + i * PWS;
    __half* wt_in  = wth + 4 * PWS;
    __half* wt_out = wt_in + INS;
    __half* wt_ffc = wt_out + PWS;

    int ntot = NW + NTR + NPE + NQZ;
    prep_all<<<(ntot + 255) / 256, 256>>>(pwp[0], pwp[1], pwp[2], pwp[3],
                                          in_w, out_w, ffc_w,
                                          dwp[0], dwp[1], dwp[2], dwp[3],
                                          wth, wtr, pet, qkvh);

    int pblocks  = (BT * 125 + 255) / 256;
    int cblocks  = ((BT / 4) * 128 + 255) / 256;   // 2048
    dim3 gg5((D + GBN - 1) / GBN, BT / GBM);    // (4, 128)
    dim3 ggq((D3 + GBN - 1) / GBN, BT / GBM);   // (12, 128)
    dim3 gga(T / AMQ, B * H);                   // (4, 320)

    posemb_kernel<<<pblocks, 256>>>(ori, x, pet, b0);
    dwconv4_kernel<<<cblocks, 256>>>(b0, wtr + 0 * KW * D, dbp[0], bt);
    gemm_pipe<<<gg5, 256, GSM_BYTES>>>(bt, wtp[0], pbp[0], b0, b1, nullptr, D, 0);
    dwconv4_kernel<<<cblocks, 256>>>(b1, wtr + 1 * KW * D, dbp[1], bt);
    gemm_pipe<<<gg5, 256, GSM_BYTES>>>(bt, wtp[1], pbp[1], b1, b2, nullptr, D, 0);
    dwconv4_kernel<<<cblocks, 256>>>(b2, wtr + 2 * KW * D, dbp[2], bt);
    gemm_pipe<<<gg5, 256, GSM_BYTES>>>(bt, wtp[2], pbp[2], b2, b0, nullptr, D, 0);
    dwconv4_kernel<<<cblocks, 256>>>(b0, wtr + 3 * KW * D, dbp[3], bt);
    gemm_pipe<<<gg5, 256, GSM_BYTES>>>(bt, wtp[3], pbp[3], b0, b1, b1t, D, 1);
    gemm_pipe<<<ggq, 256, GSM_BYTES>>>(b1t, wt_in, in_b, nullptr, nullptr, qkvh, D3, 2);
    attn_mma<<<gga, 256, ASM_BYTES>>>(qkvh, xm, bt);
    gemm_pipe<<<gg5, 256, GSM_BYTES>>>(bt, wt_out, out_b, b1, b2, b2t, D, 1);
    gemm_pipe<<<gg5, 256, GSM_BYTES>>>(b2t, wt_ffc, ffc_b, b2, outp, nullptr, D, 0);
}